// round 5
// baseline (speedup 1.0000x reference)
#include <cuda_runtime.h>
#include <cuda.h>
#include <math.h>

#define Bn   16
#define Ln   512
#define Cn   38
#define Dn   512
#define Hn   8
#define En   64
#define DFFn 2048
#define NLn  3
#define DRESn 128
#define Mn   (Bn*Ln)     /* 8192 */
#define BHn  (Bn*Hn)     /* 128  */

// ---------------- scratch (static device memory) ----------------
__device__ float g_h    [Mn*Dn];
__device__ float g_q    [Mn*Dn];
__device__ float g_k    [Mn*Dn];
__device__ float g_v    [Mn*Dn];
__device__ float g_attnv[Mn*Dn];
__device__ float g_tmp  [Mn*Dn];
__device__ float g_x1   [Mn*Dn];
__device__ float g_enc  [Mn*Dn];
__device__ float g_ff1  [Mn*DFFn];
__device__ float g_scores[33554432];         // 128*512*512
__device__ float g_xcat [Mn*128];
__device__ float g_vt   [BHn*En*Ln];         // [z][e][s]
__device__ float g_wt   [9830400];           // transposed weights (tf32-rounded)

#define WTQ 0
#define WTK 786432
#define WTV 1572864
#define WTO 2359296
#define WT1 3145728
#define WT2 6291456
#define WTP 9437184
#define WTF 9699328
#define KTF 9764864

// ================= helpers =================
__device__ __forceinline__ unsigned smem_u32(const void* p) {
    unsigned a;
    asm("{ .reg .u64 t; cvta.to.shared.u64 t, %1; cvt.u32.u64 %0, t; }"
        : "=r"(a) : "l"(p));
    return a;
}
__device__ __forceinline__ unsigned cvt_tf32(float f) {
    unsigned u; asm("cvt.rna.tf32.f32 %0, %1;" : "=r"(u) : "f"(f)); return u;
}
__device__ __forceinline__ float round_tf32f(float f) {
    return __uint_as_float(cvt_tf32(f));
}
__device__ __forceinline__ void mma8(float* c, const unsigned* a, const unsigned* b) {
    asm volatile("mma.sync.aligned.m16n8k8.row.col.f32.tf32.tf32.f32 "
        "{%0,%1,%2,%3}, {%4,%5,%6,%7}, {%8,%9}, {%0,%1,%2,%3};"
        : "+f"(c[0]), "+f"(c[1]), "+f"(c[2]), "+f"(c[3])
        : "r"(a[0]), "r"(a[1]), "r"(a[2]), "r"(a[3]), "r"(b[0]), "r"(b[1]));
}
__device__ __forceinline__ void ldsm4(unsigned* r, unsigned addr) {
    asm volatile("ldmatrix.sync.aligned.m8n8.x4.shared.b16 {%0,%1,%2,%3}, [%4];"
        : "=r"(r[0]), "=r"(r[1]), "=r"(r[2]), "=r"(r[3]) : "r"(addr));
}
#define CP16(sa, gp) \
    asm volatile("cp.async.cg.shared.global [%0], [%1], 16;" :: "r"(sa), "l"(gp))
#define CPCOMMIT() asm volatile("cp.async.commit_group;" ::: "memory")
#define CPWAIT(n)  asm volatile("cp.async.wait_group %0;" :: "n"(n) : "memory")

// ================= tensor-core GEMM via mma.sync (tf32) =================
// C[128 x NT] per CTA: C = A[M,K] @ BT[N,K]^T  (BT stored [N][K], tf32-rounded)
// MODE 0: plain    MODE 2: attn*V batch
// CVTA: round A fragments in-loop (A buffer is raw fp32)
template<int NT, int MODE, bool CVTA>
__global__ __launch_bounds__(256, 2)
void gemm_mma(const float* __restrict__ A, int lda,
              const float* __restrict__ BT, int ldb,
              const float* __restrict__ bias,
              float* __restrict__ C, int ldc,
              int K, float scale, int do_gelu, int round_out)
{
    constexpr int WC  = (NT == 128) ? 4 : 2;
    constexpr int WM  = (NT == 128) ? 64 : 32;
    constexpr int MT  = WM / 16;
    constexpr int ASZ = 128 * 36;
    constexpr int BSZ = NT * 36;
    constexpr int STG = ASZ + BSZ;

    extern __shared__ float sm[];
    const int tid = threadIdx.x, w = tid >> 5, lane = tid & 31;
    const int m0 = blockIdx.y * 128, n0 = blockIdx.x * NT;
    const int sel = lane >> 3, lr = lane & 7;

    size_t aoff = 0, boff = 0, coff = 0;
    if (MODE == 2) {
        int z = blockIdx.z;
        aoff = (size_t)z * Ln * Ln;
        boff = (size_t)z * En * Ln;
        coff = ((size_t)(z >> 3) * Ln) * Dn + (size_t)(z & 7) * En;
    }
    const float* Ag = A + aoff;
    const float* Bg = BT + boff;

    auto load_stage = [&](int kc, int st) {
        float* As = sm + st * STG;
        float* Bs = As + ASZ;
        const float* Ap = Ag + (size_t)m0 * lda + kc * 32;
#pragma unroll
        for (int i = 0; i < 4; i++) {
            int fi = tid + i * 256, row = fi >> 3, seg = fi & 7;
            CP16(smem_u32(As + row * 36 + seg * 4), Ap + (size_t)row * lda + seg * 4);
        }
        const float* Bp = Bg + (size_t)n0 * ldb + kc * 32;
#pragma unroll
        for (int i = 0; i < NT / 32; i++) {
            int fi = tid + i * 256, row = fi >> 3, seg = fi & 7;
            CP16(smem_u32(Bs + row * 36 + seg * 4), Bp + (size_t)row * ldb + seg * 4);
        }
    };

    float acc[MT][4][4];
#pragma unroll
    for (int mt = 0; mt < MT; mt++)
#pragma unroll
        for (int nt = 0; nt < 4; nt++)
#pragma unroll
            for (int j = 0; j < 4; j++) acc[mt][nt][j] = 0.f;

    const int wm0 = (w / WC) * WM, wn0 = (w % WC) * 32;
    const int r = lane >> 2, cl = lane & 3;

    auto compute = [&](int st) {
        const float* As = sm + st * STG;
        const float* Bs = As + ASZ;
        // ldmatrix bases: A matrices (sel&1)->+8 rows, (sel>>1)->+4 k
        //                 B matrices (sel>>1)->+8 rows, (sel&1)->+4 k
        unsigned aBase = smem_u32(As) + 4u * ((wm0 + (sel & 1) * 8 + lr) * 36 + (sel >> 1) * 4);
        unsigned bBase = smem_u32(Bs) + 4u * ((wn0 + (sel >> 1) * 8 + lr) * 36 + (sel & 1) * 4);
#pragma unroll
        for (int kk = 0; kk < 4; kk++) {
            const unsigned koff = kk * 32;     // kk*8 floats * 4B
            unsigned a[MT][4], b[4][2], t0[4], t1[4];
#pragma unroll
            for (int mt = 0; mt < MT; mt++)
                ldsm4(a[mt], aBase + mt * (16 * 36 * 4) + koff);
            ldsm4(t0, bBase + koff);
            ldsm4(t1, bBase + 16 * 36 * 4 + koff);
            b[0][0] = t0[0]; b[0][1] = t0[1]; b[1][0] = t0[2]; b[1][1] = t0[3];
            b[2][0] = t1[0]; b[2][1] = t1[1]; b[3][0] = t1[2]; b[3][1] = t1[3];
            if (CVTA) {
#pragma unroll
                for (int mt = 0; mt < MT; mt++)
#pragma unroll
                    for (int j = 0; j < 4; j++)
                        a[mt][j] = cvt_tf32(__uint_as_float(a[mt][j]));
            }
#pragma unroll
            for (int mt = 0; mt < MT; mt++)
#pragma unroll
                for (int nt = 0; nt < 4; nt++)
                    mma8(acc[mt][nt], a[mt], b[nt]);
        }
    };

    const int NC = K >> 5;
    load_stage(0, 0);
    CPCOMMIT();
    for (int c = 0; c < NC; c++) {
        if (c + 1 < NC) { load_stage(c + 1, (c + 1) & 1); CPCOMMIT(); CPWAIT(1); }
        else            { CPWAIT(0); }
        __syncthreads();
        compute(c & 1);
        __syncthreads();
    }

#pragma unroll
    for (int mt = 0; mt < MT; mt++) {
#pragma unroll
        for (int nt = 0; nt < 4; nt++) {
            int row = m0 + wm0 + mt * 16 + r;
            int col = n0 + wn0 + nt * 8 + cl * 2;
            float bs0 = bias ? bias[col] : 0.f;
            float bs1 = bias ? bias[col + 1] : 0.f;
            float v0 = acc[mt][nt][0] * scale + bs0;
            float v1 = acc[mt][nt][1] * scale + bs1;
            float v2 = acc[mt][nt][2] * scale + bs0;
            float v3 = acc[mt][nt][3] * scale + bs1;
            if (do_gelu) {
                v0 = 0.5f * v0 * (1.0f + erff(v0 * 0.70710678118654752f));
                v1 = 0.5f * v1 * (1.0f + erff(v1 * 0.70710678118654752f));
                v2 = 0.5f * v2 * (1.0f + erff(v2 * 0.70710678118654752f));
                v3 = 0.5f * v3 * (1.0f + erff(v3 * 0.70710678118654752f));
            }
            if (round_out) {
                v0 = round_tf32f(v0); v1 = round_tf32f(v1);
                v2 = round_tf32f(v2); v3 = round_tf32f(v3);
            }
            float* p0 = C + coff + (size_t)row * ldc + col;
            float* p1 = p0 + (size_t)8 * ldc;
            p0[0] = v0; p0[1] = v1;
            p1[0] = v2; p1[1] = v3;
        }
    }
}

// ================= fused scores + softmax =================
// grid (z=BHn, mtile=16); CTA 256 thr. P[32 x 512] per CTA for one (b,h).
// q,k are tf32-pre-rounded by their producing GEMMs.
#define FS_QS   0
#define FS_KS   2176            /* 32*68 */
#define FS_RED  36992           /* 2176 + 512*68 */
#define FS_SMEM ((36992 + 512) * 4)

__global__ __launch_bounds__(256, 1)
void fused_scores_softmax(const float* __restrict__ q,
                          const float* __restrict__ kmat,
                          float* __restrict__ scores)
{
    extern __shared__ float sm[];
    const int tid = threadIdx.x, w = tid >> 5, lane = tid & 31;
    const int r = lane >> 2, cl = lane & 3;
    const int sel = lane >> 3, lr = lane & 7;
    const int z = blockIdx.x;
    const int m0 = blockIdx.y * 32;
    const size_t off = ((size_t)(z >> 3) * Ln) * Dn + (size_t)(z & 7) * En;

    unsigned* Qs = (unsigned*)(sm + FS_QS);
    unsigned* Ks = (unsigned*)(sm + FS_KS);
    float* red  = sm + FS_RED;           // [8][32]
    float* red2 = red + 256;             // [8][32]

    {
        const float* Qp = q + off;
#pragma unroll
        for (int i = 0; i < 2; i++) {
            int idx = tid + i * 256, row = idx >> 4, seg = idx & 15;
            float4 v = *(const float4*)(Qp + (size_t)(m0 + row) * Dn + seg * 4);
            unsigned* d = Qs + row * 68 + seg * 4;
            d[0] = __float_as_uint(v.x); d[1] = __float_as_uint(v.y);
            d[2] = __float_as_uint(v.z); d[3] = __float_as_uint(v.w);
        }
        const float* Kp = kmat + off;
#pragma unroll 8
        for (int i = 0; i < 32; i++) {
            int idx = tid + i * 256, row = idx >> 4, seg = idx & 15;
            float4 v = *(const float4*)(Kp + (size_t)row * Dn + seg * 4);
            unsigned* d = Ks + row * 68 + seg * 4;
            d[0] = __float_as_uint(v.x); d[1] = __float_as_uint(v.y);
            d[2] = __float_as_uint(v.z); d[3] = __float_as_uint(v.w);
        }
    }
    __syncthreads();

    const int wn0 = w * 64;
    float acc[2][8][4];
#pragma unroll
    for (int mt = 0; mt < 2; mt++)
#pragma unroll
        for (int nt = 0; nt < 8; nt++)
#pragma unroll
            for (int j = 0; j < 4; j++) acc[mt][nt][j] = 0.f;

    unsigned aBase = smem_u32(Qs) + 4u * (((sel & 1) * 8 + lr) * 68 + (sel >> 1) * 4);
    unsigned bBase = smem_u32(Ks) + 4u * ((wn0 + (sel >> 1) * 8 + lr) * 68 + (sel & 1) * 4);
#pragma unroll
    for (int kk = 0; kk < 8; kk++) {
        const unsigned koff = kk * 32;
        unsigned a[2][4], b[8][2];
#pragma unroll
        for (int mt = 0; mt < 2; mt++)
            ldsm4(a[mt], aBase + mt * (16 * 68 * 4) + koff);
#pragma unroll
        for (int p = 0; p < 4; p++) {
            unsigned t[4];
            ldsm4(t, bBase + p * (16 * 68 * 4) + koff);
            b[2 * p][0] = t[0]; b[2 * p][1] = t[1];
            b[2 * p + 1][0] = t[2]; b[2 * p + 1][1] = t[3];
        }
#pragma unroll
        for (int mt = 0; mt < 2; mt++)
#pragma unroll
            for (int nt = 0; nt < 8; nt++)
                mma8(acc[mt][nt], a[mt], b[nt]);
    }

    // ---- row softmax over 512 cols ----
    float M[4], inv[4];
#pragma unroll
    for (int rs = 0; rs < 4; rs++) {
        int mt = rs >> 1, jb = (rs & 1) * 2;
        float mx = -1e30f;
#pragma unroll
        for (int nt = 0; nt < 8; nt++)
            mx = fmaxf(mx, fmaxf(acc[mt][nt][jb], acc[mt][nt][jb + 1]));
        mx = fmaxf(mx, __shfl_xor_sync(0xFFFFFFFFu, mx, 1));
        mx = fmaxf(mx, __shfl_xor_sync(0xFFFFFFFFu, mx, 2));
        M[rs] = mx;
        if (cl == 0) red[w * 32 + mt * 16 + r + (rs & 1) * 8] = mx;
    }
    __syncthreads();
#pragma unroll
    for (int rs = 0; rs < 4; rs++) {
        int row = (rs >> 1) * 16 + r + (rs & 1) * 8;
        float mx = -1e30f;
#pragma unroll
        for (int w2 = 0; w2 < 8; w2++) mx = fmaxf(mx, red[w2 * 32 + row]);
        M[rs] = mx;
    }
#pragma unroll
    for (int rs = 0; rs < 4; rs++) {
        int mt = rs >> 1, jb = (rs & 1) * 2;
        float s = 0.f;
#pragma unroll
        for (int nt = 0; nt < 8; nt++) {
            float e0 = __expf((acc[mt][nt][jb]     - M[rs]) * 0.125f);
            float e1 = __expf((acc[mt][nt][jb + 1] - M[rs]) * 0.125f);
            acc[mt][nt][jb] = e0; acc[mt][nt][jb + 1] = e1;
            s += e0 + e1;
        }
        s += __shfl_xor_sync(0xFFFFFFFFu, s, 1);
        s += __shfl_xor_sync(0xFFFFFFFFu, s, 2);
        if (cl == 0) red2[w * 32 + mt * 16 + r + (rs & 1) * 8] = s;
    }
    __syncthreads();
#pragma unroll
    for (int rs = 0; rs < 4; rs++) {
        int row = (rs >> 1) * 16 + r + (rs & 1) * 8;
        float s = 0.f;
#pragma unroll
        for (int w2 = 0; w2 < 8; w2++) s += red2[w2 * 32 + row];
        inv[rs] = 1.0f / s;
    }

    // write P pre-rounded to tf32 (only consumer is the PV GEMM A-side)
    float* C = scores + (size_t)z * Ln * Ln;
#pragma unroll
    for (int mt = 0; mt < 2; mt++) {
#pragma unroll
        for (int nt = 0; nt < 8; nt++) {
            int row = m0 + mt * 16 + r;
            int col = wn0 + nt * 8 + cl * 2;
            float* p0 = C + (size_t)row * Ln + col;
            float* p1 = p0 + (size_t)8 * Ln;
            p0[0] = round_tf32f(acc[mt][nt][0] * inv[mt * 2]);
            p0[1] = round_tf32f(acc[mt][nt][1] * inv[mt * 2]);
            p1[0] = round_tf32f(acc[mt][nt][2] * inv[mt * 2 + 1]);
            p1[1] = round_tf32f(acc[mt][nt][3] * inv[mt * 2 + 1]);
        }
    }
}

// ================= packing / transpose =================
__global__ void pack_xcat(const float* __restrict__ x, float* __restrict__ xc) {
    int bl = blockIdx.x;
    int b = bl >> 9, l = bl & 511;
    int i = threadIdx.x;
    float val = 0.f;
    if (i < Cn * 3) {
        int c = i / 3, t = i - c * 3;
        int ls = (l - 1 + t + Ln) & (Ln - 1);
        val = round_tf32f(x[((size_t)b * Ln + ls) * Cn + c]);
    }
    xc[(size_t)bl * 128 + i] = val;
}
__global__ void pack_ktf(const float* __restrict__ kern, float* __restrict__ kt) {
    int d = blockIdx.x, i = threadIdx.x;
    kt[(size_t)d * 128 + i] = (i < Cn * 3) ? round_tf32f(kern[(size_t)d * (Cn * 3) + i]) : 0.f;
}
__global__ void transpose_kn(const float* __restrict__ in, float* __restrict__ out,
                             int K, int N) {
    __shared__ float t[32][33];
    int k0 = blockIdx.y * 32, n0 = blockIdx.x * 32;
    int tx = threadIdx.x, ty = threadIdx.y;
#pragma unroll
    for (int r = 0; r < 4; r++)
        t[ty + r * 8][tx] = in[(size_t)(k0 + ty + r * 8) * N + n0 + tx];
    __syncthreads();
#pragma unroll
    for (int r = 0; r < 4; r++)
        out[(size_t)(n0 + ty + r * 8) * K + k0 + tx] = round_tf32f(t[tx][ty + r * 8]);
}
__global__ void transpose_v(const float* __restrict__ v, float* __restrict__ vt) {
    __shared__ float t[64][65];
    int z = blockIdx.y, s0 = blockIdx.x * 64;
    int b = z >> 3, h = z & 7;
    const float* src = v + ((size_t)b * Ln) * Dn + (size_t)h * En;
    int e = threadIdx.x & 63, idx = threadIdx.x >> 6;
#pragma unroll
    for (int r = 0; r < 16; r++)
        t[idx + r * 4][e] = src[(size_t)(s0 + idx + r * 4) * Dn + e];
    __syncthreads();
    float* dst = vt + (size_t)z * En * Ln;
#pragma unroll
    for (int r = 0; r < 16; r++)
        dst[(size_t)(idx + r * 4) * Ln + s0 + e] = t[e][idx + r * 4];
}

// ================= layernorm (+optional residual, +optional 384-col copy) ====
__global__ void add_ln512(const float* __restrict__ a, const float* __restrict__ b,
                          const float* __restrict__ g, const float* __restrict__ be,
                          float* __restrict__ o, float* __restrict__ res) {
    int row = blockIdx.x, t = threadIdx.x;
    size_t base = (size_t)row * Dn;
    float v0 = a[base + t], v1 = a[base + t + 256];
    if (b) { v0 += b[base + t]; v1 += b[base + t + 256]; }
    float s = v0 + v1;
#pragma unroll
    for (int oo = 16; oo > 0; oo >>= 1) s += __shfl_xor_sync(0xFFFFFFFFu, s, oo);
    __shared__ float s1[8], s2[8];
    if ((t & 31) == 0) s1[t >> 5] = s;
    __syncthreads();
    float mean = (s1[0] + s1[1] + s1[2] + s1[3] + s1[4] + s1[5] + s1[6] + s1[7]) * (1.0f / Dn);
    float d0 = v0 - mean, d1 = v1 - mean;
    float q2 = d0 * d0 + d1 * d1;
#pragma unroll
    for (int oo = 16; oo > 0; oo >>= 1) q2 += __shfl_xor_sync(0xFFFFFFFFu, q2, oo);
    if ((t & 31) == 0) s2[t >> 5] = q2;
    __syncthreads();
    float var = (s2[0] + s2[1] + s2[2] + s2[3] + s2[4] + s2[5] + s2[6] + s2[7]) * (1.0f / Dn);
    float rr = rsqrtf(var + 1e-5f);
    float o0 = d0 * rr * g[t]       + be[t];
    float o1 = d1 * rr * g[t + 256] + be[t + 256];
    o[base + t]       = o0;
    o[base + t + 256] = o1;
    if (res) {
        res[(size_t)row * 384 + t] = o0;
        if (t < 128) res[(size_t)row * 384 + t + 256] = o1;
    }
}

// ================= launcher =================
extern "C" void kernel_launch(void* const* d_in, const int* in_sizes, int n_in,
                              void* d_out, int out_size)
{
    const float* x     = (const float*)d_in[0];
    const float* embk  = (const float*)d_in[1];
    const float* Wq    = (const float*)d_in[2];
    const float* bq    = (const float*)d_in[3];
    const float* Wk    = (const float*)d_in[4];
    const float* bk    = (const float*)d_in[5];
    const float* Wv    = (const float*)d_in[6];
    const float* bv    = (const float*)d_in[7];
    // d_in[8], d_in[9]: Wsig/bsig are dead code in the reference
    const float* Wo    = (const float*)d_in[10];
    const float* bo    = (const float*)d_in[11];
    const float* W1    = (const float*)d_in[12];
    const float* b1    = (const float*)d_in[13];
    const float* W2    = (const float*)d_in[14];
    const float* b2    = (const float*)d_in[15];
    const float* n1g   = (const float*)d_in[16];
    const float* n1b   = (const float*)d_in[17];
    const float* n2g   = (const float*)d_in[18];
    const float* n2b   = (const float*)d_in[19];
    const float* nfg   = (const float*)d_in[20];
    const float* nfb   = (const float*)d_in[21];
    const float* Wproj = (const float*)d_in[22];
    const float* bproj = (const float*)d_in[23];
    const float* Wfea  = (const float*)d_in[24];
    const float* bfea  = (const float*)d_in[25];
    float* out = (float*)d_out;

    float *h,*q,*k,*v,*attnv,*tmp,*x1,*enc,*ff1,*scores,*xcat,*vt,*wt;
    cudaGetSymbolAddress((void**)&h,      g_h);
    cudaGetSymbolAddress((void**)&q,      g_q);
    cudaGetSymbolAddress((void**)&k,      g_k);
    cudaGetSymbolAddress((void**)&v,      g_v);
    cudaGetSymbolAddress((void**)&attnv,  g_attnv);
    cudaGetSymbolAddress((void**)&tmp,    g_tmp);
    cudaGetSymbolAddress((void**)&x1,     g_x1);
    cudaGetSymbolAddress((void**)&enc,    g_enc);
    cudaGetSymbolAddress((void**)&ff1,    g_ff1);
    cudaGetSymbolAddress((void**)&scores, g_scores);
    cudaGetSymbolAddress((void**)&xcat,   g_xcat);
    cudaGetSymbolAddress((void**)&vt,     g_vt);
    cudaGetSymbolAddress((void**)&wt,     g_wt);

    // outputs: fea_t | enc_res | rec_temp | emb
    const size_t OFF_FEA = 0;
    const size_t OFF_RES = (size_t)Mn * Dn;
    const size_t OFF_REC = OFF_RES + (size_t)Mn * 384;
    const size_t OFF_EMB = OFF_REC + (size_t)Mn * Dn;
    float* emb = out + OFF_EMB;

    const int SM128 = (128 + 128) * 36 * 4 * 2;   // 73728
    const int SM64  = (128 +  64) * 36 * 4 * 2;   // 55296
    cudaFuncSetAttribute((const void*)gemm_mma<128,0,true>,  cudaFuncAttributeMaxDynamicSharedMemorySize, SM128);
    cudaFuncSetAttribute((const void*)gemm_mma<128,0,false>, cudaFuncAttributeMaxDynamicSharedMemorySize, SM128);
    cudaFuncSetAttribute((const void*)gemm_mma<64,2,false>,  cudaFuncAttributeMaxDynamicSharedMemorySize, SM64);
    cudaFuncSetAttribute((const void*)fused_scores_softmax,  cudaFuncAttributeMaxDynamicSharedMemorySize, FS_SMEM);

    // ---- per-launch weight transposes + packs (tf32-rounded) ----
    pack_ktf<<<512, 128>>>(embk, wt + KTF);
    pack_xcat<<<Mn, 128>>>(x, xcat);
    dim3 tb(32, 8);
    for (int l = 0; l < NLn; l++) {
        size_t o512 = (size_t)l * Dn * Dn, o1 = (size_t)l * Dn * DFFn;
        transpose_kn<<<dim3(16, 16), tb>>>(Wq + o512, wt + WTQ + o512, Dn, Dn);
        transpose_kn<<<dim3(16, 16), tb>>>(Wk + o512, wt + WTK + o512, Dn, Dn);
        transpose_kn<<<dim3(16, 16), tb>>>(Wv + o512, wt + WTV + o512, Dn, Dn);
        transpose_kn<<<dim3(16, 16), tb>>>(Wo + o512, wt + WTO + o512, Dn, Dn);
        transpose_kn<<<dim3(64, 16), tb>>>(W1 + o1,   wt + WT1 + o1,   Dn, DFFn);
        transpose_kn<<<dim3(16, 64), tb>>>(W2 + o1,   wt + WT2 + o1,   DFFn, Dn);
    }
    transpose_kn<<<dim3(16, 16), tb>>>(Wproj, wt + WTP, Dn, Dn);
    transpose_kn<<<dim3(16, 4),  tb>>>(Wfea,  wt + WTF, DRESn, Dn);

    // conv1d as GEMM (A=xcat pre-rounded; emb is a final output -> no rounding)
    gemm_mma<128,0,false><<<dim3(4, 64), 256, SM128>>>(xcat, 128, wt + KTF, 128, nullptr,
                                                       emb, Dn, 128, 1.0f, 0, 0);

    for (int l = 0; l < NLn; l++) {
        const float* hin = (l == 0) ? emb : h;
        size_t o512 = (size_t)l * Dn * Dn, o1 = (size_t)l * Dn * DFFn;
        // q,k,v feed only GEMM/softmax A-slots -> round at epilogue
        gemm_mma<128,0,true><<<dim3(4, 64), 256, SM128>>>(hin, Dn, wt + WTQ + o512, Dn,
                                                          bq + l * Dn, q, Dn, Dn, 1.0f, 0, 1);
        gemm_mma<128,0,true><<<dim3(4, 64), 256, SM128>>>(hin, Dn, wt + WTK + o512, Dn,
                                                          bk + l * Dn, k, Dn, Dn, 1.0f, 0, 1);
        gemm_mma<128,0,true><<<dim3(4, 64), 256, SM128>>>(hin, Dn, wt + WTV + o512, Dn,
                                                          bv + l * Dn, v, Dn, Dn, 1.0f, 0, 1);
        transpose_v<<<dim3(8, BHn), 256>>>(v, vt);
        fused_scores_softmax<<<dim3(BHn, 16), 256, FS_SMEM>>>(q, k, scores);
        // P pre-rounded, vt pre-rounded; attnv feeds only Wo GEMM -> round out
        gemm_mma<64,2,false><<<dim3(1, 4, BHn), 256, SM64>>>(scores, Ln, vt, Ln, nullptr,
                                                             attnv, Dn, Ln, 1.0f, 0, 1);
        gemm_mma<128,0,false><<<dim3(4, 64), 256, SM128>>>(attnv, Dn, wt + WTO + o512, Dn,
                                                           bo + l * Dn, tmp, Dn, Dn, 1.0f, 0, 0);
        add_ln512<<<Mn, 256>>>(hin, tmp, n1g + l * Dn, n1b + l * Dn, x1, nullptr);
        // ff1 feeds only W2 GEMM -> round out
        gemm_mma<128,0,true><<<dim3(16, 64), 256, SM128>>>(x1, Dn, wt + WT1 + o1, Dn,
                                                           b1 + l * DFFn, ff1, DFFn, Dn, 1.0f, 1, 1);
        gemm_mma<128,0,false><<<dim3(4, 64), 256, SM128>>>(ff1, DFFn, wt + WT2 + o1, DFFn,
                                                           b2 + l * Dn, tmp, Dn, DFFn, 1.0f, 0, 0);
        add_ln512<<<Mn, 256>>>(x1, tmp, n2g + l * Dn, n2b + l * Dn, h, nullptr);
    }

    add_ln512<<<Mn, 256>>>(h, nullptr, nfg, nfb, enc, out + OFF_RES);

    gemm_mma<128,0,true><<<dim3(4, 64), 256, SM128>>>(enc + (Dn - DRESn), Dn, wt + WTF, DRESn,
                                                      bfea, out + OFF_FEA, Dn, DRESn, 1.0f, 0, 0);
    gemm_mma<128,0,true><<<dim3(4, 64), 256, SM128>>>(enc, Dn, wt + WTP, Dn,
                                                      bproj, out + OFF_REC, Dn, Dn, 1.0f, 0, 0);
}

// round 6
// speedup vs baseline: 1.5853x; 1.5853x over previous
#include <cuda_runtime.h>
#include <cuda.h>
#include <cuda_fp16.h>
#include <math.h>

#define Bn   16
#define Ln   512
#define Cn   38
#define Dn   512
#define Hn   8
#define En   64
#define DFFn 2048
#define NLn  3
#define DRESn 128
#define Mn   (Bn*Ln)     /* 8192 */
#define BHn  (Bn*Hn)     /* 128  */

// ---------------- scratch (static device memory) ----------------
__device__ float  g_h   [Mn*Dn];
__device__ float  g_x1  [Mn*Dn];
__device__ float  g_tmp [Mn*Dn];
__device__ __align__(16) __half g_h16  [Mn*Dn];
__device__ __align__(16) __half g_x1h  [Mn*Dn];
__device__ __align__(16) __half g_enc16[Mn*Dn];
__device__ __align__(16) __half g_q    [Mn*Dn];
__device__ __align__(16) __half g_k    [Mn*Dn];
__device__ __align__(16) __half g_v    [Mn*Dn];
__device__ __align__(16) __half g_attnv[Mn*Dn];
__device__ __align__(16) __half g_ff1  [Mn*DFFn];
__device__ __align__(16) __half g_scores[33554432];   // 128*512*512
__device__ __align__(16) __half g_xcat [Mn*128];
__device__ __align__(16) __half g_vt   [BHn*En*Ln];   // [z][e][s]
__device__ __align__(16) __half g_wt   [9830400];     // transposed weights (half)

#define WTQ 0
#define WTK 786432
#define WTV 1572864
#define WTO 2359296
#define WT1 3145728
#define WT2 6291456
#define WTP 9437184
#define WTF 9699328
#define KTF 9764864

// ================= helpers =================
__device__ __forceinline__ unsigned smem_u32(const void* p) {
    unsigned a;
    asm("{ .reg .u64 t; cvta.to.shared.u64 t, %1; cvt.u32.u64 %0, t; }"
        : "=r"(a) : "l"(p));
    return a;
}
__device__ __forceinline__ void mma16(float* c, const unsigned* a, const unsigned* b) {
    asm volatile("mma.sync.aligned.m16n8k16.row.col.f32.f16.f16.f32 "
        "{%0,%1,%2,%3}, {%4,%5,%6,%7}, {%8,%9}, {%0,%1,%2,%3};"
        : "+f"(c[0]), "+f"(c[1]), "+f"(c[2]), "+f"(c[3])
        : "r"(a[0]), "r"(a[1]), "r"(a[2]), "r"(a[3]), "r"(b[0]), "r"(b[1]));
}
__device__ __forceinline__ void ldsm4(unsigned* r, unsigned addr) {
    asm volatile("ldmatrix.sync.aligned.m8n8.x4.shared.b16 {%0,%1,%2,%3}, [%4];"
        : "=r"(r[0]), "=r"(r[1]), "=r"(r[2]), "=r"(r[3]) : "r"(addr));
}
#define CP16(sa, gp) \
    asm volatile("cp.async.cg.shared.global [%0], [%1], 16;" :: "r"(sa), "l"(gp))
#define CPCOMMIT() asm volatile("cp.async.commit_group;" ::: "memory")
#define CPWAIT(n)  asm volatile("cp.async.wait_group %0;" :: "n"(n) : "memory")

// ================= fp16 tensor-core GEMM =================
// C[128 x NT] per CTA: C = A[M,K] @ BT[N,K]^T  (A, BT half; accum f32)
// MODE 0: plain    MODE 2: attn*V batch
// RS = smem row stride in halves (40 -> conflict-free ldmatrix, 80B rows)
template<int NT, int MODE>
__global__ __launch_bounds__(256, 2)
void gemm_mma(const __half* __restrict__ A, int lda,
              const __half* __restrict__ BT, int ldb,
              const float* __restrict__ bias,
              float* __restrict__ C, __half* __restrict__ C16, int ldc,
              int K, float scale, int do_gelu)
{
    constexpr int WC  = (NT == 128) ? 4 : 2;
    constexpr int WM  = (NT == 128) ? 64 : 32;
    constexpr int MT  = WM / 16;
    constexpr int RS  = 40;
    constexpr int STG = (128 + NT) * RS;     // halves per stage

    extern __shared__ __align__(16) char dsm[];
    __half* sm = (__half*)dsm;
    const int tid = threadIdx.x, w = tid >> 5, lane = tid & 31;
    const int m0 = blockIdx.y * 128, n0 = blockIdx.x * NT;
    const int g = lane >> 3, lr = lane & 7;

    size_t aoff = 0, boff = 0, coff = 0;
    if (MODE == 2) {
        int z = blockIdx.z;
        aoff = (size_t)z * Ln * Ln;
        boff = (size_t)z * En * Ln;
        coff = ((size_t)(z >> 3) * Ln) * Dn + (size_t)(z & 7) * En;
    }
    const __half* Ag = A + aoff;
    const __half* Bg = BT + boff;

    auto load_stage = [&](int kc, int st) {
        __half* As = sm + st * STG;
        __half* Bs = As + 128 * RS;
        const __half* Ap = Ag + (size_t)m0 * lda + kc * 32;
#pragma unroll
        for (int i = 0; i < 2; i++) {
            int fi = tid + i * 256, row = fi >> 2, seg = fi & 3;
            CP16(smem_u32(As + row * RS + seg * 8), Ap + (size_t)row * lda + seg * 8);
        }
        const __half* Bp = Bg + (size_t)n0 * ldb + kc * 32;
#pragma unroll
        for (int i = 0; i < NT / 64; i++) {
            int fi = tid + i * 256, row = fi >> 2, seg = fi & 3;
            CP16(smem_u32(Bs + row * RS + seg * 8), Bp + (size_t)row * ldb + seg * 8);
        }
    };

    float acc[MT][4][4];
#pragma unroll
    for (int mt = 0; mt < MT; mt++)
#pragma unroll
        for (int nt = 0; nt < 4; nt++)
#pragma unroll
            for (int j = 0; j < 4; j++) acc[mt][nt][j] = 0.f;

    const int wm0 = (w / WC) * WM, wn0 = (w % WC) * 32;
    const int r = lane >> 2, cl = lane & 3;

    // ldmatrix lane-address mapping (x4):
    //  A: groups 0..3 -> (rows+0,k0)(rows+8,k0)(rows+0,k8)(rows+8,k8)
    //  B: groups 0..3 -> (nt0,k0)(nt0,k8)(nt1,k0)(nt1,k8)
    const unsigned aLane = ((g & 1) * 8 + lr) * RS + (g >> 1) * 8;
    const unsigned bLane = ((g >> 1) * 8 + lr) * RS + (g & 1) * 8;

    auto compute = [&](int st) {
        __half* As = sm + st * STG;
        __half* Bs = As + 128 * RS;
        unsigned aBase = smem_u32(As) + 2u * (wm0 * RS + aLane);
        unsigned bBase = smem_u32(Bs) + 2u * (wn0 * RS + bLane);
#pragma unroll
        for (int ks = 0; ks < 2; ks++) {            // two k16 steps per 32-chunk
            const unsigned koff = ks * 32;          // 16 halves * 2B
            unsigned a[MT][4], b[4][2];
#pragma unroll
            for (int mt = 0; mt < MT; mt++)
                ldsm4(a[mt], aBase + mt * (16 * RS * 2) + koff);
#pragma unroll
            for (int p = 0; p < 2; p++) {
                unsigned t[4];
                ldsm4(t, bBase + p * (16 * RS * 2) + koff);
                b[2 * p][0] = t[0]; b[2 * p][1] = t[1];
                b[2 * p + 1][0] = t[2]; b[2 * p + 1][1] = t[3];
            }
#pragma unroll
            for (int mt = 0; mt < MT; mt++)
#pragma unroll
                for (int nt = 0; nt < 4; nt++)
                    mma16(acc[mt][nt], a[mt], b[nt]);
        }
    };

    const int NC = K >> 5;
    load_stage(0, 0);
    CPCOMMIT();
    for (int c = 0; c < NC; c++) {
        if (c + 1 < NC) { load_stage(c + 1, (c + 1) & 1); CPCOMMIT(); CPWAIT(1); }
        else            { CPWAIT(0); }
        __syncthreads();
        compute(c & 1);
        __syncthreads();
    }

#pragma unroll
    for (int mt = 0; mt < MT; mt++) {
#pragma unroll
        for (int nt = 0; nt < 4; nt++) {
            int row = m0 + wm0 + mt * 16 + r;
            int col = n0 + wn0 + nt * 8 + cl * 2;
            float bs0 = bias ? bias[col] : 0.f;
            float bs1 = bias ? bias[col + 1] : 0.f;
            float v0 = acc[mt][nt][0] * scale + bs0;
            float v1 = acc[mt][nt][1] * scale + bs1;
            float v2 = acc[mt][nt][2] * scale + bs0;
            float v3 = acc[mt][nt][3] * scale + bs1;
            if (do_gelu) {
                v0 = 0.5f * v0 * (1.0f + erff(v0 * 0.70710678118654752f));
                v1 = 0.5f * v1 * (1.0f + erff(v1 * 0.70710678118654752f));
                v2 = 0.5f * v2 * (1.0f + erff(v2 * 0.70710678118654752f));
                v3 = 0.5f * v3 * (1.0f + erff(v3 * 0.70710678118654752f));
            }
            if (C) {
                float* p0 = C + coff + (size_t)row * ldc + col;
                float* p1 = p0 + (size_t)8 * ldc;
                p0[0] = v0; p0[1] = v1;
                p1[0] = v2; p1[1] = v3;
            }
            if (C16) {
                __half2* q0 = (__half2*)(C16 + coff + (size_t)row * ldc + col);
                __half2* q1 = (__half2*)(C16 + coff + (size_t)(row + 8) * ldc + col);
                *q0 = __floats2half2_rn(v0, v1);
                *q1 = __floats2half2_rn(v2, v3);
            }
        }
    }
}

// ================= fused scores + softmax (fp16 MMA, fp32 softmax) ==========
// grid (z=BHn, mtile=16); CTA 256 thr. P[32 x 512] per CTA for one (b,h).
#define FS_RSH  72                                   /* half row stride */
#define FS_QH   (32 * FS_RSH)
#define FS_KH   (512 * FS_RSH)
#define FS_SMEM ((FS_QH + FS_KH) * 2 + 512 * 4 + 16)

__global__ __launch_bounds__(256, 1)
void fused_scores_softmax(const __half* __restrict__ q,
                          const __half* __restrict__ kmat,
                          __half* __restrict__ scores)
{
    extern __shared__ __align__(16) char dsm[];
    __half* Qs = (__half*)dsm;
    __half* Ks = Qs + FS_QH;
    float* red  = (float*)(Ks + FS_KH);              // [8][32]
    float* red2 = red + 256;                         // [8][32]

    const int tid = threadIdx.x, w = tid >> 5, lane = tid & 31;
    const int r = lane >> 2, cl = lane & 3;
    const int g = lane >> 3, lr = lane & 7;
    const int z = blockIdx.x;
    const int m0 = blockIdx.y * 32;
    const size_t off = ((size_t)(z >> 3) * Ln) * Dn + (size_t)(z & 7) * En;

    {   // load Q (32x64) + K (512x64) halves, 8 halves per uint4
        const __half* Qp = q + off;
        {
            int row = tid >> 3, seg = tid & 7;
            *(uint4*)(Qs + row * FS_RSH + seg * 8) =
                *(const uint4*)(Qp + (size_t)(m0 + row) * Dn + seg * 8);
        }
        const __half* Kp = kmat + off;
#pragma unroll 4
        for (int i = 0; i < 16; i++) {
            int idx = tid + i * 256, row = idx >> 3, seg = idx & 7;
            *(uint4*)(Ks + row * FS_RSH + seg * 8) =
                *(const uint4*)(Kp + (size_t)row * Dn + seg * 8);
        }
    }
    __syncthreads();

    const int wn0 = w * 64;
    float acc[2][8][4];
#pragma unroll
    for (int mt = 0; mt < 2; mt++)
#pragma unroll
        for (int nt = 0; nt < 8; nt++)
#pragma unroll
            for (int j = 0; j < 4; j++) acc[mt][nt][j] = 0.f;

    const unsigned aBase = smem_u32(Qs) + 2u * (((g & 1) * 8 + lr) * FS_RSH + (g >> 1) * 8);
    const unsigned bBase = smem_u32(Ks) + 2u * ((wn0 + (g >> 1) * 8 + lr) * FS_RSH + (g & 1) * 8);
#pragma unroll
    for (int ks = 0; ks < 4; ks++) {                 // E=64 -> 4 k16 steps
        const unsigned koff = ks * 32;
        unsigned a[2][4], b[8][2];
#pragma unroll
        for (int mt = 0; mt < 2; mt++)
            ldsm4(a[mt], aBase + mt * (16 * FS_RSH * 2) + koff);
#pragma unroll
        for (int p = 0; p < 4; p++) {
            unsigned t[4];
            ldsm4(t, bBase + p * (16 * FS_RSH * 2) + koff);
            b[2 * p][0] = t[0]; b[2 * p][1] = t[1];
            b[2 * p + 1][0] = t[2]; b[2 * p + 1][1] = t[3];
        }
#pragma unroll
        for (int mt = 0; mt < 2; mt++)
#pragma unroll
            for (int nt = 0; nt < 8; nt++)
                mma16(acc[mt][nt], a[mt], b[nt]);
    }

    // ---- row softmax over 512 cols ----
    float M[4], inv[4];
#pragma unroll
    for (int rs = 0; rs < 4; rs++) {
        int mt = rs >> 1, jb = (rs & 1) * 2;
        float mx = -1e30f;
#pragma unroll
        for (int nt = 0; nt < 8; nt++)
            mx = fmaxf(mx, fmaxf(acc[mt][nt][jb], acc[mt][nt][jb + 1]));
        mx = fmaxf(mx, __shfl_xor_sync(0xFFFFFFFFu, mx, 1));
        mx = fmaxf(mx, __shfl_xor_sync(0xFFFFFFFFu, mx, 2));
        if (cl == 0) red[w * 32 + mt * 16 + r + (rs & 1) * 8] = mx;
    }
    __syncthreads();
#pragma unroll
    for (int rs = 0; rs < 4; rs++) {
        int row = (rs >> 1) * 16 + r + (rs & 1) * 8;
        float mx = -1e30f;
#pragma unroll
        for (int w2 = 0; w2 < 8; w2++) mx = fmaxf(mx, red[w2 * 32 + row]);
        M[rs] = mx;
    }
#pragma unroll
    for (int rs = 0; rs < 4; rs++) {
        int mt = rs >> 1, jb = (rs & 1) * 2;
        float s = 0.f;
#pragma unroll
        for (int nt = 0; nt < 8; nt++) {
            float e0 = __expf((acc[mt][nt][jb]     - M[rs]) * 0.125f);
            float e1 = __expf((acc[mt][nt][jb + 1] - M[rs]) * 0.125f);
            acc[mt][nt][jb] = e0; acc[mt][nt][jb + 1] = e1;
            s += e0 + e1;
        }
        s += __shfl_xor_sync(0xFFFFFFFFu, s, 1);
        s += __shfl_xor_sync(0xFFFFFFFFu, s, 2);
        if (cl == 0) red2[w * 32 + mt * 16 + r + (rs & 1) * 8] = s;
    }
    __syncthreads();
#pragma unroll
    for (int rs = 0; rs < 4; rs++) {
        int row = (rs >> 1) * 16 + r + (rs & 1) * 8;
        float s = 0.f;
#pragma unroll
        for (int w2 = 0; w2 < 8; w2++) s += red2[w2 * 32 + row];
        inv[rs] = 1.0f / s;
    }

    __half* C = scores + (size_t)z * Ln * Ln;
#pragma unroll
    for (int mt = 0; mt < 2; mt++) {
#pragma unroll
        for (int nt = 0; nt < 8; nt++) {
            int row = m0 + mt * 16 + r;
            int col = wn0 + nt * 8 + cl * 2;
            *(__half2*)(C + (size_t)row * Ln + col) =
                __floats2half2_rn(acc[mt][nt][0] * inv[mt * 2], acc[mt][nt][1] * inv[mt * 2]);
            *(__half2*)(C + (size_t)(row + 8) * Ln + col) =
                __floats2half2_rn(acc[mt][nt][2] * inv[mt * 2 + 1], acc[mt][nt][3] * inv[mt * 2 + 1]);
        }
    }
}

// ================= packing / transpose =================
__global__ void pack_xcat(const float* __restrict__ x, __half* __restrict__ xc) {
    int bl = blockIdx.x;
    int b = bl >> 9, l = bl & 511;
    int i = threadIdx.x;
    float val = 0.f;
    if (i < Cn * 3) {
        int c = i / 3, t = i - c * 3;
        int ls = (l - 1 + t + Ln) & (Ln - 1);
        val = x[((size_t)b * Ln + ls) * Cn + c];
    }
    xc[(size_t)bl * 128 + i] = __float2half(val);
}
__global__ void pack_ktf(const float* __restrict__ kern, __half* __restrict__ kt) {
    int d = blockIdx.x, i = threadIdx.x;
    kt[(size_t)d * 128 + i] = __float2half((i < Cn * 3) ? kern[(size_t)d * (Cn * 3) + i] : 0.f);
}
__global__ void transpose_kn(const float* __restrict__ in, __half* __restrict__ out,
                             int K, int N) {
    __shared__ float t[32][33];
    int k0 = blockIdx.y * 32, n0 = blockIdx.x * 32;
    int tx = threadIdx.x, ty = threadIdx.y;
#pragma unroll
    for (int r = 0; r < 4; r++)
        t[ty + r * 8][tx] = in[(size_t)(k0 + ty + r * 8) * N + n0 + tx];
    __syncthreads();
#pragma unroll
    for (int r = 0; r < 4; r++)
        out[(size_t)(n0 + ty + r * 8) * K + k0 + tx] = __float2half(t[tx][ty + r * 8]);
}
__global__ void transpose_v(const __half* __restrict__ v, __half* __restrict__ vt) {
    __shared__ __half t[64][72];
    int z = blockIdx.y, s0 = blockIdx.x * 64;
    int b = z >> 3, h = z & 7;
    const __half* src = v + ((size_t)b * Ln) * Dn + (size_t)h * En;
    int e = threadIdx.x & 63, idx = threadIdx.x >> 6;
#pragma unroll
    for (int r = 0; r < 16; r++)
        t[idx + r * 4][e] = src[(size_t)(s0 + idx + r * 4) * Dn + e];
    __syncthreads();
    __half* dst = vt + (size_t)z * En * Ln;
#pragma unroll
    for (int r = 0; r < 16; r++)
        dst[(size_t)(idx + r * 4) * Ln + s0 + e] = t[e][idx + r * 4];
}

// ===== layernorm: fp32 out (opt) + fp16 out (opt) + 384-col res copy (opt) ===
__global__ void add_ln512(const float* __restrict__ a, const float* __restrict__ b,
                          const float* __restrict__ g, const float* __restrict__ be,
                          float* __restrict__ o, __half* __restrict__ o16,
                          float* __restrict__ res) {
    int row = blockIdx.x, t = threadIdx.x;
    size_t base = (size_t)row * Dn;
    float v0 = a[base + t], v1 = a[base + t + 256];
    if (b) { v0 += b[base + t]; v1 += b[base + t + 256]; }
    float s = v0 + v1;
#pragma unroll
    for (int oo = 16; oo > 0; oo >>= 1) s += __shfl_xor_sync(0xFFFFFFFFu, s, oo);
    __shared__ float s1[8], s2[8];
    if ((t & 31) == 0) s1[t >> 5] = s;
    __syncthreads();
    float mean = (s1[0] + s1[1] + s1[2] + s1[3] + s1[4] + s1[5] + s1[6] + s1[7]) * (1.0f / Dn);
    float d0 = v0 - mean, d1 = v1 - mean;
    float q2 = d0 * d0 + d1 * d1;
#pragma unroll
    for (int oo = 16; oo > 0; oo >>= 1) q2 += __shfl_xor_sync(0xFFFFFFFFu, q2, oo);
    if ((t & 31) == 0) s2[t >> 5] = q2;
    __syncthreads();
    float var = (s2[0] + s2[1] + s2[2] + s2[3] + s2[4] + s2[5] + s2[6] + s2[7]) * (1.0f / Dn);
    float rr = rsqrtf(var + 1e-5f);
    float o0 = d0 * rr * g[t]       + be[t];
    float o1 = d1 * rr * g[t + 256] + be[t + 256];
    if (o)  { o[base + t] = o0; o[base + t + 256] = o1; }
    if (o16) { o16[base + t] = __float2half(o0); o16[base + t + 256] = __float2half(o1); }
    if (res) {
        res[(size_t)row * 384 + t] = o0;
        if (t < 128) res[(size_t)row * 384 + t + 256] = o1;
    }
}

// ================= launcher =================
extern "C" void kernel_launch(void* const* d_in, const int* in_sizes, int n_in,
                              void* d_out, int out_size)
{
    const float* x     = (const float*)d_in[0];
    const float* embk  = (const float*)d_in[1];
    const float* Wq    = (const float*)d_in[2];
    const float* bq    = (const float*)d_in[3];
    const float* Wk    = (const float*)d_in[4];
    const float* bk    = (const float*)d_in[5];
    const float* Wv    = (const float*)d_in[6];
    const float* bv    = (const float*)d_in[7];
    // d_in[8], d_in[9]: Wsig/bsig are dead code in the reference
    const float* Wo    = (const float*)d_in[10];
    const float* bo    = (const float*)d_in[11];
    const float* W1    = (const float*)d_in[12];
    const float* b1    = (const float*)d_in[13];
    const float* W2    = (const float*)d_in[14];
    const float* b2    = (const float*)d_in[15];
    const float* n1g   = (const float*)d_in[16];
    const float* n1b   = (const float*)d_in[17];
    const float* n2g   = (const float*)d_in[18];
    const float* n2b   = (const float*)d_in[19];
    const float* nfg   = (const float*)d_in[20];
    const float* nfb   = (const float*)d_in[21];
    const float* Wproj = (const float*)d_in[22];
    const float* bproj = (const float*)d_in[23];
    const float* Wfea  = (const float*)d_in[24];
    const float* bfea  = (const float*)d_in[25];
    float* out = (float*)d_out;

    float *h, *x1, *tmp;
    __half *h16,*x1h,*enc16,*q,*k,*v,*attnv,*ff1,*scores,*xcat,*vt,*wt;
    cudaGetSymbolAddress((void**)&h,     g_h);
    cudaGetSymbolAddress((void**)&x1,    g_x1);
    cudaGetSymbolAddress((void**)&tmp,   g_tmp);
    cudaGetSymbolAddress((void**)&h16,   g_h16);
    cudaGetSymbolAddress((void**)&x1h,   g_x1h);
    cudaGetSymbolAddress((void**)&enc16, g_enc16);
    cudaGetSymbolAddress((void**)&q,     g_q);
    cudaGetSymbolAddress((void**)&k,     g_k);
    cudaGetSymbolAddress((void**)&v,     g_v);
    cudaGetSymbolAddress((void**)&attnv, g_attnv);
    cudaGetSymbolAddress((void**)&ff1,   g_ff1);
    cudaGetSymbolAddress((void**)&scores,g_scores);
    cudaGetSymbolAddress((void**)&xcat,  g_xcat);
    cudaGetSymbolAddress((void**)&vt,    g_vt);
    cudaGetSymbolAddress((void**)&wt,    g_wt);

    // outputs: fea_t | enc_res | rec_temp | emb
    const size_t OFF_FEA = 0;
    const size_t OFF_RES = (size_t)Mn * Dn;
    const size_t OFF_REC = OFF_RES + (size_t)Mn * 384;
    const size_t OFF_EMB = OFF_REC + (size_t)Mn * Dn;
    float* emb = out + OFF_EMB;

    const int SM128 = (128 + 128) * 40 * 2 * 2;   // 40960 B
    const int SM64  = (128 +  64) * 40 * 2 * 2;   // 30720 B
    cudaFuncSetAttribute((const void*)gemm_mma<128,0>, cudaFuncAttributeMaxDynamicSharedMemorySize, SM128);
    cudaFuncSetAttribute((const void*)gemm_mma<64,2>,  cudaFuncAttributeMaxDynamicSharedMemorySize, SM64);
    cudaFuncSetAttribute((const void*)fused_scores_softmax, cudaFuncAttributeMaxDynamicSharedMemorySize, FS_SMEM);

    // ---- per-launch weight transposes + packs (half) ----
    pack_ktf<<<512, 128>>>(embk, wt + KTF);
    pack_xcat<<<Mn, 128>>>(x, xcat);
    dim3 tb(32, 8);
    for (int l = 0; l < NLn; l++) {
        size_t o512 = (size_t)l * Dn * Dn, o1 = (size_t)l * Dn * DFFn;
        transpose_kn<<<dim3(16, 16), tb>>>(Wq + o512, wt + WTQ + o512, Dn, Dn);
        transpose_kn<<<dim3(16, 16), tb>>>(Wk + o512, wt + WTK + o512, Dn, Dn);
        transpose_kn<<<dim3(16, 16), tb>>>(Wv + o512, wt + WTV + o512, Dn, Dn);
        transpose_kn<<<dim3(16, 16), tb>>>(Wo + o512, wt + WTO + o512, Dn, Dn);
        transpose_kn<<<dim3(64, 16), tb>>>(W1 + o1,   wt + WT1 + o1,   Dn, DFFn);
        transpose_kn<<<dim3(16, 64), tb>>>(W2 + o1,   wt + WT2 + o1,   DFFn, Dn);
    }
    transpose_kn<<<dim3(16, 16), tb>>>(Wproj, wt + WTP, Dn, Dn);
    transpose_kn<<<dim3(16, 4),  tb>>>(Wfea,  wt + WTF, DRESn, Dn);

    // conv1d as GEMM -> emb fp32 output + h16 (layer-0 activation, half)
    gemm_mma<128,0><<<dim3(4, 64), 256, SM128>>>(xcat, 128, wt + KTF, 128, nullptr,
                                                 emb, h16, Dn, 128, 1.0f, 0);

    for (int l = 0; l < NLn; l++) {
        const float* hin = (l == 0) ? emb : h;   // fp32 residual source
        // h16 always holds current activation in half
        size_t o512 = (size_t)l * Dn * Dn, o1 = (size_t)l * Dn * DFFn;
        gemm_mma<128,0><<<dim3(4, 64), 256, SM128>>>(h16, Dn, wt + WTQ + o512, Dn,
                                                     bq + l * Dn, nullptr, q, Dn, Dn, 1.0f, 0);
        gemm_mma<128,0><<<dim3(4, 64), 256, SM128>>>(h16, Dn, wt + WTK + o512, Dn,
                                                     bk + l * Dn, nullptr, k, Dn, Dn, 1.0f, 0);
        gemm_mma<128,0><<<dim3(4, 64), 256, SM128>>>(h16, Dn, wt + WTV + o512, Dn,
                                                     bv + l * Dn, nullptr, v, Dn, Dn, 1.0f, 0);
        transpose_v<<<dim3(8, BHn), 256>>>(v, vt);
        fused_scores_softmax<<<dim3(BHn, 16), 256, FS_SMEM>>>(q, k, scores);
        gemm_mma<64,2><<<dim3(1, 4, BHn), 256, SM64>>>(scores, Ln, vt, Ln, nullptr,
                                                       nullptr, attnv, Dn, Ln, 1.0f, 0);
        gemm_mma<128,0><<<dim3(4, 64), 256, SM128>>>(attnv, Dn, wt + WTO + o512, Dn,
                                                     bo + l * Dn, tmp, nullptr, Dn, Dn, 1.0f, 0);
        add_ln512<<<Mn, 256>>>(hin, tmp, n1g + l * Dn, n1b + l * Dn, x1, x1h, nullptr);
        gemm_mma<128,0><<<dim3(16, 64), 256, SM128>>>(x1h, Dn, wt + WT1 + o1, Dn,
                                                      b1 + l * DFFn, nullptr, ff1, DFFn, Dn, 1.0f, 1);
        gemm_mma<128,0><<<dim3(4, 64), 256, SM128>>>(ff1, DFFn, wt + WT2 + o1, DFFn,
                                                     b2 + l * Dn, tmp, nullptr, Dn, DFFn, 1.0f, 0);
        add_ln512<<<Mn, 256>>>(x1, tmp, n2g + l * Dn, n2b + l * Dn, h, h16, nullptr);
    }

    // final LN: enc in half (GEMM-only consumer) + enc_res fp32 fused
    add_ln512<<<Mn, 256>>>(h, nullptr, nfg, nfb, nullptr, enc16, out + OFF_RES);

    gemm_mma<128,0><<<dim3(4, 64), 256, SM128>>>(enc16 + (Dn - DRESn), Dn, wt + WTF, DRESn,
                                                 bfea, out + OFF_FEA, nullptr, Dn, DRESn, 1.0f, 0);
    gemm_mma<128,0><<<dim3(4, 64), 256, SM128>>>(enc16, Dn, wt + WTP, Dn,
                                                 bproj, out + OFF_REC, nullptr, Dn, Dn, 1.0f, 0);
}

// round 7
// speedup vs baseline: 1.6184x; 1.0209x over previous
#include <cuda_runtime.h>
#include <cuda.h>
#include <cuda_fp16.h>
#include <math.h>

#define Bn   16
#define Ln   512
#define Cn   38
#define Dn   512
#define Hn   8
#define En   64
#define DFFn 2048
#define NLn  3
#define DRESn 128
#define Mn   (Bn*Ln)     /* 8192 */
#define BHn  (Bn*Hn)     /* 128  */

// ---------------- scratch (static device memory) ----------------
__device__ float  g_h   [Mn*Dn];
__device__ float  g_x1  [Mn*Dn];
__device__ float  g_tmp [Mn*Dn];
__device__ __align__(16) __half g_h16  [Mn*Dn];
__device__ __align__(16) __half g_x1h  [Mn*Dn];
__device__ __align__(16) __half g_enc16[Mn*Dn];
__device__ __align__(16) __half g_qkv  [Mn*1536];
__device__ __align__(16) __half g_attnv[Mn*Dn];
__device__ __align__(16) __half g_ff1  [Mn*DFFn];
__device__ __align__(16) __half g_xcat [Mn*128];
__device__ __align__(16) __half g_vt   [BHn*En*Ln];   // [z][e][s]
__device__ __align__(16) __half g_wt   [9830400];     // transposed weights (half)
__device__ float  g_bqkv[NLn*1536];

#define WQKV(l) ((size_t)(l) * 786432)                 /* fused [1536][512] per layer */
#define WTO 2359296
#define WT1 3145728
#define WT2 6291456
#define WTP 9437184
#define WTF 9699328
#define KTF 9764864

// ================= helpers =================
__device__ __forceinline__ unsigned smem_u32(const void* p) {
    unsigned a;
    asm("{ .reg .u64 t; cvta.to.shared.u64 t, %1; cvt.u32.u64 %0, t; }"
        : "=r"(a) : "l"(p));
    return a;
}
__device__ __forceinline__ void mma16(float* c, const unsigned* a, const unsigned* b) {
    asm volatile("mma.sync.aligned.m16n8k16.row.col.f32.f16.f16.f32 "
        "{%0,%1,%2,%3}, {%4,%5,%6,%7}, {%8,%9}, {%0,%1,%2,%3};"
        : "+f"(c[0]), "+f"(c[1]), "+f"(c[2]), "+f"(c[3])
        : "r"(a[0]), "r"(a[1]), "r"(a[2]), "r"(a[3]), "r"(b[0]), "r"(b[1]));
}
__device__ __forceinline__ void ldsm4(unsigned* r, unsigned addr) {
    asm volatile("ldmatrix.sync.aligned.m8n8.x4.shared.b16 {%0,%1,%2,%3}, [%4];"
        : "=r"(r[0]), "=r"(r[1]), "=r"(r[2]), "=r"(r[3]) : "r"(addr));
}
__device__ __forceinline__ unsigned h2u(__half2 v) { return *(unsigned*)&v; }
#define CP16(sa, gp) \
    asm volatile("cp.async.cg.shared.global [%0], [%1], 16;" :: "r"(sa), "l"(gp))
#define CPCOMMIT() asm volatile("cp.async.commit_group;" ::: "memory")
#define CPWAIT(n)  asm volatile("cp.async.wait_group %0;" :: "n"(n) : "memory")

// ================= fp16 tensor-core GEMM =================
template<int NT>
__global__ __launch_bounds__(256, 2)
void gemm_mma(const __half* __restrict__ A, int lda,
              const __half* __restrict__ BT, int ldb,
              const float* __restrict__ bias,
              float* __restrict__ C, __half* __restrict__ C16, int ldc,
              int K, int do_gelu)
{
    constexpr int WC  = 4;
    constexpr int WM  = 64;
    constexpr int MT  = WM / 16;
    constexpr int RS  = 40;
    constexpr int STG = (128 + NT) * RS;

    extern __shared__ __align__(16) char dsm[];
    __half* sm = (__half*)dsm;
    const int tid = threadIdx.x, w = tid >> 5, lane = tid & 31;
    const int m0 = blockIdx.y * 128, n0 = blockIdx.x * NT;
    const int g = lane >> 3, lr = lane & 7;

    auto load_stage = [&](int kc, int st) {
        __half* As = sm + st * STG;
        __half* Bs = As + 128 * RS;
        const __half* Ap = A + (size_t)m0 * lda + kc * 32;
#pragma unroll
        for (int i = 0; i < 2; i++) {
            int fi = tid + i * 256, row = fi >> 2, seg = fi & 3;
            CP16(smem_u32(As + row * RS + seg * 8), Ap + (size_t)row * lda + seg * 8);
        }
        const __half* Bp = BT + (size_t)n0 * ldb + kc * 32;
#pragma unroll
        for (int i = 0; i < NT / 64; i++) {
            int fi = tid + i * 256, row = fi >> 2, seg = fi & 3;
            CP16(smem_u32(Bs + row * RS + seg * 8), Bp + (size_t)row * ldb + seg * 8);
        }
    };

    float acc[MT][4][4];
#pragma unroll
    for (int mt = 0; mt < MT; mt++)
#pragma unroll
        for (int nt = 0; nt < 4; nt++)
#pragma unroll
            for (int j = 0; j < 4; j++) acc[mt][nt][j] = 0.f;

    const int wm0 = (w / WC) * WM, wn0 = (w % WC) * 32;
    const int r = lane >> 2, cl = lane & 3;
    const unsigned aLane = ((g & 1) * 8 + lr) * RS + (g >> 1) * 8;
    const unsigned bLane = ((g >> 1) * 8 + lr) * RS + (g & 1) * 8;

    auto compute = [&](int st) {
        __half* As = sm + st * STG;
        __half* Bs = As + 128 * RS;
        unsigned aBase = smem_u32(As) + 2u * (wm0 * RS + aLane);
        unsigned bBase = smem_u32(Bs) + 2u * (wn0 * RS + bLane);
#pragma unroll
        for (int ks = 0; ks < 2; ks++) {
            const unsigned koff = ks * 32;
            unsigned a[MT][4], b[4][2];
#pragma unroll
            for (int mt = 0; mt < MT; mt++)
                ldsm4(a[mt], aBase + mt * (16 * RS * 2) + koff);
#pragma unroll
            for (int p = 0; p < 2; p++) {
                unsigned t[4];
                ldsm4(t, bBase + p * (16 * RS * 2) + koff);
                b[2 * p][0] = t[0]; b[2 * p][1] = t[1];
                b[2 * p + 1][0] = t[2]; b[2 * p + 1][1] = t[3];
            }
#pragma unroll
            for (int mt = 0; mt < MT; mt++)
#pragma unroll
                for (int nt = 0; nt < 4; nt++)
                    mma16(acc[mt][nt], a[mt], b[nt]);
        }
    };

    const int NC = K >> 5;
    load_stage(0, 0);
    CPCOMMIT();
    for (int c = 0; c < NC; c++) {
        if (c + 1 < NC) { load_stage(c + 1, (c + 1) & 1); CPCOMMIT(); CPWAIT(1); }
        else            { CPWAIT(0); }
        __syncthreads();
        compute(c & 1);
        __syncthreads();
    }

#pragma unroll
    for (int mt = 0; mt < MT; mt++) {
#pragma unroll
        for (int nt = 0; nt < 4; nt++) {
            int row = m0 + wm0 + mt * 16 + r;
            int col = n0 + wn0 + nt * 8 + cl * 2;
            float bs0 = bias ? bias[col] : 0.f;
            float bs1 = bias ? bias[col + 1] : 0.f;
            float v0 = acc[mt][nt][0] + bs0;
            float v1 = acc[mt][nt][1] + bs1;
            float v2 = acc[mt][nt][2] + bs0;
            float v3 = acc[mt][nt][3] + bs1;
            if (do_gelu) {
                v0 = 0.5f * v0 * (1.0f + erff(v0 * 0.70710678118654752f));
                v1 = 0.5f * v1 * (1.0f + erff(v1 * 0.70710678118654752f));
                v2 = 0.5f * v2 * (1.0f + erff(v2 * 0.70710678118654752f));
                v3 = 0.5f * v3 * (1.0f + erff(v3 * 0.70710678118654752f));
            }
            if (C) {
                float* p0 = C + (size_t)row * ldc + col;
                float* p1 = p0 + (size_t)8 * ldc;
                p0[0] = v0; p0[1] = v1;
                p1[0] = v2; p1[1] = v3;
            }
            if (C16) {
                *(__half2*)(C16 + (size_t)row * ldc + col) = __floats2half2_rn(v0, v1);
                *(__half2*)(C16 + (size_t)(row + 8) * ldc + col) = __floats2half2_rn(v2, v3);
            }
        }
    }
}

// ================= flash attention: scores + softmax + P.V =================
#define FL_RSQ 72
#define FL_RSK 72
#define FL_RSV 520
#define FL_KOFF (32*FL_RSQ)
#define FL_VOFF (FL_KOFF + 512*FL_RSK)
#define FL_REDB ((FL_VOFF + 64*FL_RSV)*2)
#define FL_SMEM (FL_REDB + 2048 + 16)

__global__ __launch_bounds__(256, 1)
void flash_attn(const __half* __restrict__ qkv,
                const __half* __restrict__ vt,
                __half* __restrict__ attnv)
{
    extern __shared__ __align__(16) char dsm[];
    __half* Qs = (__half*)dsm;
    __half* Ks = Qs + FL_KOFF;
    __half* Vs = Qs + FL_VOFF;
    float* red  = (float*)(dsm + FL_REDB);
    float* red2 = red + 256;

    const int tid = threadIdx.x, w = tid >> 5, lane = tid & 31;
    const int r = lane >> 2, cl = lane & 3;
    const int g = lane >> 3, lr = lane & 7;
    const int z = blockIdx.x;
    const int m0 = blockIdx.y * 32;
    const int b = z >> 3, hh = z & 7;
    const size_t qbase = ((size_t)b * Ln) * 1536 + (size_t)hh * 64;

    {
        int row = tid >> 3, seg = tid & 7;
        *(uint4*)(Qs + row * FL_RSQ + seg * 8) =
            *(const uint4*)(qkv + qbase + (size_t)(m0 + row) * 1536 + seg * 8);
    }
#pragma unroll 4
    for (int i = 0; i < 16; i++) {
        int idx = tid + i * 256, krow = idx >> 3, ks = idx & 7;
        *(uint4*)(Ks + krow * FL_RSK + ks * 8) =
            *(const uint4*)(qkv + qbase + 512 + (size_t)krow * 1536 + ks * 8);
    }
    {
        const __half* vp = vt + (size_t)z * En * Ln;
#pragma unroll 4
        for (int i = 0; i < 16; i++) {
            int idx = tid + i * 256, vrow = idx >> 6, vs = idx & 63;
            *(uint4*)(Vs + vrow * FL_RSV + vs * 8) =
                *(const uint4*)(vp + (size_t)vrow * Ln + vs * 8);
        }
    }
    __syncthreads();

    const int wn0 = w * 64;
    float acc[2][8][4];
#pragma unroll
    for (int mt = 0; mt < 2; mt++)
#pragma unroll
        for (int nt = 0; nt < 8; nt++)
#pragma unroll
            for (int j = 0; j < 4; j++) acc[mt][nt][j] = 0.f;

    const unsigned aBase = smem_u32(Qs) + 2u * (((g & 1) * 8 + lr) * FL_RSQ + (g >> 1) * 8);
    const unsigned bBase = smem_u32(Ks) + 2u * ((wn0 + (g >> 1) * 8 + lr) * FL_RSK + (g & 1) * 8);
#pragma unroll
    for (int ks = 0; ks < 4; ks++) {
        const unsigned koff = ks * 32;
        unsigned a[2][4], b[8][2];
#pragma unroll
        for (int mt = 0; mt < 2; mt++)
            ldsm4(a[mt], aBase + mt * (16 * FL_RSQ * 2) + koff);
#pragma unroll
        for (int p = 0; p < 4; p++) {
            unsigned t[4];
            ldsm4(t, bBase + p * (16 * FL_RSK * 2) + koff);
            b[2 * p][0] = t[0]; b[2 * p][1] = t[1];
            b[2 * p + 1][0] = t[2]; b[2 * p + 1][1] = t[3];
        }
#pragma unroll
        for (int mt = 0; mt < 2; mt++)
#pragma unroll
            for (int nt = 0; nt < 8; nt++)
                mma16(acc[mt][nt], a[mt], b[nt]);
    }

    float M[4], inv[4];
#pragma unroll
    for (int rs = 0; rs < 4; rs++) {
        int mt = rs >> 1, jb = (rs & 1) * 2;
        float mx = -1e30f;
#pragma unroll
        for (int nt = 0; nt < 8; nt++)
            mx = fmaxf(mx, fmaxf(acc[mt][nt][jb], acc[mt][nt][jb + 1]));
        mx = fmaxf(mx, __shfl_xor_sync(0xFFFFFFFFu, mx, 1));
        mx = fmaxf(mx, __shfl_xor_sync(0xFFFFFFFFu, mx, 2));
        if (cl == 0) red[w * 32 + mt * 16 + r + (rs & 1) * 8] = mx;
    }
    __syncthreads();
#pragma unroll
    for (int rs = 0; rs < 4; rs++) {
        int row = (rs >> 1) * 16 + r + (rs & 1) * 8;
        float mx = -1e30f;
#pragma unroll
        for (int w2 = 0; w2 < 8; w2++) mx = fmaxf(mx, red[w2 * 32 + row]);
        M[rs] = mx;
    }
#pragma unroll
    for (int rs = 0; rs < 4; rs++) {
        int mt = rs >> 1, jb = (rs & 1) * 2;
        float s = 0.f;
#pragma unroll
        for (int nt = 0; nt < 8; nt++) {
            float e0 = __expf((acc[mt][nt][jb]     - M[rs]) * 0.125f);
            float e1 = __expf((acc[mt][nt][jb + 1] - M[rs]) * 0.125f);
            acc[mt][nt][jb] = e0; acc[mt][nt][jb + 1] = e1;
            s += e0 + e1;
        }
        s += __shfl_xor_sync(0xFFFFFFFFu, s, 1);
        s += __shfl_xor_sync(0xFFFFFFFFu, s, 2);
        if (cl == 0) red2[w * 32 + mt * 16 + r + (rs & 1) * 8] = s;
    }
    __syncthreads();
#pragma unroll
    for (int rs = 0; rs < 4; rs++) {
        int row = (rs >> 1) * 16 + r + (rs & 1) * 8;
        float s = 0.f;
#pragma unroll
        for (int w2 = 0; w2 < 8; w2++) s += red2[w2 * 32 + row];
        inv[rs] = 1.0f / s;
    }

    // ---- P.V over this warp's 64 s-values ----
    float o[2][8][4];
#pragma unroll
    for (int mt = 0; mt < 2; mt++)
#pragma unroll
        for (int nt = 0; nt < 8; nt++)
#pragma unroll
            for (int j = 0; j < 4; j++) o[mt][nt][j] = 0.f;

    const unsigned vBase = smem_u32(Vs) + 2u * (((g >> 1) * 8 + lr) * FL_RSV + wn0 + (g & 1) * 8);
#pragma unroll
    for (int t = 0; t < 4; t++) {
        unsigned a[2][4], b[8][2];
#pragma unroll
        for (int mt = 0; mt < 2; mt++) {
            a[mt][0] = h2u(__floats2half2_rn(acc[mt][2*t][0]   * inv[2*mt],     acc[mt][2*t][1]   * inv[2*mt]));
            a[mt][1] = h2u(__floats2half2_rn(acc[mt][2*t][2]   * inv[2*mt + 1], acc[mt][2*t][3]   * inv[2*mt + 1]));
            a[mt][2] = h2u(__floats2half2_rn(acc[mt][2*t+1][0] * inv[2*mt],     acc[mt][2*t+1][1] * inv[2*mt]));
            a[mt][3] = h2u(__floats2half2_rn(acc[mt][2*t+1][2] * inv[2*mt + 1], acc[mt][2*t+1][3] * inv[2*mt + 1]));
        }
#pragma unroll
        for (int p = 0; p < 4; p++) {
            unsigned tb[4];
            ldsm4(tb, vBase + p * (16 * FL_RSV * 2) + t * 32);
            b[2 * p][0] = tb[0]; b[2 * p][1] = tb[1];
            b[2 * p + 1][0] = tb[2]; b[2 * p + 1][1] = tb[3];
        }
#pragma unroll
        for (int mt = 0; mt < 2; mt++)
#pragma unroll
            for (int nt = 0; nt < 8; nt++)
                mma16(o[mt][nt], a[mt], b[nt]);
    }

    // ---- cross-warp reduce (partials overlay dead K region) ----
    float* part = (float*)(dsm + FL_KOFF * 2);
#pragma unroll
    for (int mt = 0; mt < 2; mt++)
#pragma unroll
        for (int nt = 0; nt < 8; nt++) {
            int row = mt * 16 + r, col = nt * 8 + cl * 2;
            float* p = part + w * 2112 + row * 66 + col;
            p[0] = o[mt][nt][0]; p[1] = o[mt][nt][1];
            p[8 * 66] = o[mt][nt][2]; p[8 * 66 + 1] = o[mt][nt][3];
        }
    __syncthreads();

    {
        int orow = tid >> 3, c0 = (tid & 7) * 8;
        float s[8];
#pragma unroll
        for (int c = 0; c < 8; c++) s[c] = 0.f;
#pragma unroll
        for (int w2 = 0; w2 < 8; w2++) {
            const float* p = part + w2 * 2112 + orow * 66 + c0;
#pragma unroll
            for (int c = 0; c < 8; c++) s[c] += p[c];
        }
        __align__(16) __half2 hb[4];
#pragma unroll
        for (int c = 0; c < 4; c++) hb[c] = __floats2half2_rn(s[2 * c], s[2 * c + 1]);
        *(uint4*)(attnv + ((size_t)b * Ln + m0 + orow) * Dn + hh * 64 + c0) = *(uint4*)hb;
    }
}

// ================= packing / transpose =================
__global__ void pack_xcat(const float* __restrict__ x, __half* __restrict__ xc) {
    int bl = blockIdx.x;
    int b = bl >> 9, l = bl & 511;
    int i = threadIdx.x;
    float val = 0.f;
    if (i < Cn * 3) {
        int c = i / 3, t = i - c * 3;
        int ls = (l - 1 + t + Ln) & (Ln - 1);
        val = x[((size_t)b * Ln + ls) * Cn + c];
    }
    xc[(size_t)bl * 128 + i] = __float2half(val);
}
__global__ void pack_ktf(const float* __restrict__ kern, __half* __restrict__ kt) {
    int d = blockIdx.x, i = threadIdx.x;
    kt[(size_t)d * 128 + i] = __float2half((i < Cn * 3) ? kern[(size_t)d * (Cn * 3) + i] : 0.f);
}
__global__ void pack_bqkv(const float* __restrict__ bq, const float* __restrict__ bk,
                          const float* __restrict__ bv, float* __restrict__ dst) {
    int l = blockIdx.x, i = threadIdx.x;
    dst[l * 1536 + i]        = bq[l * 512 + i];
    dst[l * 1536 + 512 + i]  = bk[l * 512 + i];
    dst[l * 1536 + 1024 + i] = bv[l * 512 + i];
}
__global__ void transpose_kn(const float* __restrict__ in, __half* __restrict__ out,
                             int K, int N) {
    __shared__ float t[32][33];
    int k0 = blockIdx.y * 32, n0 = blockIdx.x * 32;
    int tx = threadIdx.x, ty = threadIdx.y;
#pragma unroll
    for (int r = 0; r < 4; r++)
        t[ty + r * 8][tx] = in[(size_t)(k0 + ty + r * 8) * N + n0 + tx];
    __syncthreads();
#pragma unroll
    for (int r = 0; r < 4; r++)
        out[(size_t)(n0 + ty + r * 8) * K + k0 + tx] = __float2half(t[tx][ty + r * 8]);
}
__global__ void transpose_v(const __half* __restrict__ qkv, __half* __restrict__ vt) {
    __shared__ __half t[64][72];
    int z = blockIdx.y, s0 = blockIdx.x * 64;
    int b = z >> 3, h = z & 7;
    const __half* src = qkv + ((size_t)b * Ln) * 1536 + (size_t)h * 64 + 1024;
    int e = threadIdx.x & 63, idx = threadIdx.x >> 6;
#pragma unroll
    for (int r = 0; r < 16; r++)
        t[idx + r * 4][e] = src[(size_t)(s0 + idx + r * 4) * 1536 + e];
    __syncthreads();
    __half* dst = vt + (size_t)z * En * Ln;
#pragma unroll
    for (int r = 0; r < 16; r++)
        dst[(size_t)(idx + r * 4) * Ln + s0 + e] = t[e][idx + r * 4];
}

// ===== layernorm =====
__global__ void add_ln512(const float* __restrict__ a, const float* __restrict__ b,
                          const float* __restrict__ g, const float* __restrict__ be,
                          float* __restrict__ o, __half* __restrict__ o16,
                          float* __restrict__ res) {
    int row = blockIdx.x, t = threadIdx.x;
    size_t base = (size_t)row * Dn;
    float v0 = a[base + t], v1 = a[base + t + 256];
    if (b) { v0 += b[base + t]; v1 += b[base + t + 256]; }
    float s = v0 + v1;
#pragma unroll
    for (int oo = 16; oo > 0; oo >>= 1) s += __shfl_xor_sync(0xFFFFFFFFu, s, oo);
    __shared__ float s1[8], s2[8];
    if ((t & 31) == 0) s1[t >> 5] = s;
    __syncthreads();
    float mean = (s1[0] + s1[1] + s1[2] + s1[3] + s1[4] + s1[5] + s1[6] + s1[7]) * (1.0f / Dn);
    float d0 = v0 - mean, d1 = v1 - mean;
    float q2 = d0 * d0 + d1 * d1;
#pragma unroll
    for (int oo = 16; oo > 0; oo >>= 1) q2 += __shfl_xor_sync(0xFFFFFFFFu, q2, oo);
    if ((t & 31) == 0) s2[t >> 5] = q2;
    __syncthreads();
    float var = (s2[0] + s2[1] + s2[2] + s2[3] + s2[4] + s2[5] + s2[6] + s2[7]) * (1.0f / Dn);
    float rr = rsqrtf(var + 1e-5f);
    float o0 = d0 * rr * g[t]       + be[t];
    float o1 = d1 * rr * g[t + 256] + be[t + 256];
    if (o)  { o[base + t] = o0; o[base + t + 256] = o1; }
    if (o16) { o16[base + t] = __float2half(o0); o16[base + t + 256] = __float2half(o1); }
    if (res) {
        res[(size_t)row * 384 + t] = o0;
        if (t < 128) res[(size_t)row * 384 + t + 256] = o1;
    }
}

// ================= launcher =================
extern "C" void kernel_launch(void* const* d_in, const int* in_sizes, int n_in,
                              void* d_out, int out_size)
{
    const float* x     = (const float*)d_in[0];
    const float* embk  = (const float*)d_in[1];
    const float* Wq    = (const float*)d_in[2];
    const float* bq    = (const float*)d_in[3];
    const float* Wk    = (const float*)d_in[4];
    const float* bk    = (const float*)d_in[5];
    const float* Wv    = (const float*)d_in[6];
    const float* bv    = (const float*)d_in[7];
    // d_in[8], d_in[9]: Wsig/bsig are dead code in the reference
    const float* Wo    = (const float*)d_in[10];
    const float* bo    = (const float*)d_in[11];
    const float* W1    = (const float*)d_in[12];
    const float* b1    = (const float*)d_in[13];
    const float* W2    = (const float*)d_in[14];
    const float* b2    = (const float*)d_in[15];
    const float* n1g   = (const float*)d_in[16];
    const float* n1b   = (const float*)d_in[17];
    const float* n2g   = (const float*)d_in[18];
    const float* n2b   = (const float*)d_in[19];
    const float* nfg   = (const float*)d_in[20];
    const float* nfb   = (const float*)d_in[21];
    const float* Wproj = (const float*)d_in[22];
    const float* bproj = (const float*)d_in[23];
    const float* Wfea  = (const float*)d_in[24];
    const float* bfea  = (const float*)d_in[25];
    float* out = (float*)d_out;

    float *h, *x1, *tmp, *bqkv;
    __half *h16,*x1h,*enc16,*qkv,*attnv,*ff1,*xcat,*vt,*wt;
    cudaGetSymbolAddress((void**)&h,     g_h);
    cudaGetSymbolAddress((void**)&x1,    g_x1);
    cudaGetSymbolAddress((void**)&tmp,   g_tmp);
    cudaGetSymbolAddress((void**)&bqkv,  g_bqkv);
    cudaGetSymbolAddress((void**)&h16,   g_h16);
    cudaGetSymbolAddress((void**)&x1h,   g_x1h);
    cudaGetSymbolAddress((void**)&enc16, g_enc16);
    cudaGetSymbolAddress((void**)&qkv,   g_qkv);
    cudaGetSymbolAddress((void**)&attnv, g_attnv);
    cudaGetSymbolAddress((void**)&ff1,   g_ff1);
    cudaGetSymbolAddress((void**)&xcat,  g_xcat);
    cudaGetSymbolAddress((void**)&vt,    g_vt);
    cudaGetSymbolAddress((void**)&wt,    g_wt);

    const size_t OFF_FEA = 0;
    const size_t OFF_RES = (size_t)Mn * Dn;
    const size_t OFF_REC = OFF_RES + (size_t)Mn * 384;
    const size_t OFF_EMB = OFF_REC + (size_t)Mn * Dn;
    float* emb = out + OFF_EMB;

    const int SM128 = (128 + 128) * 40 * 2 * 2;   // 40960 B
    cudaFuncSetAttribute((const void*)gemm_mma<128>, cudaFuncAttributeMaxDynamicSharedMemorySize, SM128);
    cudaFuncSetAttribute((const void*)flash_attn, cudaFuncAttributeMaxDynamicSharedMemorySize, FL_SMEM);

    pack_ktf<<<512, 128>>>(embk, wt + KTF);
    pack_xcat<<<Mn, 128>>>(x, xcat);
    pack_bqkv<<<NLn, 512>>>(bq, bk, bv, bqkv);
    dim3 tb(32, 8);
    for (int l = 0; l < NLn; l++) {
        size_t o512 = (size_t)l * Dn * Dn, o1 = (size_t)l * Dn * DFFn;
        transpose_kn<<<dim3(16, 16), tb>>>(Wq + o512, wt + WQKV(l),          Dn, Dn);
        transpose_kn<<<dim3(16, 16), tb>>>(Wk + o512, wt + WQKV(l) + 262144, Dn, Dn);
        transpose_kn<<<dim3(16, 16), tb>>>(Wv + o512, wt + WQKV(l) + 524288, Dn, Dn);
        transpose_kn<<<dim3(16, 16), tb>>>(Wo + o512, wt + WTO + o512, Dn, Dn);
        transpose_kn<<<dim3(64, 16), tb>>>(W1 + o1,   wt + WT1 + o1,   Dn, DFFn);
        transpose_kn<<<dim3(16, 64), tb>>>(W2 + o1,   wt + WT2 + o1,   DFFn, Dn);
    }
    transpose_kn<<<dim3(16, 16), tb>>>(Wproj, wt + WTP, Dn, Dn);
    transpose_kn<<<dim3(16, 4),  tb>>>(Wfea,  wt + WTF, DRESn, Dn);

    gemm_mma<128><<<dim3(4, 64), 256, SM128>>>(xcat, 128, wt + KTF, 128, nullptr,
                                               emb, h16, Dn, 128, 0);

    for (int l = 0; l < NLn; l++) {
        const float* hin = (l == 0) ? emb : h;
        size_t o512 = (size_t)l * Dn * Dn, o1 = (size_t)l * Dn * DFFn;
        gemm_mma<128><<<dim3(12, 64), 256, SM128>>>(h16, Dn, wt + WQKV(l), Dn,
                                                    bqkv + l * 1536, nullptr, qkv, 1536, Dn, 0);
        transpose_v<<<dim3(8, BHn), 256>>>(qkv, vt);
        flash_attn<<<dim3(BHn, 16), 256, FL_SMEM>>>(qkv, vt, attnv);
        gemm_mma<128><<<dim3(4, 64), 256, SM128>>>(attnv, Dn, wt + WTO + o512, Dn,
                                                   bo + l * Dn, tmp, nullptr, Dn, Dn, 0);
        add_ln512<<<Mn, 256>>>(hin, tmp, n1g + l * Dn, n1b + l * Dn, x1, x1h, nullptr);
        gemm_mma<128><<<dim3(16, 64), 256, SM128>>>(x1h, Dn, wt + WT1 + o1, Dn,
                                                    b1 + l * DFFn, nullptr, ff1, DFFn, Dn, 1);
        gemm_mma<128><<<dim3(4, 64), 256, SM128>>>(ff1, DFFn, wt + WT2 + o1, DFFn,
                                                   b2 + l * Dn, tmp, nullptr, Dn, DFFn, 0);
        add_ln512<<<Mn, 256>>>(x1, tmp, n2g + l * Dn, n2b + l * Dn, h, h16, nullptr);
    }

    add_ln512<<<Mn, 256>>>(h, nullptr, nfg, nfb, nullptr, enc16, out + OFF_RES);

    gemm_mma<128><<<dim3(4, 64), 256, SM128>>>(enc16 + (Dn - DRESn), Dn, wt + WTF, DRESn,
                                               bfea, out + OFF_FEA, nullptr, Dn, DRESn, 0);
    gemm_mma<128><<<dim3(4, 64), 256, SM128>>>(enc16, Dn, wt + WTP, Dn,
                                               bproj, out + OFF_REC, nullptr, Dn, Dn, 0);
}

// round 9
// speedup vs baseline: 1.8627x; 1.1510x over previous
#include <cuda_runtime.h>
#include <cuda.h>
#include <cuda_fp16.h>
#include <math.h>

#define Bn   16
#define Ln   512
#define Cn   38
#define Dn   512
#define Hn   8
#define En   64
#define DFFn 2048
#define NLn  3
#define DRESn 128
#define Mn   (Bn*Ln)     /* 8192 */
#define BHn  (Bn*Hn)     /* 128  */

// ---------------- scratch (static device memory) ----------------
__device__ float  g_h   [Mn*Dn];
__device__ float  g_x1  [Mn*Dn];
__device__ float  g_tmp [Mn*Dn];
__device__ __align__(16) __half g_h16  [Mn*Dn];
__device__ __align__(16) __half g_x1h  [Mn*Dn];
__device__ __align__(16) __half g_enc16[Mn*Dn];
__device__ __align__(16) __half g_qkv  [Mn*1536];
__device__ __align__(16) __half g_attnv[Mn*Dn];
__device__ __align__(16) __half g_ff1  [Mn*DFFn];
__device__ __align__(16) __half g_xcat [Mn*128];
__device__ __align__(16) __half g_vt   [BHn*En*Ln];   // [z][e][s]
__device__ __align__(16) __half g_wt   [9830400];     // transposed weights (half)
__device__ float  g_bqkv[NLn*1536];

#define WQKV(l) ((size_t)(l) * 786432)                 /* fused [1536][512] per layer */
#define WTO 2359296
#define WT1 3145728
#define WT2 6291456
#define WTP 9437184
#define WTF 9699328
#define KTF 9764864

// ================= helpers =================
__device__ __forceinline__ unsigned smem_u32(const void* p) {
    unsigned a;
    asm("{ .reg .u64 t; cvta.to.shared.u64 t, %1; cvt.u32.u64 %0, t; }"
        : "=r"(a) : "l"(p));
    return a;
}
__device__ __forceinline__ void mma16(float* c, const unsigned* a, const unsigned* b) {
    asm volatile("mma.sync.aligned.m16n8k16.row.col.f32.f16.f16.f32 "
        "{%0,%1,%2,%3}, {%4,%5,%6,%7}, {%8,%9}, {%0,%1,%2,%3};"
        : "+f"(c[0]), "+f"(c[1]), "+f"(c[2]), "+f"(c[3])
        : "r"(a[0]), "r"(a[1]), "r"(a[2]), "r"(a[3]), "r"(b[0]), "r"(b[1]));
}
__device__ __forceinline__ void ldsm4(unsigned* r, unsigned addr) {
    asm volatile("ldmatrix.sync.aligned.m8n8.x4.shared.b16 {%0,%1,%2,%3}, [%4];"
        : "=r"(r[0]), "=r"(r[1]), "=r"(r[2]), "=r"(r[3]) : "r"(addr));
}
__device__ __forceinline__ unsigned h2u(__half2 v) { return *(unsigned*)&v; }
#define CP16(sa, gp) \
    asm volatile("cp.async.cg.shared.global [%0], [%1], 16;" :: "r"(sa), "l"(gp))
#define CPCOMMIT() asm volatile("cp.async.commit_group;" ::: "memory")
#define CPWAIT(n)  asm volatile("cp.async.wait_group %0;" :: "n"(n) : "memory")

// ================= fp16 tensor-core GEMM (3-stage pipeline) =================
template<int NT>
__global__ __launch_bounds__(256, 2)
void gemm_mma(const __half* __restrict__ A, int lda,
              const __half* __restrict__ BT, int ldb,
              const float* __restrict__ bias,
              float* __restrict__ C, __half* __restrict__ C16, int ldc,
              int K, int do_gelu)
{
    constexpr int WC  = 4;
    constexpr int WM  = 64;
    constexpr int MT  = WM / 16;
    constexpr int RS  = 40;
    constexpr int STG = (128 + NT) * RS;

    extern __shared__ __align__(16) char dsm[];
    __half* sm = (__half*)dsm;
    const int tid = threadIdx.x, w = tid >> 5, lane = tid & 31;
    const int m0 = blockIdx.y * 128, n0 = blockIdx.x * NT;
    const int g = lane >> 3, lr = lane & 7;

    auto load_stage = [&](int kc, int st) {
        __half* As = sm + st * STG;
        __half* Bs = As + 128 * RS;
        const __half* Ap = A + (size_t)m0 * lda + kc * 32;
#pragma unroll
        for (int i = 0; i < 2; i++) {
            int fi = tid + i * 256, row = fi >> 2, seg = fi & 3;
            CP16(smem_u32(As + row * RS + seg * 8), Ap + (size_t)row * lda + seg * 8);
        }
        const __half* Bp = BT + (size_t)n0 * ldb + kc * 32;
#pragma unroll
        for (int i = 0; i < NT / 64; i++) {
            int fi = tid + i * 256, row = fi >> 2, seg = fi & 3;
            CP16(smem_u32(Bs + row * RS + seg * 8), Bp + (size_t)row * ldb + seg * 8);
        }
    };

    float acc[MT][4][4];
#pragma unroll
    for (int mt = 0; mt < MT; mt++)
#pragma unroll
        for (int nt = 0; nt < 4; nt++)
#pragma unroll
            for (int j = 0; j < 4; j++) acc[mt][nt][j] = 0.f;

    const int wm0 = (w / WC) * WM, wn0 = (w % WC) * 32;
    const int r = lane >> 2, cl = lane & 3;
    const unsigned aLane = ((g & 1) * 8 + lr) * RS + (g >> 1) * 8;
    const unsigned bLane = ((g >> 1) * 8 + lr) * RS + (g & 1) * 8;

    auto compute = [&](int st) {
        __half* As = sm + st * STG;
        __half* Bs = As + 128 * RS;
        unsigned aBase = smem_u32(As) + 2u * (wm0 * RS + aLane);
        unsigned bBase = smem_u32(Bs) + 2u * (wn0 * RS + bLane);
#pragma unroll
        for (int ks = 0; ks < 2; ks++) {
            const unsigned koff = ks * 32;
            unsigned a[MT][4], b[4][2];
#pragma unroll
            for (int mt = 0; mt < MT; mt++)
                ldsm4(a[mt], aBase + mt * (16 * RS * 2) + koff);
#pragma unroll
            for (int p = 0; p < 2; p++) {
                unsigned t[4];
                ldsm4(t, bBase + p * (16 * RS * 2) + koff);
                b[2 * p][0] = t[0]; b[2 * p][1] = t[1];
                b[2 * p + 1][0] = t[2]; b[2 * p + 1][1] = t[3];
            }
#pragma unroll
            for (int mt = 0; mt < MT; mt++)
#pragma unroll
                for (int nt = 0; nt < 4; nt++)
                    mma16(acc[mt][nt], a[mt], b[nt]);
        }
    };

    const int NC = K >> 5;                 // >= 4 for all our shapes
    load_stage(0, 0); CPCOMMIT();
    load_stage(1, 1); CPCOMMIT();
    int st = 0;
    for (int c = 0; c < NC; c++) {
        if (c + 1 < NC) { CPWAIT(1); }     // chunk c landed, chunk c+1 may fly
        else            { CPWAIT(0); }     // FINAL chunk: must be fully landed
        __syncthreads();
        compute(st);
        if (c + 2 < NC) {
            int ls = st + 2; if (ls >= 3) ls -= 3;
            load_stage(c + 2, ls);
            CPCOMMIT();
        }
        if (++st == 3) st = 0;
    }

#pragma unroll
    for (int mt = 0; mt < MT; mt++) {
#pragma unroll
        for (int nt = 0; nt < 4; nt++) {
            int row = m0 + wm0 + mt * 16 + r;
            int col = n0 + wn0 + nt * 8 + cl * 2;
            float bs0 = bias ? bias[col] : 0.f;
            float bs1 = bias ? bias[col + 1] : 0.f;
            float v0 = acc[mt][nt][0] + bs0;
            float v1 = acc[mt][nt][1] + bs1;
            float v2 = acc[mt][nt][2] + bs0;
            float v3 = acc[mt][nt][3] + bs1;
            if (do_gelu) {
                v0 = 0.5f * v0 * (1.0f + erff(v0 * 0.70710678118654752f));
                v1 = 0.5f * v1 * (1.0f + erff(v1 * 0.70710678118654752f));
                v2 = 0.5f * v2 * (1.0f + erff(v2 * 0.70710678118654752f));
                v3 = 0.5f * v3 * (1.0f + erff(v3 * 0.70710678118654752f));
            }
            if (C) {
                float* p0 = C + (size_t)row * ldc + col;
                float* p1 = p0 + (size_t)8 * ldc;
                p0[0] = v0; p0[1] = v1;
                p1[0] = v2; p1[1] = v3;
            }
            if (C16) {
                *(__half2*)(C16 + (size_t)row * ldc + col) = __floats2half2_rn(v0, v1);
                *(__half2*)(C16 + (size_t)(row + 8) * ldc + col) = __floats2half2_rn(v2, v3);
            }
        }
    }
}

// ================= flash attention: scores + softmax + P.V =================
#define FL_RSQ 72
#define FL_RSK 72
#define FL_RSV 520
#define FL_KOFF (32*FL_RSQ)
#define FL_VOFF (FL_KOFF + 512*FL_RSK)
#define FL_REDB ((FL_VOFF + 64*FL_RSV)*2)
#define FL_SMEM (FL_REDB + 2048 + 16)

__global__ __launch_bounds__(256, 1)
void flash_attn(const __half* __restrict__ qkv,
                const __half* __restrict__ vt,
                __half* __restrict__ attnv)
{
    extern __shared__ __align__(16) char dsm[];
    __half* Qs = (__half*)dsm;
    __half* Ks = Qs + FL_KOFF;
    __half* Vs = Qs + FL_VOFF;
    float* red  = (float*)(dsm + FL_REDB);
    float* red2 = red + 256;

    const int tid = threadIdx.x, w = tid >> 5, lane = tid & 31;
    const int r = lane >> 2, cl = lane & 3;
    const int g = lane >> 3, lr = lane & 7;
    const int z = blockIdx.x;
    const int m0 = blockIdx.y * 32;
    const int b = z >> 3, hh = z & 7;
    const size_t qbase = ((size_t)b * Ln) * 1536 + (size_t)hh * 64;

    {
        int row = tid >> 3, seg = tid & 7;
        *(uint4*)(Qs + row * FL_RSQ + seg * 8) =
            *(const uint4*)(qkv + qbase + (size_t)(m0 + row) * 1536 + seg * 8);
    }
#pragma unroll 4
    for (int i = 0; i < 16; i++) {
        int idx = tid + i * 256, krow = idx >> 3, ks = idx & 7;
        *(uint4*)(Ks + krow * FL_RSK + ks * 8) =
            *(const uint4*)(qkv + qbase + 512 + (size_t)krow * 1536 + ks * 8);
    }
    {
        const __half* vp = vt + (size_t)z * En * Ln;
#pragma unroll 4
        for (int i = 0; i < 16; i++) {
            int idx = tid + i * 256, vrow = idx >> 6, vs = idx & 63;
            *(uint4*)(Vs + vrow * FL_RSV + vs * 8) =
                *(const uint4*)(vp + (size_t)vrow * Ln + vs * 8);
        }
    }
    __syncthreads();

    const int wn0 = w * 64;
    float acc[2][8][4];
#pragma unroll
    for (int mt = 0; mt < 2; mt++)
#pragma unroll
        for (int nt = 0; nt < 8; nt++)
#pragma unroll
            for (int j = 0; j < 4; j++) acc[mt][nt][j] = 0.f;

    const unsigned aBase = smem_u32(Qs) + 2u * (((g & 1) * 8 + lr) * FL_RSQ + (g >> 1) * 8);
    const unsigned bBase = smem_u32(Ks) + 2u * ((wn0 + (g >> 1) * 8 + lr) * FL_RSK + (g & 1) * 8);
#pragma unroll
    for (int ks = 0; ks < 4; ks++) {
        const unsigned koff = ks * 32;
        unsigned a[2][4], b[8][2];
#pragma unroll
        for (int mt = 0; mt < 2; mt++)
            ldsm4(a[mt], aBase + mt * (16 * FL_RSQ * 2) + koff);
#pragma unroll
        for (int p = 0; p < 4; p++) {
            unsigned t[4];
            ldsm4(t, bBase + p * (16 * FL_RSK * 2) + koff);
            b[2 * p][0] = t[0]; b[2 * p][1] = t[1];
            b[2 * p + 1][0] = t[2]; b[2 * p + 1][1] = t[3];
        }
#pragma unroll
        for (int mt = 0; mt < 2; mt++)
#pragma unroll
            for (int nt = 0; nt < 8; nt++)
                mma16(acc[mt][nt], a[mt], b[nt]);
    }

    float M[4], inv[4];
#pragma unroll
    for (int rs = 0; rs < 4; rs++) {
        int mt = rs >> 1, jb = (rs & 1) * 2;
        float mx = -1e30f;
#pragma unroll
        for (int nt = 0; nt < 8; nt++)
            mx = fmaxf(mx, fmaxf(acc[mt][nt][jb], acc[mt][nt][jb + 1]));
        mx = fmaxf(mx, __shfl_xor_sync(0xFFFFFFFFu, mx, 1));
        mx = fmaxf(mx, __shfl_xor_sync(0xFFFFFFFFu, mx, 2));
        if (cl == 0) red[w * 32 + mt * 16 + r + (rs & 1) * 8] = mx;
    }
    __syncthreads();
#pragma unroll
    for (int rs = 0; rs < 4; rs++) {
        int row = (rs >> 1) * 16 + r + (rs & 1) * 8;
        float mx = -1e30f;
#pragma unroll
        for (int w2 = 0; w2 < 8; w2++) mx = fmaxf(mx, red[w2 * 32 + row]);
        M[rs] = mx;
    }
#pragma unroll
    for (int rs = 0; rs < 4; rs++) {
        int mt = rs >> 1, jb = (rs & 1) * 2;
        float s = 0.f;
#pragma unroll
        for (int nt = 0; nt < 8; nt++) {
            float e0 = __expf((acc[mt][nt][jb]     - M[rs]) * 0.125f);
            float e1 = __expf((acc[mt][nt][jb + 1] - M[rs]) * 0.125f);
            acc[mt][nt][jb] = e0; acc[mt][nt][jb + 1] = e1;
            s += e0 + e1;
        }
        s += __shfl_xor_sync(0xFFFFFFFFu, s, 1);
        s += __shfl_xor_sync(0xFFFFFFFFu, s, 2);
        if (cl == 0) red2[w * 32 + mt * 16 + r + (rs & 1) * 8] = s;
    }
    __syncthreads();
#pragma unroll
    for (int rs = 0; rs < 4; rs++) {
        int row = (rs >> 1) * 16 + r + (rs & 1) * 8;
        float s = 0.f;
#pragma unroll
        for (int w2 = 0; w2 < 8; w2++) s += red2[w2 * 32 + row];
        inv[rs] = 1.0f / s;
    }

    float o[2][8][4];
#pragma unroll
    for (int mt = 0; mt < 2; mt++)
#pragma unroll
        for (int nt = 0; nt < 8; nt++)
#pragma unroll
            for (int j = 0; j < 4; j++) o[mt][nt][j] = 0.f;

    const unsigned vBase = smem_u32(Vs) + 2u * (((g >> 1) * 8 + lr) * FL_RSV + wn0 + (g & 1) * 8);
#pragma unroll
    for (int t = 0; t < 4; t++) {
        unsigned a[2][4], b[8][2];
#pragma unroll
        for (int mt = 0; mt < 2; mt++) {
            a[mt][0] = h2u(__floats2half2_rn(acc[mt][2*t][0]   * inv[2*mt],     acc[mt][2*t][1]   * inv[2*mt]));
            a[mt][1] = h2u(__floats2half2_rn(acc[mt][2*t][2]   * inv[2*mt + 1], acc[mt][2*t][3]   * inv[2*mt + 1]));
            a[mt][2] = h2u(__floats2half2_rn(acc[mt][2*t+1][0] * inv[2*mt],     acc[mt][2*t+1][1] * inv[2*mt]));
            a[mt][3] = h2u(__floats2half2_rn(acc[mt][2*t+1][2] * inv[2*mt + 1], acc[mt][2*t+1][3] * inv[2*mt + 1]));
        }
#pragma unroll
        for (int p = 0; p < 4; p++) {
            unsigned tb[4];
            ldsm4(tb, vBase + p * (16 * FL_RSV * 2) + t * 32);
            b[2 * p][0] = tb[0]; b[2 * p][1] = tb[1];
            b[2 * p + 1][0] = tb[2]; b[2 * p + 1][1] = tb[3];
        }
#pragma unroll
        for (int mt = 0; mt < 2; mt++)
#pragma unroll
            for (int nt = 0; nt < 8; nt++)
                mma16(o[mt][nt], a[mt], b[nt]);
    }

    float* part = (float*)(dsm + FL_KOFF * 2);
#pragma unroll
    for (int mt = 0; mt < 2; mt++)
#pragma unroll
        for (int nt = 0; nt < 8; nt++) {
            int row = mt * 16 + r, col = nt * 8 + cl * 2;
            float* p = part + w * 2112 + row * 66 + col;
            p[0] = o[mt][nt][0]; p[1] = o[mt][nt][1];
            p[8 * 66] = o[mt][nt][2]; p[8 * 66 + 1] = o[mt][nt][3];
        }
    __syncthreads();

    {
        int orow = tid >> 3, c0 = (tid & 7) * 8;
        float s[8];
#pragma unroll
        for (int c = 0; c < 8; c++) s[c] = 0.f;
#pragma unroll
        for (int w2 = 0; w2 < 8; w2++) {
            const float* p = part + w2 * 2112 + orow * 66 + c0;
#pragma unroll
            for (int c = 0; c < 8; c++) s[c] += p[c];
        }
        __align__(16) __half2 hb[4];
#pragma unroll
        for (int c = 0; c < 4; c++) hb[c] = __floats2half2_rn(s[2 * c], s[2 * c + 1]);
        *(uint4*)(attnv + ((size_t)b * Ln + m0 + orow) * Dn + hh * 64 + c0) = *(uint4*)hb;
    }
}

// ================= batched weight transpose (ALL weights, one launch) =======
__global__ void transpose_all(const float* __restrict__ Wq, const float* __restrict__ Wk,
                              const float* __restrict__ Wv, const float* __restrict__ Wo,
                              const float* __restrict__ W1, const float* __restrict__ W2,
                              const float* __restrict__ Wproj, const float* __restrict__ Wfea,
                              __half* __restrict__ wt)
{
    int bid = blockIdx.x;
    const float* in; __half* out; int K, N, bx, by;
    if (bid < 9216) {
        int l = bid / 3072, rr = bid - l * 3072;
        size_t o512 = (size_t)l * 262144, o1 = (size_t)l * 1048576;
        if (rr < 1024) {
            int m = rr >> 8, idx = rr & 255;
            K = 512; N = 512; bx = idx & 15; by = idx >> 4;
            if (m == 0)      { in = Wq + o512; out = wt + WQKV(l); }
            else if (m == 1) { in = Wk + o512; out = wt + WQKV(l) + 262144; }
            else if (m == 2) { in = Wv + o512; out = wt + WQKV(l) + 524288; }
            else             { in = Wo + o512; out = wt + WTO + o512; }
        } else if (rr < 2048) {
            int idx = rr - 1024;
            K = 512; N = 2048; bx = idx & 63; by = idx >> 6;
            in = W1 + o1; out = wt + WT1 + o1;
        } else {
            int idx = rr - 2048;
            K = 2048; N = 512; bx = idx & 15; by = idx >> 4;
            in = W2 + o1; out = wt + WT2 + o1;
        }
    } else if (bid < 9472) {
        int idx = bid - 9216;
        K = 512; N = 512; bx = idx & 15; by = idx >> 4;
        in = Wproj; out = wt + WTP;
    } else {
        int idx = bid - 9472;
        K = 128; N = 512; bx = idx & 15; by = idx >> 4;
        in = Wfea; out = wt + WTF;
    }
    __shared__ float t[32][33];
    int k0 = by * 32, n0 = bx * 32;
    int tx = threadIdx.x, ty = threadIdx.y;
#pragma unroll
    for (int rr2 = 0; rr2 < 4; rr2++)
        t[ty + rr2 * 8][tx] = in[(size_t)(k0 + ty + rr2 * 8) * N + n0 + tx];
    __syncthreads();
#pragma unroll
    for (int rr2 = 0; rr2 < 4; rr2++)
        out[(size_t)(n0 + ty + rr2 * 8) * K + k0 + tx] = __float2half(t[tx][ty + rr2 * 8]);
}

// ================= packing =================
__global__ void pack_xcat(const float* __restrict__ x, __half* __restrict__ xc) {
    int bl = blockIdx.x;
    int b = bl >> 9, l = bl & 511;
    int i = threadIdx.x;
    float val = 0.f;
    if (i < Cn * 3) {
        int c = i / 3, t = i - c * 3;
        int ls = (l - 1 + t + Ln) & (Ln - 1);
        val = x[((size_t)b * Ln + ls) * Cn + c];
    }
    xc[(size_t)bl * 128 + i] = __float2half(val);
}
__global__ void pack_ktf(const float* __restrict__ kern, __half* __restrict__ kt) {
    int d = blockIdx.x, i = threadIdx.x;
    kt[(size_t)d * 128 + i] = __float2half((i < Cn * 3) ? kern[(size_t)d * (Cn * 3) + i] : 0.f);
}
__global__ void pack_bqkv(const float* __restrict__ bq, const float* __restrict__ bk,
                          const float* __restrict__ bv, float* __restrict__ dst) {
    int l = blockIdx.x, i = threadIdx.x;
    dst[l * 1536 + i]        = bq[l * 512 + i];
    dst[l * 1536 + 512 + i]  = bk[l * 512 + i];
    dst[l * 1536 + 1024 + i] = bv[l * 512 + i];
}
__global__ void transpose_v(const __half* __restrict__ qkv, __half* __restrict__ vt) {
    __shared__ __half t[64][72];
    int z = blockIdx.y, s0 = blockIdx.x * 64;
    int b = z >> 3, h = z & 7;
    const __half* src = qkv + ((size_t)b * Ln) * 1536 + (size_t)h * 64 + 1024;
    int e = threadIdx.x & 63, idx = threadIdx.x >> 6;
#pragma unroll
    for (int r = 0; r < 16; r++)
        t[idx + r * 4][e] = src[(size_t)(s0 + idx + r * 4) * 1536 + e];
    __syncthreads();
    __half* dst = vt + (size_t)z * En * Ln;
#pragma unroll
    for (int r = 0; r < 16; r++)
        dst[(size_t)(idx + r * 4) * Ln + s0 + e] = t[e][idx + r * 4];
}

// ===== layernorm (vectorized: 128 thr x float4) =====
__global__ void add_ln512(const float* __restrict__ a, const float* __restrict__ b,
                          const float* __restrict__ g, const float* __restrict__ be,
                          float* __restrict__ o, __half* __restrict__ o16,
                          float* __restrict__ res) {
    int row = blockIdx.x, t = threadIdx.x;        // 128 threads
    size_t base = (size_t)row * Dn;
    float4 v = *(const float4*)(a + base + t * 4);
    if (b) {
        float4 vb = *(const float4*)(b + base + t * 4);
        v.x += vb.x; v.y += vb.y; v.z += vb.z; v.w += vb.w;
    }
    float s = v.x + v.y + v.z + v.w;
#pragma unroll
    for (int oo = 16; oo > 0; oo >>= 1) s += __shfl_xor_sync(0xFFFFFFFFu, s, oo);
    __shared__ float s1[4], s2[4];
    if ((t & 31) == 0) s1[t >> 5] = s;
    __syncthreads();
    float mean = (s1[0] + s1[1] + s1[2] + s1[3]) * (1.0f / Dn);
    float d0 = v.x - mean, d1 = v.y - mean, d2 = v.z - mean, d3 = v.w - mean;
    float q2 = d0 * d0 + d1 * d1 + d2 * d2 + d3 * d3;
#pragma unroll
    for (int oo = 16; oo > 0; oo >>= 1) q2 += __shfl_xor_sync(0xFFFFFFFFu, q2, oo);
    if ((t & 31) == 0) s2[t >> 5] = q2;
    __syncthreads();
    float var = (s2[0] + s2[1] + s2[2] + s2[3]) * (1.0f / Dn);
    float rr = rsqrtf(var + 1e-5f);
    float4 gg = *(const float4*)(g + t * 4);
    float4 bb = *(const float4*)(be + t * 4);
    float o0 = d0 * rr * gg.x + bb.x;
    float o1 = d1 * rr * gg.y + bb.y;
    float o2 = d2 * rr * gg.z + bb.z;
    float o3 = d3 * rr * gg.w + bb.w;
    if (o) {
        float4 ov = {o0, o1, o2, o3};
        *(float4*)(o + base + t * 4) = ov;
    }
    if (o16) {
        *(__half2*)(o16 + base + t * 4)     = __floats2half2_rn(o0, o1);
        *(__half2*)(o16 + base + t * 4 + 2) = __floats2half2_rn(o2, o3);
    }
    if (res && t < 96) {
        float4 rv = {o0, o1, o2, o3};
        *(float4*)(res + (size_t)row * 384 + t * 4) = rv;
    }
}

// ================= launcher =================
extern "C" void kernel_launch(void* const* d_in, const int* in_sizes, int n_in,
                              void* d_out, int out_size)
{
    const float* x     = (const float*)d_in[0];
    const float* embk  = (const float*)d_in[1];
    const float* Wq    = (const float*)d_in[2];
    const float* bq    = (const float*)d_in[3];
    const float* Wk    = (const float*)d_in[4];
    const float* bk    = (const float*)d_in[5];
    const float* Wv    = (const float*)d_in[6];
    const float* bv    = (const float*)d_in[7];
    // d_in[8], d_in[9]: Wsig/bsig are dead code in the reference
    const float* Wo    = (const float*)d_in[10];
    const float* bo    = (const float*)d_in[11];
    const float* W1    = (const float*)d_in[12];
    const float* b1    = (const float*)d_in[13];
    const float* W2    = (const float*)d_in[14];
    const float* b2    = (const float*)d_in[15];
    const float* n1g   = (const float*)d_in[16];
    const float* n1b   = (const float*)d_in[17];
    const float* n2g   = (const float*)d_in[18];
    const float* n2b   = (const float*)d_in[19];
    const float* nfg   = (const float*)d_in[20];
    const float* nfb   = (const float*)d_in[21];
    const float* Wproj = (const float*)d_in[22];
    const float* bproj = (const float*)d_in[23];
    const float* Wfea  = (const float*)d_in[24];
    const float* bfea  = (const float*)d_in[25];
    float* out = (float*)d_out;

    float *h, *x1, *tmp, *bqkv;
    __half *h16,*x1h,*enc16,*qkv,*attnv,*ff1,*xcat,*vt,*wt;
    cudaGetSymbolAddress((void**)&h,     g_h);
    cudaGetSymbolAddress((void**)&x1,    g_x1);
    cudaGetSymbolAddress((void**)&tmp,   g_tmp);
    cudaGetSymbolAddress((void**)&bqkv,  g_bqkv);
    cudaGetSymbolAddress((void**)&h16,   g_h16);
    cudaGetSymbolAddress((void**)&x1h,   g_x1h);
    cudaGetSymbolAddress((void**)&enc16, g_enc16);
    cudaGetSymbolAddress((void**)&qkv,   g_qkv);
    cudaGetSymbolAddress((void**)&attnv, g_attnv);
    cudaGetSymbolAddress((void**)&ff1,   g_ff1);
    cudaGetSymbolAddress((void**)&xcat,  g_xcat);
    cudaGetSymbolAddress((void**)&vt,    g_vt);
    cudaGetSymbolAddress((void**)&wt,    g_wt);

    // outputs: fea_t | enc_res(384) | rec_temp(512) | emb(512)
    const size_t OFF_FEA = 0;
    const size_t OFF_RES = (size_t)Mn * Dn;
    const size_t OFF_REC = OFF_RES + (size_t)Mn * 384;
    const size_t OFF_EMB = OFF_REC + (size_t)Mn * Dn;
    float* emb = out + OFF_EMB;

    const int SM128 = 3 * (128 + 128) * 40 * 2;   // 61440 B (3 stages)
    cudaFuncSetAttribute((const void*)gemm_mma<128>, cudaFuncAttributeMaxDynamicSharedMemorySize, SM128);
    cudaFuncSetAttribute((const void*)flash_attn, cudaFuncAttributeMaxDynamicSharedMemorySize, FL_SMEM);

    // ---- preprocessing: ONE batched transpose + small packs ----
    transpose_all<<<9536, dim3(32, 8)>>>(Wq, Wk, Wv, Wo, W1, W2, Wproj, Wfea, wt);
    pack_ktf<<<512, 128>>>(embk, wt + KTF);
    pack_xcat<<<Mn, 128>>>(x, xcat);
    pack_bqkv<<<NLn, 512>>>(bq, bk, bv, bqkv);

    gemm_mma<128><<<dim3(4, 64), 256, SM128>>>(xcat, 128, wt + KTF, 128, nullptr,
                                               emb, h16, Dn, 128, 0);

    for (int l = 0; l < NLn; l++) {
        const float* hin = (l == 0) ? emb : h;
        size_t o512 = (size_t)l * Dn * Dn, o1 = (size_t)l * Dn * DFFn;
        gemm_mma<128><<<dim3(12, 64), 256, SM128>>>(h16, Dn, wt + WQKV(l), Dn,
                                                    bqkv + l * 1536, nullptr, qkv, 1536, Dn, 0);
        transpose_v<<<dim3(8, BHn), 256>>>(qkv, vt);
        flash_attn<<<dim3(BHn, 16), 256, FL_SMEM>>>(qkv, vt, attnv);
        gemm_mma<128><<<dim3(4, 64), 256, SM128>>>(attnv, Dn, wt + WTO + o512, Dn,
                                                   bo + l * Dn, tmp, nullptr, Dn, Dn, 0);
        add_ln512<<<Mn, 128>>>(hin, tmp, n1g + l * Dn, n1b + l * Dn, x1, x1h, nullptr);
        gemm_mma<128><<<dim3(16, 64), 256, SM128>>>(x1h, Dn, wt + WT1 + o1, Dn,
                                                    b1 + l * DFFn, nullptr, ff1, DFFn, Dn, 1);
        gemm_mma<128><<<dim3(4, 64), 256, SM128>>>(ff1, DFFn, wt + WT2 + o1, DFFn,
                                                   b2 + l * Dn, tmp, nullptr, Dn, DFFn, 0);
        add_ln512<<<Mn, 128>>>(x1, tmp, n2g + l * Dn, n2b + l * Dn, h, h16, nullptr);
    }

    add_ln512<<<Mn, 128>>>(h, nullptr, nfg, nfb, nullptr, enc16, out + OFF_RES);

    gemm_mma<128><<<dim3(4, 64), 256, SM128>>>(enc16 + (Dn - DRESn), Dn, wt + WTF, DRESn,
                                               bfea, out + OFF_FEA, nullptr, Dn, DRESn, 0);
    gemm_mma<128><<<dim3(4, 64), 256, SM128>>>(enc16, Dn, wt + WTP, Dn,
                                               bproj, out + OFF_REC, nullptr, Dn, Dn, 0);
}

// round 10
// speedup vs baseline: 1.9331x; 1.0378x over previous
#include <cuda_runtime.h>
#include <cuda.h>
#include <cuda_fp16.h>
#include <math.h>

#define Bn   16
#define Ln   512
#define Cn   38
#define Dn   512
#define Hn   8
#define En   64
#define DFFn 2048
#define NLn  3
#define DRESn 128
#define Mn   (Bn*Ln)     /* 8192 */
#define BHn  (Bn*Hn)     /* 128  */

// ---------------- scratch (static device memory) ----------------
__device__ float  g_h   [Mn*Dn];
__device__ float  g_x1  [Mn*Dn];
__device__ float  g_tmp [Mn*Dn];
__device__ __align__(16) __half g_h16  [Mn*Dn];
__device__ __align__(16) __half g_x1h  [Mn*Dn];
__device__ __align__(16) __half g_enc16[Mn*Dn];
__device__ __align__(16) __half g_qkv  [Mn*1536];
__device__ __align__(16) __half g_attnv[Mn*Dn];
__device__ __align__(16) __half g_ff1  [Mn*DFFn];
__device__ __align__(16) __half g_xcat [Mn*128];
__device__ __align__(16) __half g_wt   [9830400];     // transposed weights (half)
__device__ float  g_bqkv[NLn*1536];

#define WQKV(l) ((size_t)(l) * 786432)                 /* fused [1536][512] per layer */
#define WTO 2359296
#define WT1 3145728
#define WT2 6291456
#define WTP 9437184
#define WTF 9699328
#define KTF 9764864

// ================= helpers =================
__device__ __forceinline__ unsigned smem_u32(const void* p) {
    unsigned a;
    asm("{ .reg .u64 t; cvta.to.shared.u64 t, %1; cvt.u32.u64 %0, t; }"
        : "=r"(a) : "l"(p));
    return a;
}
__device__ __forceinline__ void mma16(float* c, const unsigned* a, const unsigned* b) {
    asm volatile("mma.sync.aligned.m16n8k16.row.col.f32.f16.f16.f32 "
        "{%0,%1,%2,%3}, {%4,%5,%6,%7}, {%8,%9}, {%0,%1,%2,%3};"
        : "+f"(c[0]), "+f"(c[1]), "+f"(c[2]), "+f"(c[3])
        : "r"(a[0]), "r"(a[1]), "r"(a[2]), "r"(a[3]), "r"(b[0]), "r"(b[1]));
}
__device__ __forceinline__ void ldsm4(unsigned* r, unsigned addr) {
    asm volatile("ldmatrix.sync.aligned.m8n8.x4.shared.b16 {%0,%1,%2,%3}, [%4];"
        : "=r"(r[0]), "=r"(r[1]), "=r"(r[2]), "=r"(r[3]) : "r"(addr));
}
__device__ __forceinline__ void ldsm4t(unsigned* r, unsigned addr) {
    asm volatile("ldmatrix.sync.aligned.m8n8.x4.trans.shared.b16 {%0,%1,%2,%3}, [%4];"
        : "=r"(r[0]), "=r"(r[1]), "=r"(r[2]), "=r"(r[3]) : "r"(addr));
}
__device__ __forceinline__ unsigned h2u(__half2 v) { return *(unsigned*)&v; }
#define CP16(sa, gp) \
    asm volatile("cp.async.cg.shared.global [%0], [%1], 16;" :: "r"(sa), "l"(gp))
#define CPCOMMIT() asm volatile("cp.async.commit_group;" ::: "memory")
#define CPWAIT(n)  asm volatile("cp.async.wait_group %0;" :: "n"(n) : "memory")

// ================= fp16 tensor-core GEMM (3-stage pipeline) =================
template<int NT>
__global__ __launch_bounds__(256, 2)
void gemm_mma(const __half* __restrict__ A, int lda,
              const __half* __restrict__ BT, int ldb,
              const float* __restrict__ bias,
              float* __restrict__ C, __half* __restrict__ C16, int ldc,
              int K, int do_gelu)
{
    constexpr int WC  = 4;
    constexpr int WM  = 64;
    constexpr int MT  = WM / 16;
    constexpr int RS  = 40;
    constexpr int STG = (128 + NT) * RS;

    extern __shared__ __align__(16) char dsm[];
    __half* sm = (__half*)dsm;
    const int tid = threadIdx.x, w = tid >> 5, lane = tid & 31;
    const int m0 = blockIdx.y * 128, n0 = blockIdx.x * NT;
    const int g = lane >> 3, lr = lane & 7;

    auto load_stage = [&](int kc, int st) {
        __half* As = sm + st * STG;
        __half* Bs = As + 128 * RS;
        const __half* Ap = A + (size_t)m0 * lda + kc * 32;
#pragma unroll
        for (int i = 0; i < 2; i++) {
            int fi = tid + i * 256, row = fi >> 2, seg = fi & 3;
            CP16(smem_u32(As + row * RS + seg * 8), Ap + (size_t)row * lda + seg * 8);
        }
        const __half* Bp = BT + (size_t)n0 * ldb + kc * 32;
#pragma unroll
        for (int i = 0; i < NT / 64; i++) {
            int fi = tid + i * 256, row = fi >> 2, seg = fi & 3;
            CP16(smem_u32(Bs + row * RS + seg * 8), Bp + (size_t)row * ldb + seg * 8);
        }
    };

    float acc[MT][4][4];
#pragma unroll
    for (int mt = 0; mt < MT; mt++)
#pragma unroll
        for (int nt = 0; nt < 4; nt++)
#pragma unroll
            for (int j = 0; j < 4; j++) acc[mt][nt][j] = 0.f;

    const int wm0 = (w / WC) * WM, wn0 = (w % WC) * 32;
    const int r = lane >> 2, cl = lane & 3;
    const unsigned aLane = ((g & 1) * 8 + lr) * RS + (g >> 1) * 8;
    const unsigned bLane = ((g >> 1) * 8 + lr) * RS + (g & 1) * 8;

    auto compute = [&](int st) {
        __half* As = sm + st * STG;
        __half* Bs = As + 128 * RS;
        unsigned aBase = smem_u32(As) + 2u * (wm0 * RS + aLane);
        unsigned bBase = smem_u32(Bs) + 2u * (wn0 * RS + bLane);
#pragma unroll
        for (int ks = 0; ks < 2; ks++) {
            const unsigned koff = ks * 32;
            unsigned a[MT][4], b[4][2];
#pragma unroll
            for (int mt = 0; mt < MT; mt++)
                ldsm4(a[mt], aBase + mt * (16 * RS * 2) + koff);
#pragma unroll
            for (int p = 0; p < 2; p++) {
                unsigned t[4];
                ldsm4(t, bBase + p * (16 * RS * 2) + koff);
                b[2 * p][0] = t[0]; b[2 * p][1] = t[1];
                b[2 * p + 1][0] = t[2]; b[2 * p + 1][1] = t[3];
            }
#pragma unroll
            for (int mt = 0; mt < MT; mt++)
#pragma unroll
                for (int nt = 0; nt < 4; nt++)
                    mma16(acc[mt][nt], a[mt], b[nt]);
        }
    };

    const int NC = K >> 5;
    load_stage(0, 0); CPCOMMIT();
    load_stage(1, 1); CPCOMMIT();
    int st = 0;
    for (int c = 0; c < NC; c++) {
        if (c + 1 < NC) { CPWAIT(1); }
        else            { CPWAIT(0); }
        __syncthreads();
        compute(st);
        if (c + 2 < NC) {
            int ls = st + 2; if (ls >= 3) ls -= 3;
            load_stage(c + 2, ls);
            CPCOMMIT();
        }
        if (++st == 3) st = 0;
    }

#pragma unroll
    for (int mt = 0; mt < MT; mt++) {
#pragma unroll
        for (int nt = 0; nt < 4; nt++) {
            int row = m0 + wm0 + mt * 16 + r;
            int col = n0 + wn0 + nt * 8 + cl * 2;
            float bs0 = bias ? bias[col] : 0.f;
            float bs1 = bias ? bias[col + 1] : 0.f;
            float v0 = acc[mt][nt][0] + bs0;
            float v1 = acc[mt][nt][1] + bs1;
            float v2 = acc[mt][nt][2] + bs0;
            float v3 = acc[mt][nt][3] + bs1;
            if (do_gelu) {
                v0 = 0.5f * v0 * (1.0f + erff(v0 * 0.70710678118654752f));
                v1 = 0.5f * v1 * (1.0f + erff(v1 * 0.70710678118654752f));
                v2 = 0.5f * v2 * (1.0f + erff(v2 * 0.70710678118654752f));
                v3 = 0.5f * v3 * (1.0f + erff(v3 * 0.70710678118654752f));
            }
            if (C) {
                float* p0 = C + (size_t)row * ldc + col;
                float* p1 = p0 + (size_t)8 * ldc;
                p0[0] = v0; p0[1] = v1;
                p1[0] = v2; p1[1] = v3;
            }
            if (C16) {
                *(__half2*)(C16 + (size_t)row * ldc + col) = __floats2half2_rn(v0, v1);
                *(__half2*)(C16 + (size_t)(row + 8) * ldc + col) = __floats2half2_rn(v2, v3);
            }
        }
    }
}

// ================= flash attention: scores + softmax + P.V ==================
// V stored [s][e] directly from qkv; PV B-fragments via ldmatrix.trans.
#define FL_RSQ 72
#define FL_RSK 72
#define FL_RSV 72
#define FL_KOFF (32*FL_RSQ)                    /* halves */
#define FL_VOFF (FL_KOFF + 512*FL_RSK)
#define FL_REDB ((FL_VOFF + 512*FL_RSV)*2)     /* bytes  */
#define FL_SMEM (FL_REDB + 2048 + 16)

__global__ __launch_bounds__(256, 1)
void flash_attn(const __half* __restrict__ qkv,
                __half* __restrict__ attnv)
{
    extern __shared__ __align__(16) char dsm[];
    __half* Qs = (__half*)dsm;
    __half* Ks = Qs + FL_KOFF;
    __half* Vs = Qs + FL_VOFF;
    float* red  = (float*)(dsm + FL_REDB);
    float* red2 = red + 256;

    const int tid = threadIdx.x, w = tid >> 5, lane = tid & 31;
    const int r = lane >> 2, cl = lane & 3;
    const int g = lane >> 3, lr = lane & 7;
    const int z = blockIdx.x;
    const int m0 = blockIdx.y * 32;
    const int b = z >> 3, hh = z & 7;
    const size_t qbase = ((size_t)b * Ln) * 1536 + (size_t)hh * 64;

    {
        int row = tid >> 3, seg = tid & 7;
        *(uint4*)(Qs + row * FL_RSQ + seg * 8) =
            *(const uint4*)(qkv + qbase + (size_t)(m0 + row) * 1536 + seg * 8);
    }
#pragma unroll 4
    for (int i = 0; i < 16; i++) {
        int idx = tid + i * 256, row = idx >> 3, seg = idx & 7;
        const __half* src = qkv + qbase + 512 + (size_t)row * 1536 + seg * 8;
        *(uint4*)(Ks + row * FL_RSK + seg * 8) = *(const uint4*)src;
        *(uint4*)(Vs + row * FL_RSV + seg * 8) = *(const uint4*)(src + 512);
    }
    __syncthreads();

    const int wn0 = w * 64;
    float acc[2][8][4];
#pragma unroll
    for (int mt = 0; mt < 2; mt++)
#pragma unroll
        for (int nt = 0; nt < 8; nt++)
#pragma unroll
            for (int j = 0; j < 4; j++) acc[mt][nt][j] = 0.f;

    const unsigned aBase = smem_u32(Qs) + 2u * (((g & 1) * 8 + lr) * FL_RSQ + (g >> 1) * 8);
    const unsigned bBase = smem_u32(Ks) + 2u * ((wn0 + (g >> 1) * 8 + lr) * FL_RSK + (g & 1) * 8);
#pragma unroll
    for (int ks = 0; ks < 4; ks++) {
        const unsigned koff = ks * 32;
        unsigned a[2][4], b[8][2];
#pragma unroll
        for (int mt = 0; mt < 2; mt++)
            ldsm4(a[mt], aBase + mt * (16 * FL_RSQ * 2) + koff);
#pragma unroll
        for (int p = 0; p < 4; p++) {
            unsigned t[4];
            ldsm4(t, bBase + p * (16 * FL_RSK * 2) + koff);
            b[2 * p][0] = t[0]; b[2 * p][1] = t[1];
            b[2 * p + 1][0] = t[2]; b[2 * p + 1][1] = t[3];
        }
#pragma unroll
        for (int mt = 0; mt < 2; mt++)
#pragma unroll
            for (int nt = 0; nt < 8; nt++)
                mma16(acc[mt][nt], a[mt], b[nt]);
    }

    float M[4], inv[4];
#pragma unroll
    for (int rs = 0; rs < 4; rs++) {
        int mt = rs >> 1, jb = (rs & 1) * 2;
        float mx = -1e30f;
#pragma unroll
        for (int nt = 0; nt < 8; nt++)
            mx = fmaxf(mx, fmaxf(acc[mt][nt][jb], acc[mt][nt][jb + 1]));
        mx = fmaxf(mx, __shfl_xor_sync(0xFFFFFFFFu, mx, 1));
        mx = fmaxf(mx, __shfl_xor_sync(0xFFFFFFFFu, mx, 2));
        if (cl == 0) red[w * 32 + mt * 16 + r + (rs & 1) * 8] = mx;
    }
    __syncthreads();
#pragma unroll
    for (int rs = 0; rs < 4; rs++) {
        int row = (rs >> 1) * 16 + r + (rs & 1) * 8;
        float mx = -1e30f;
#pragma unroll
        for (int w2 = 0; w2 < 8; w2++) mx = fmaxf(mx, red[w2 * 32 + row]);
        M[rs] = mx;
    }
#pragma unroll
    for (int rs = 0; rs < 4; rs++) {
        int mt = rs >> 1, jb = (rs & 1) * 2;
        float s = 0.f;
#pragma unroll
        for (int nt = 0; nt < 8; nt++) {
            float e0 = __expf((acc[mt][nt][jb]     - M[rs]) * 0.125f);
            float e1 = __expf((acc[mt][nt][jb + 1] - M[rs]) * 0.125f);
            acc[mt][nt][jb] = e0; acc[mt][nt][jb + 1] = e1;
            s += e0 + e1;
        }
        s += __shfl_xor_sync(0xFFFFFFFFu, s, 1);
        s += __shfl_xor_sync(0xFFFFFFFFu, s, 2);
        if (cl == 0) red2[w * 32 + mt * 16 + r + (rs & 1) * 8] = s;
    }
    __syncthreads();
#pragma unroll
    for (int rs = 0; rs < 4; rs++) {
        int row = (rs >> 1) * 16 + r + (rs & 1) * 8;
        float s = 0.f;
#pragma unroll
        for (int w2 = 0; w2 < 8; w2++) s += red2[w2 * 32 + row];
        inv[rs] = 1.0f / s;
    }

    // ---- P.V: warp contracts its 64 s-values (k), V[s][e] via ldsm.trans ----
    float o[2][8][4];
#pragma unroll
    for (int mt = 0; mt < 2; mt++)
#pragma unroll
        for (int nt = 0; nt < 8; nt++)
#pragma unroll
            for (int j = 0; j < 4; j++) o[mt][nt][j] = 0.f;

    // trans tile mapping: tile g addresses stored row s = wn0 + (g&1)*8 + lr,
    // col e = (g>>1)*8; per-t step = 16 s rows; per-p step = 16 e cols.
    const unsigned vBase = smem_u32(Vs) + 2u * ((wn0 + (g & 1) * 8 + lr) * FL_RSV + (g >> 1) * 8);
#pragma unroll
    for (int t = 0; t < 4; t++) {
        unsigned a[2][4], b[8][2];
#pragma unroll
        for (int mt = 0; mt < 2; mt++) {
            a[mt][0] = h2u(__floats2half2_rn(acc[mt][2*t][0]   * inv[2*mt],     acc[mt][2*t][1]   * inv[2*mt]));
            a[mt][1] = h2u(__floats2half2_rn(acc[mt][2*t][2]   * inv[2*mt + 1], acc[mt][2*t][3]   * inv[2*mt + 1]));
            a[mt][2] = h2u(__floats2half2_rn(acc[mt][2*t+1][0] * inv[2*mt],     acc[mt][2*t+1][1] * inv[2*mt]));
            a[mt][3] = h2u(__floats2half2_rn(acc[mt][2*t+1][2] * inv[2*mt + 1], acc[mt][2*t+1][3] * inv[2*mt + 1]));
        }
#pragma unroll
        for (int p = 0; p < 4; p++) {
            unsigned tb[4];
            ldsm4t(tb, vBase + t * (16 * FL_RSV * 2) + p * 32);
            b[2 * p][0] = tb[0]; b[2 * p][1] = tb[1];
            b[2 * p + 1][0] = tb[2]; b[2 * p + 1][1] = tb[3];
        }
#pragma unroll
        for (int mt = 0; mt < 2; mt++)
#pragma unroll
            for (int nt = 0; nt < 8; nt++)
                mma16(o[mt][nt], a[mt], b[nt]);
    }

    // ---- cross-warp reduce (partials overlay dead K region) ----
    float* part = (float*)(dsm + FL_KOFF * 2);
#pragma unroll
    for (int mt = 0; mt < 2; mt++)
#pragma unroll
        for (int nt = 0; nt < 8; nt++) {
            int row = mt * 16 + r, col = nt * 8 + cl * 2;
            float* p = part + w * 2112 + row * 66 + col;
            p[0] = o[mt][nt][0]; p[1] = o[mt][nt][1];
            p[8 * 66] = o[mt][nt][2]; p[8 * 66 + 1] = o[mt][nt][3];
        }
    __syncthreads();

    {
        int orow = tid >> 3, c0 = (tid & 7) * 8;
        float s[8];
#pragma unroll
        for (int c = 0; c < 8; c++) s[c] = 0.f;
#pragma unroll
        for (int w2 = 0; w2 < 8; w2++) {
            const float* p = part + w2 * 2112 + orow * 66 + c0;
#pragma unroll
            for (int c = 0; c < 8; c++) s[c] += p[c];
        }
        __align__(16) __half2 hb[4];
#pragma unroll
        for (int c = 0; c < 4; c++) hb[c] = __floats2half2_rn(s[2 * c], s[2 * c + 1]);
        *(uint4*)(attnv + ((size_t)b * Ln + m0 + orow) * Dn + hh * 64 + c0) = *(uint4*)hb;
    }
}

// ================= batched weight transpose (ALL weights, one launch) =======
__global__ void transpose_all(const float* __restrict__ Wq, const float* __restrict__ Wk,
                              const float* __restrict__ Wv, const float* __restrict__ Wo,
                              const float* __restrict__ W1, const float* __restrict__ W2,
                              const float* __restrict__ Wproj, const float* __restrict__ Wfea,
                              __half* __restrict__ wt)
{
    int bid = blockIdx.x;
    const float* in; __half* out; int K, N, bx, by;
    if (bid < 9216) {
        int l = bid / 3072, rr = bid - l * 3072;
        size_t o512 = (size_t)l * 262144, o1 = (size_t)l * 1048576;
        if (rr < 1024) {
            int m = rr >> 8, idx = rr & 255;
            K = 512; N = 512; bx = idx & 15; by = idx >> 4;
            if (m == 0)      { in = Wq + o512; out = wt + WQKV(l); }
            else if (m == 1) { in = Wk + o512; out = wt + WQKV(l) + 262144; }
            else if (m == 2) { in = Wv + o512; out = wt + WQKV(l) + 524288; }
            else             { in = Wo + o512; out = wt + WTO + o512; }
        } else if (rr < 2048) {
            int idx = rr - 1024;
            K = 512; N = 2048; bx = idx & 63; by = idx >> 6;
            in = W1 + o1; out = wt + WT1 + o1;
        } else {
            int idx = rr - 2048;
            K = 2048; N = 512; bx = idx & 15; by = idx >> 4;
            in = W2 + o1; out = wt + WT2 + o1;
        }
    } else if (bid < 9472) {
        int idx = bid - 9216;
        K = 512; N = 512; bx = idx & 15; by = idx >> 4;
        in = Wproj; out = wt + WTP;
    } else {
        int idx = bid - 9472;
        K = 128; N = 512; bx = idx & 15; by = idx >> 4;
        in = Wfea; out = wt + WTF;
    }
    __shared__ float t[32][33];
    int k0 = by * 32, n0 = bx * 32;
    int tx = threadIdx.x, ty = threadIdx.y;
#pragma unroll
    for (int rr2 = 0; rr2 < 4; rr2++)
        t[ty + rr2 * 8][tx] = in[(size_t)(k0 + ty + rr2 * 8) * N + n0 + tx];
    __syncthreads();
#pragma unroll
    for (int rr2 = 0; rr2 < 4; rr2++)
        out[(size_t)(n0 + ty + rr2 * 8) * K + k0 + tx] = __float2half(t[tx][ty + rr2 * 8]);
}

// ================= combined small packs: ktf | bqkv | xcat ==================
// grid: [0,512) ktf | [512,524) bqkv | [524, 524+8192) xcat ; 128 threads
__global__ void pack_misc(const float* __restrict__ kern,
                          const float* __restrict__ bq, const float* __restrict__ bk,
                          const float* __restrict__ bv,
                          const float* __restrict__ x,
                          __half* __restrict__ kt, float* __restrict__ bdst,
                          __half* __restrict__ xc)
{
    int bid = blockIdx.x, tidx = threadIdx.x;
    if (bid < 512) {
        int d = bid;
        kt[(size_t)d * 128 + tidx] =
            __float2half((tidx < Cn * 3) ? kern[(size_t)d * (Cn * 3) + tidx] : 0.f);
    } else if (bid < 524) {
        int j = bid - 512;
        int l = j >> 2, i = (j & 3) * 128 + tidx;
        bdst[l * 1536 + i]        = bq[l * 512 + i];
        bdst[l * 1536 + 512 + i]  = bk[l * 512 + i];
        bdst[l * 1536 + 1024 + i] = bv[l * 512 + i];
    } else {
        int bl = bid - 524;
        int b = bl >> 9, l = bl & 511;
        float val = 0.f;
        if (tidx < Cn * 3) {
            int c = tidx / 3, t = tidx - c * 3;
            int ls = (l - 1 + t + Ln) & (Ln - 1);
            val = x[((size_t)b * Ln + ls) * Cn + c];
        }
        xc[(size_t)bl * 128 + tidx] = __float2half(val);
    }
}

// ===== layernorm (vectorized: 128 thr x float4) =====
__global__ void add_ln512(const float* __restrict__ a, const float* __restrict__ b,
                          const float* __restrict__ g, const float* __restrict__ be,
                          float* __restrict__ o, __half* __restrict__ o16,
                          float* __restrict__ res) {
    int row = blockIdx.x, t = threadIdx.x;        // 128 threads
    size_t base = (size_t)row * Dn;
    float4 v = *(const float4*)(a + base + t * 4);
    if (b) {
        float4 vb = *(const float4*)(b + base + t * 4);
        v.x += vb.x; v.y += vb.y; v.z += vb.z; v.w += vb.w;
    }
    float s = v.x + v.y + v.z + v.w;
#pragma unroll
    for (int oo = 16; oo > 0; oo >>= 1) s += __shfl_xor_sync(0xFFFFFFFFu, s, oo);
    __shared__ float s1[4], s2[4];
    if ((t & 31) == 0) s1[t >> 5] = s;
    __syncthreads();
    float mean = (s1[0] + s1[1] + s1[2] + s1[3]) * (1.0f / Dn);
    float d0 = v.x - mean, d1 = v.y - mean, d2 = v.z - mean, d3 = v.w - mean;
    float q2 = d0 * d0 + d1 * d1 + d2 * d2 + d3 * d3;
#pragma unroll
    for (int oo = 16; oo > 0; oo >>= 1) q2 += __shfl_xor_sync(0xFFFFFFFFu, q2, oo);
    if ((t & 31) == 0) s2[t >> 5] = q2;
    __syncthreads();
    float var = (s2[0] + s2[1] + s2[2] + s2[3]) * (1.0f / Dn);
    float rr = rsqrtf(var + 1e-5f);
    float4 gg = *(const float4*)(g + t * 4);
    float4 bb = *(const float4*)(be + t * 4);
    float o0 = d0 * rr * gg.x + bb.x;
    float o1 = d1 * rr * gg.y + bb.y;
    float o2 = d2 * rr * gg.z + bb.z;
    float o3 = d3 * rr * gg.w + bb.w;
    if (o) {
        float4 ov = {o0, o1, o2, o3};
        *(float4*)(o + base + t * 4) = ov;
    }
    if (o16) {
        *(__half2*)(o16 + base + t * 4)     = __floats2half2_rn(o0, o1);
        *(__half2*)(o16 + base + t * 4 + 2) = __floats2half2_rn(o2, o3);
    }
    if (res && t < 96) {
        float4 rv = {o0, o1, o2, o3};
        *(float4*)(res + (size_t)row * 384 + t * 4) = rv;
    }
}

// ================= launcher =================
extern "C" void kernel_launch(void* const* d_in, const int* in_sizes, int n_in,
                              void* d_out, int out_size)
{
    const float* x     = (const float*)d_in[0];
    const float* embk  = (const float*)d_in[1];
    const float* Wq    = (const float*)d_in[2];
    const float* bq    = (const float*)d_in[3];
    const float* Wk    = (const float*)d_in[4];
    const float* bk    = (const float*)d_in[5];
    const float* Wv    = (const float*)d_in[6];
    const float* bv    = (const float*)d_in[7];
    // d_in[8], d_in[9]: Wsig/bsig are dead code in the reference
    const float* Wo    = (const float*)d_in[10];
    const float* bo    = (const float*)d_in[11];
    const float* W1    = (const float*)d_in[12];
    const float* b1    = (const float*)d_in[13];
    const float* W2    = (const float*)d_in[14];
    const float* b2    = (const float*)d_in[15];
    const float* n1g   = (const float*)d_in[16];
    const float* n1b   = (const float*)d_in[17];
    const float* n2g   = (const float*)d_in[18];
    const float* n2b   = (const float*)d_in[19];
    const float* nfg   = (const float*)d_in[20];
    const float* nfb   = (const float*)d_in[21];
    const float* Wproj = (const float*)d_in[22];
    const float* bproj = (const float*)d_in[23];
    const float* Wfea  = (const float*)d_in[24];
    const float* bfea  = (const float*)d_in[25];
    float* out = (float*)d_out;

    float *h, *x1, *tmp, *bqkv;
    __half *h16,*x1h,*enc16,*qkv,*attnv,*ff1,*xcat,*wt;
    cudaGetSymbolAddress((void**)&h,     g_h);
    cudaGetSymbolAddress((void**)&x1,    g_x1);
    cudaGetSymbolAddress((void**)&tmp,   g_tmp);
    cudaGetSymbolAddress((void**)&bqkv,  g_bqkv);
    cudaGetSymbolAddress((void**)&h16,   g_h16);
    cudaGetSymbolAddress((void**)&x1h,   g_x1h);
    cudaGetSymbolAddress((void**)&enc16, g_enc16);
    cudaGetSymbolAddress((void**)&qkv,   g_qkv);
    cudaGetSymbolAddress((void**)&attnv, g_attnv);
    cudaGetSymbolAddress((void**)&ff1,   g_ff1);
    cudaGetSymbolAddress((void**)&xcat,  g_xcat);
    cudaGetSymbolAddress((void**)&wt,    g_wt);

    // outputs: fea_t | enc_res(384) | rec_temp(512) | emb(512)
    const size_t OFF_FEA = 0;
    const size_t OFF_RES = (size_t)Mn * Dn;
    const size_t OFF_REC = OFF_RES + (size_t)Mn * 384;
    const size_t OFF_EMB = OFF_REC + (size_t)Mn * Dn;
    float* emb = out + OFF_EMB;

    const int SM128 = 3 * (128 + 128) * 40 * 2;   // 61440 B (3 stages)
    cudaFuncSetAttribute((const void*)gemm_mma<128>, cudaFuncAttributeMaxDynamicSharedMemorySize, SM128);
    cudaFuncSetAttribute((const void*)flash_attn, cudaFuncAttributeMaxDynamicSharedMemorySize, FL_SMEM);

    // ---- preprocessing ----
    transpose_all<<<9536, dim3(32, 8)>>>(Wq, Wk, Wv, Wo, W1, W2, Wproj, Wfea, wt);
    pack_misc<<<524 + Mn, 128>>>(embk, bq, bk, bv, x, wt + KTF, bqkv, xcat);

    gemm_mma<128><<<dim3(4, 64), 256, SM128>>>(xcat, 128, wt + KTF, 128, nullptr,
                                               emb, h16, Dn, 128, 0);

    for (int l = 0; l < NLn; l++) {
        const float* hin = (l == 0) ? emb : h;
        size_t o512 = (size_t)l * Dn * Dn, o1 = (size_t)l * Dn * DFFn;
        gemm_mma<128><<<dim3(12, 64), 256, SM128>>>(h16, Dn, wt + WQKV(l), Dn,
                                                    bqkv + l * 1536, nullptr, qkv, 1536, Dn, 0);
        flash_attn<<<dim3(BHn, 16), 256, FL_SMEM>>>(qkv, attnv);
        gemm_mma<128><<<dim3(4, 64), 256, SM128>>>(attnv, Dn, wt + WTO + o512, Dn,
                                                   bo + l * Dn, tmp, nullptr, Dn, Dn, 0);
        add_ln512<<<Mn, 128>>>(hin, tmp, n1g + l * Dn, n1b + l * Dn, x1, x1h, nullptr);
        gemm_mma<128><<<dim3(16, 64), 256, SM128>>>(x1h, Dn, wt + WT1 + o1, Dn,
                                                    b1 + l * DFFn, nullptr, ff1, DFFn, Dn, 1);
        gemm_mma<128><<<dim3(4, 64), 256, SM128>>>(ff1, DFFn, wt + WT2 + o1, DFFn,
                                                   b2 + l * Dn, tmp, nullptr, Dn, DFFn, 0);
        add_ln512<<<Mn, 128>>>(x1, tmp, n2g + l * Dn, n2b + l * Dn, h, h16, nullptr);
    }

    add_ln512<<<Mn, 128>>>(h, nullptr, nfg, nfb, nullptr, enc16, out + OFF_RES);

    gemm_mma<128><<<dim3(4, 64), 256, SM128>>>(enc16 + (Dn - DRESn), Dn, wt + WTF, DRESn,
                                               bfea, out + OFF_FEA, nullptr, Dn, DRESn, 0);
    gemm_mma<128><<<dim3(4, 64), 256, SM128>>>(enc16, Dn, wt + WTP, Dn,
                                               bproj, out + OFF_REC, nullptr, Dn, Dn, 0);
}

// round 11
// speedup vs baseline: 2.0444x; 1.0575x over previous
#include <cuda_runtime.h>
#include <cuda.h>
#include <cuda_fp16.h>
#include <math.h>

#define Bn   16
#define Ln   512
#define Cn   38
#define Dn   512
#define Hn   8
#define En   64
#define DFFn 2048
#define NLn  3
#define DRESn 128
#define Mn   (Bn*Ln)     /* 8192 */
#define BHn  (Bn*Hn)     /* 128  */

// ---------------- scratch (static device memory) ----------------
__device__ float  g_h   [Mn*Dn];
__device__ float  g_x1  [Mn*Dn];
__device__ float  g_tmp [Mn*Dn];
__device__ __align__(16) __half g_h16  [Mn*Dn];
__device__ __align__(16) __half g_x1h  [Mn*Dn];
__device__ __align__(16) __half g_enc16[Mn*Dn];
__device__ __align__(16) __half g_qkv  [Mn*1536];
__device__ __align__(16) __half g_attnv[Mn*Dn];
__device__ __align__(16) __half g_ff1  [Mn*DFFn];
__device__ __align__(16) __half g_xcat [Mn*128];
__device__ __align__(16) __half g_wt   [9830400];     // transposed weights (half)
__device__ float  g_bqkv[NLn*1536];

#define WQKV(l) ((size_t)(l) * 786432)                 /* fused [1536][512] per layer */
#define WTO 2359296
#define WT1 3145728
#define WT2 6291456
#define WTP 9437184
#define WTF 9699328
#define KTF 9764864

// ================= helpers =================
__device__ __forceinline__ unsigned smem_u32(const void* p) {
    unsigned a;
    asm("{ .reg .u64 t; cvta.to.shared.u64 t, %1; cvt.u32.u64 %0, t; }"
        : "=r"(a) : "l"(p));
    return a;
}
__device__ __forceinline__ void mma16(float* c, const unsigned* a, const unsigned* b) {
    asm volatile("mma.sync.aligned.m16n8k16.row.col.f32.f16.f16.f32 "
        "{%0,%1,%2,%3}, {%4,%5,%6,%7}, {%8,%9}, {%0,%1,%2,%3};"
        : "+f"(c[0]), "+f"(c[1]), "+f"(c[2]), "+f"(c[3])
        : "r"(a[0]), "r"(a[1]), "r"(a[2]), "r"(a[3]), "r"(b[0]), "r"(b[1]));
}
__device__ __forceinline__ void ldsm4(unsigned* r, unsigned addr) {
    asm volatile("ldmatrix.sync.aligned.m8n8.x4.shared.b16 {%0,%1,%2,%3}, [%4];"
        : "=r"(r[0]), "=r"(r[1]), "=r"(r[2]), "=r"(r[3]) : "r"(addr));
}
__device__ __forceinline__ void ldsm4t(unsigned* r, unsigned addr) {
    asm volatile("ldmatrix.sync.aligned.m8n8.x4.trans.shared.b16 {%0,%1,%2,%3}, [%4];"
        : "=r"(r[0]), "=r"(r[1]), "=r"(r[2]), "=r"(r[3]) : "r"(addr));
}
__device__ __forceinline__ unsigned h2u(__half2 v) { return *(unsigned*)&v; }
#define CP16(sa, gp) \
    asm volatile("cp.async.cg.shared.global [%0], [%1], 16;" :: "r"(sa), "l"(gp))
#define CPCOMMIT() asm volatile("cp.async.commit_group;" ::: "memory")
#define CPWAIT(n)  asm volatile("cp.async.wait_group %0;" :: "n"(n) : "memory")

// ========== fp16 tensor-core GEMM (3-stage pipeline, K-chunk = 64) ==========
template<int NT>
__global__ __launch_bounds__(256, 2)
void gemm_mma(const __half* __restrict__ A, int lda,
              const __half* __restrict__ BT, int ldb,
              const float* __restrict__ bias,
              float* __restrict__ C, __half* __restrict__ C16, int ldc,
              int K, int do_gelu)
{
    constexpr int WC  = 4;
    constexpr int WM  = 64;
    constexpr int MT  = WM / 16;
    constexpr int RS  = 72;                   // 64 data halves + 8 pad
    constexpr int STG = (128 + NT) * RS;      // halves per stage

    extern __shared__ __align__(16) char dsm[];
    __half* sm = (__half*)dsm;
    const int tid = threadIdx.x, w = tid >> 5, lane = tid & 31;
    const int m0 = blockIdx.y * 128, n0 = blockIdx.x * NT;
    const int g = lane >> 3, lr = lane & 7;

    auto load_stage = [&](int kc, int st) {
        __half* As = sm + st * STG;
        __half* Bs = As + 128 * RS;
        const __half* Ap = A + (size_t)m0 * lda + kc * 64;
#pragma unroll
        for (int i = 0; i < 4; i++) {
            int fi = tid + i * 256, row = fi >> 3, seg = fi & 7;
            CP16(smem_u32(As + row * RS + seg * 8), Ap + (size_t)row * lda + seg * 8);
        }
        const __half* Bp = BT + (size_t)n0 * ldb + kc * 64;
#pragma unroll
        for (int i = 0; i < NT / 32; i++) {
            int fi = tid + i * 256, row = fi >> 3, seg = fi & 7;
            CP16(smem_u32(Bs + row * RS + seg * 8), Bp + (size_t)row * ldb + seg * 8);
        }
    };

    float acc[MT][4][4];
#pragma unroll
    for (int mt = 0; mt < MT; mt++)
#pragma unroll
        for (int nt = 0; nt < 4; nt++)
#pragma unroll
            for (int j = 0; j < 4; j++) acc[mt][nt][j] = 0.f;

    const int wm0 = (w / WC) * WM, wn0 = (w % WC) * 32;
    const int r = lane >> 2, cl = lane & 3;
    const unsigned aLane = ((g & 1) * 8 + lr) * RS + (g >> 1) * 8;
    const unsigned bLane = ((g >> 1) * 8 + lr) * RS + (g & 1) * 8;

    auto compute = [&](int st) {
        __half* As = sm + st * STG;
        __half* Bs = As + 128 * RS;
        unsigned aBase = smem_u32(As) + 2u * (wm0 * RS + aLane);
        unsigned bBase = smem_u32(Bs) + 2u * (wn0 * RS + bLane);
#pragma unroll
        for (int ks = 0; ks < 4; ks++) {          // four k16 steps per 64-chunk
            const unsigned koff = ks * 32;        // 16 halves * 2B
            unsigned a[MT][4], b[4][2];
#pragma unroll
            for (int mt = 0; mt < MT; mt++)
                ldsm4(a[mt], aBase + mt * (16 * RS * 2) + koff);
#pragma unroll
            for (int p = 0; p < 2; p++) {
                unsigned t[4];
                ldsm4(t, bBase + p * (16 * RS * 2) + koff);
                b[2 * p][0] = t[0]; b[2 * p][1] = t[1];
                b[2 * p + 1][0] = t[2]; b[2 * p + 1][1] = t[3];
            }
#pragma unroll
            for (int mt = 0; mt < MT; mt++)
#pragma unroll
                for (int nt = 0; nt < 4; nt++)
                    mma16(acc[mt][nt], a[mt], b[nt]);
        }
    };

    const int NC = K >> 6;                     // K/64 chunks (>=2 for all shapes)
    load_stage(0, 0); CPCOMMIT();
    load_stage(1, 1); CPCOMMIT();
    int st = 0;
    for (int c = 0; c < NC; c++) {
        if (c + 1 < NC) { CPWAIT(1); }         // chunk c landed; c+1 may fly
        else            { CPWAIT(0); }         // final chunk fully landed
        __syncthreads();
        compute(st);
        if (c + 2 < NC) {
            int ls = st + 2; if (ls >= 3) ls -= 3;
            load_stage(c + 2, ls);
            CPCOMMIT();
        }
        if (++st == 3) st = 0;
    }

#pragma unroll
    for (int mt = 0; mt < MT; mt++) {
#pragma unroll
        for (int nt = 0; nt < 4; nt++) {
            int row = m0 + wm0 + mt * 16 + r;
            int col = n0 + wn0 + nt * 8 + cl * 2;
            float bs0 = bias ? bias[col] : 0.f;
            float bs1 = bias ? bias[col + 1] : 0.f;
            float v0 = acc[mt][nt][0] + bs0;
            float v1 = acc[mt][nt][1] + bs1;
            float v2 = acc[mt][nt][2] + bs0;
            float v3 = acc[mt][nt][3] + bs1;
            if (do_gelu) {
                v0 = 0.5f * v0 * (1.0f + erff(v0 * 0.70710678118654752f));
                v1 = 0.5f * v1 * (1.0f + erff(v1 * 0.70710678118654752f));
                v2 = 0.5f * v2 * (1.0f + erff(v2 * 0.70710678118654752f));
                v3 = 0.5f * v3 * (1.0f + erff(v3 * 0.70710678118654752f));
            }
            if (C) {
                float* p0 = C + (size_t)row * ldc + col;
                float* p1 = p0 + (size_t)8 * ldc;
                p0[0] = v0; p0[1] = v1;
                p1[0] = v2; p1[1] = v3;
            }
            if (C16) {
                *(__half2*)(C16 + (size_t)row * ldc + col) = __floats2half2_rn(v0, v1);
                *(__half2*)(C16 + (size_t)(row + 8) * ldc + col) = __floats2half2_rn(v2, v3);
            }
        }
    }
}

// ================= flash attention: scores + softmax + P.V ==================
#define FL_RSQ 72
#define FL_RSK 72
#define FL_RSV 72
#define FL_KOFF (32*FL_RSQ)                    /* halves */
#define FL_VOFF (FL_KOFF + 512*FL_RSK)
#define FL_REDB ((FL_VOFF + 512*FL_RSV)*2)     /* bytes  */
#define FL_SMEM (FL_REDB + 2048 + 16)

__global__ __launch_bounds__(256, 1)
void flash_attn(const __half* __restrict__ qkv,
                __half* __restrict__ attnv)
{
    extern __shared__ __align__(16) char dsm[];
    __half* Qs = (__half*)dsm;
    __half* Ks = Qs + FL_KOFF;
    __half* Vs = Qs + FL_VOFF;
    float* red  = (float*)(dsm + FL_REDB);
    float* red2 = red + 256;

    const int tid = threadIdx.x, w = tid >> 5, lane = tid & 31;
    const int r = lane >> 2, cl = lane & 3;
    const int g = lane >> 3, lr = lane & 7;
    const int z = blockIdx.x;
    const int m0 = blockIdx.y * 32;
    const int b = z >> 3, hh = z & 7;
    const size_t qbase = ((size_t)b * Ln) * 1536 + (size_t)hh * 64;

    {
        int row = tid >> 3, seg = tid & 7;
        *(uint4*)(Qs + row * FL_RSQ + seg * 8) =
            *(const uint4*)(qkv + qbase + (size_t)(m0 + row) * 1536 + seg * 8);
    }
#pragma unroll 4
    for (int i = 0; i < 16; i++) {
        int idx = tid + i * 256, row = idx >> 3, seg = idx & 7;
        const __half* src = qkv + qbase + 512 + (size_t)row * 1536 + seg * 8;
        *(uint4*)(Ks + row * FL_RSK + seg * 8) = *(const uint4*)src;
        *(uint4*)(Vs + row * FL_RSV + seg * 8) = *(const uint4*)(src + 512);
    }
    __syncthreads();

    const int wn0 = w * 64;
    float acc[2][8][4];
#pragma unroll
    for (int mt = 0; mt < 2; mt++)
#pragma unroll
        for (int nt = 0; nt < 8; nt++)
#pragma unroll
            for (int j = 0; j < 4; j++) acc[mt][nt][j] = 0.f;

    const unsigned aBase = smem_u32(Qs) + 2u * (((g & 1) * 8 + lr) * FL_RSQ + (g >> 1) * 8);
    const unsigned bBase = smem_u32(Ks) + 2u * ((wn0 + (g >> 1) * 8 + lr) * FL_RSK + (g & 1) * 8);
#pragma unroll
    for (int ks = 0; ks < 4; ks++) {
        const unsigned koff = ks * 32;
        unsigned a[2][4], b[8][2];
#pragma unroll
        for (int mt = 0; mt < 2; mt++)
            ldsm4(a[mt], aBase + mt * (16 * FL_RSQ * 2) + koff);
#pragma unroll
        for (int p = 0; p < 4; p++) {
            unsigned t[4];
            ldsm4(t, bBase + p * (16 * FL_RSK * 2) + koff);
            b[2 * p][0] = t[0]; b[2 * p][1] = t[1];
            b[2 * p + 1][0] = t[2]; b[2 * p + 1][1] = t[3];
        }
#pragma unroll
        for (int mt = 0; mt < 2; mt++)
#pragma unroll
            for (int nt = 0; nt < 8; nt++)
                mma16(acc[mt][nt], a[mt], b[nt]);
    }

    float M[4], inv[4];
#pragma unroll
    for (int rs = 0; rs < 4; rs++) {
        int mt = rs >> 1, jb = (rs & 1) * 2;
        float mx = -1e30f;
#pragma unroll
        for (int nt = 0; nt < 8; nt++)
            mx = fmaxf(mx, fmaxf(acc[mt][nt][jb], acc[mt][nt][jb + 1]));
        mx = fmaxf(mx, __shfl_xor_sync(0xFFFFFFFFu, mx, 1));
        mx = fmaxf(mx, __shfl_xor_sync(0xFFFFFFFFu, mx, 2));
        if (cl == 0) red[w * 32 + mt * 16 + r + (rs & 1) * 8] = mx;
    }
    __syncthreads();
#pragma unroll
    for (int rs = 0; rs < 4; rs++) {
        int row = (rs >> 1) * 16 + r + (rs & 1) * 8;
        float mx = -1e30f;
#pragma unroll
        for (int w2 = 0; w2 < 8; w2++) mx = fmaxf(mx, red[w2 * 32 + row]);
        M[rs] = mx;
    }
#pragma unroll
    for (int rs = 0; rs < 4; rs++) {
        int mt = rs >> 1, jb = (rs & 1) * 2;
        float s = 0.f;
#pragma unroll
        for (int nt = 0; nt < 8; nt++) {
            float e0 = __expf((acc[mt][nt][jb]     - M[rs]) * 0.125f);
            float e1 = __expf((acc[mt][nt][jb + 1] - M[rs]) * 0.125f);
            acc[mt][nt][jb] = e0; acc[mt][nt][jb + 1] = e1;
            s += e0 + e1;
        }
        s += __shfl_xor_sync(0xFFFFFFFFu, s, 1);
        s += __shfl_xor_sync(0xFFFFFFFFu, s, 2);
        if (cl == 0) red2[w * 32 + mt * 16 + r + (rs & 1) * 8] = s;
    }
    __syncthreads();
#pragma unroll
    for (int rs = 0; rs < 4; rs++) {
        int row = (rs >> 1) * 16 + r + (rs & 1) * 8;
        float s = 0.f;
#pragma unroll
        for (int w2 = 0; w2 < 8; w2++) s += red2[w2 * 32 + row];
        inv[rs] = 1.0f / s;
    }

    float o[2][8][4];
#pragma unroll
    for (int mt = 0; mt < 2; mt++)
#pragma unroll
        for (int nt = 0; nt < 8; nt++)
#pragma unroll
            for (int j = 0; j < 4; j++) o[mt][nt][j] = 0.f;

    const unsigned vBase = smem_u32(Vs) + 2u * ((wn0 + (g & 1) * 8 + lr) * FL_RSV + (g >> 1) * 8);
#pragma unroll
    for (int t = 0; t < 4; t++) {
        unsigned a[2][4], b[8][2];
#pragma unroll
        for (int mt = 0; mt < 2; mt++) {
            a[mt][0] = h2u(__floats2half2_rn(acc[mt][2*t][0]   * inv[2*mt],     acc[mt][2*t][1]   * inv[2*mt]));
            a[mt][1] = h2u(__floats2half2_rn(acc[mt][2*t][2]   * inv[2*mt + 1], acc[mt][2*t][3]   * inv[2*mt + 1]));
            a[mt][2] = h2u(__floats2half2_rn(acc[mt][2*t+1][0] * inv[2*mt],     acc[mt][2*t+1][1] * inv[2*mt]));
            a[mt][3] = h2u(__floats2half2_rn(acc[mt][2*t+1][2] * inv[2*mt + 1], acc[mt][2*t+1][3] * inv[2*mt + 1]));
        }
#pragma unroll
        for (int p = 0; p < 4; p++) {
            unsigned tb[4];
            ldsm4t(tb, vBase + t * (16 * FL_RSV * 2) + p * 32);
            b[2 * p][0] = tb[0]; b[2 * p][1] = tb[1];
            b[2 * p + 1][0] = tb[2]; b[2 * p + 1][1] = tb[3];
        }
#pragma unroll
        for (int mt = 0; mt < 2; mt++)
#pragma unroll
            for (int nt = 0; nt < 8; nt++)
                mma16(o[mt][nt], a[mt], b[nt]);
    }

    float* part = (float*)(dsm + FL_KOFF * 2);
#pragma unroll
    for (int mt = 0; mt < 2; mt++)
#pragma unroll
        for (int nt = 0; nt < 8; nt++) {
            int row = mt * 16 + r, col = nt * 8 + cl * 2;
            float* p = part + w * 2112 + row * 66 + col;
            p[0] = o[mt][nt][0]; p[1] = o[mt][nt][1];
            p[8 * 66] = o[mt][nt][2]; p[8 * 66 + 1] = o[mt][nt][3];
        }
    __syncthreads();

    {
        int orow = tid >> 3, c0 = (tid & 7) * 8;
        float s[8];
#pragma unroll
        for (int c = 0; c < 8; c++) s[c] = 0.f;
#pragma unroll
        for (int w2 = 0; w2 < 8; w2++) {
            const float* p = part + w2 * 2112 + orow * 66 + c0;
#pragma unroll
            for (int c = 0; c < 8; c++) s[c] += p[c];
        }
        __align__(16) __half2 hb[4];
#pragma unroll
        for (int c = 0; c < 4; c++) hb[c] = __floats2half2_rn(s[2 * c], s[2 * c + 1]);
        *(uint4*)(attnv + ((size_t)b * Ln + m0 + orow) * Dn + hh * 64 + c0) = *(uint4*)hb;
    }
}

// ================= batched weight transpose (ALL weights, one launch) =======
__global__ void transpose_all(const float* __restrict__ Wq, const float* __restrict__ Wk,
                              const float* __restrict__ Wv, const float* __restrict__ Wo,
                              const float* __restrict__ W1, const float* __restrict__ W2,
                              const float* __restrict__ Wproj, const float* __restrict__ Wfea,
                              __half* __restrict__ wt)
{
    int bid = blockIdx.x;
    const float* in; __half* out; int K, N, bx, by;
    if (bid < 9216) {
        int l = bid / 3072, rr = bid - l * 3072;
        size_t o512 = (size_t)l * 262144, o1 = (size_t)l * 1048576;
        if (rr < 1024) {
            int m = rr >> 8, idx = rr & 255;
            K = 512; N = 512; bx = idx & 15; by = idx >> 4;
            if (m == 0)      { in = Wq + o512; out = wt + WQKV(l); }
            else if (m == 1) { in = Wk + o512; out = wt + WQKV(l) + 262144; }
            else if (m == 2) { in = Wv + o512; out = wt + WQKV(l) + 524288; }
            else             { in = Wo + o512; out = wt + WTO + o512; }
        } else if (rr < 2048) {
            int idx = rr - 1024;
            K = 512; N = 2048; bx = idx & 63; by = idx >> 6;
            in = W1 + o1; out = wt + WT1 + o1;
        } else {
            int idx = rr - 2048;
            K = 2048; N = 512; bx = idx & 15; by = idx >> 4;
            in = W2 + o1; out = wt + WT2 + o1;
        }
    } else if (bid < 9472) {
        int idx = bid - 9216;
        K = 512; N = 512; bx = idx & 15; by = idx >> 4;
        in = Wproj; out = wt + WTP;
    } else {
        int idx = bid - 9472;
        K = 128; N = 512; bx = idx & 15; by = idx >> 4;
        in = Wfea; out = wt + WTF;
    }
    __shared__ float t[32][33];
    int k0 = by * 32, n0 = bx * 32;
    int tx = threadIdx.x, ty = threadIdx.y;
#pragma unroll
    for (int rr2 = 0; rr2 < 4; rr2++)
        t[ty + rr2 * 8][tx] = in[(size_t)(k0 + ty + rr2 * 8) * N + n0 + tx];
    __syncthreads();
#pragma unroll
    for (int rr2 = 0; rr2 < 4; rr2++)
        out[(size_t)(n0 + ty + rr2 * 8) * K + k0 + tx] = __float2half(t[tx][ty + rr2 * 8]);
}

// ================= combined small packs: ktf | bqkv | xcat ==================
__global__ void pack_misc(const float* __restrict__ kern,
                          const float* __restrict__ bq, const float* __restrict__ bk,
                          const float* __restrict__ bv,
                          const float* __restrict__ x,
                          __half* __restrict__ kt, float* __restrict__ bdst,
                          __half* __restrict__ xc)
{
    int bid = blockIdx.x, tidx = threadIdx.x;
    if (bid < 512) {
        int d = bid;
        kt[(size_t)d * 128 + tidx] =
            __float2half((tidx < Cn * 3) ? kern[(size_t)d * (Cn * 3) + tidx] : 0.f);
    } else if (bid < 524) {
        int j = bid - 512;
        int l = j >> 2, i = (j & 3) * 128 + tidx;
        bdst[l * 1536 + i]        = bq[l * 512 + i];
        bdst[l * 1536 + 512 + i]  = bk[l * 512 + i];
        bdst[l * 1536 + 1024 + i] = bv[l * 512 + i];
    } else {
        int bl = bid - 524;
        int b = bl >> 9, l = bl & 511;
        float val = 0.f;
        if (tidx < Cn * 3) {
            int c = tidx / 3, t = tidx - c * 3;
            int ls = (l - 1 + t + Ln) & (Ln - 1);
            val = x[((size_t)b * Ln + ls) * Cn + c];
        }
        xc[(size_t)bl * 128 + tidx] = __float2half(val);
    }
}

// ===== layernorm (vectorized: 128 thr x float4) =====
__global__ void add_ln512(const float* __restrict__ a, const float* __restrict__ b,
                          const float* __restrict__ g, const float* __restrict__ be,
                          float* __restrict__ o, __half* __restrict__ o16,
                          float* __restrict__ res) {
    int row = blockIdx.x, t = threadIdx.x;        // 128 threads
    size_t base = (size_t)row * Dn;
    float4 v = *(const float4*)(a + base + t * 4);
    if (b) {
        float4 vb = *(const float4*)(b + base + t * 4);
        v.x += vb.x; v.y += vb.y; v.z += vb.z; v.w += vb.w;
    }
    float s = v.x + v.y + v.z + v.w;
#pragma unroll
    for (int oo = 16; oo > 0; oo >>= 1) s += __shfl_xor_sync(0xFFFFFFFFu, s, oo);
    __shared__ float s1[4], s2[4];
    if ((t & 31) == 0) s1[t >> 5] = s;
    __syncthreads();
    float mean = (s1[0] + s1[1] + s1[2] + s1[3]) * (1.0f / Dn);
    float d0 = v.x - mean, d1 = v.y - mean, d2 = v.z - mean, d3 = v.w - mean;
    float q2 = d0 * d0 + d1 * d1 + d2 * d2 + d3 * d3;
#pragma unroll
    for (int oo = 16; oo > 0; oo >>= 1) q2 += __shfl_xor_sync(0xFFFFFFFFu, q2, oo);
    if ((t & 31) == 0) s2[t >> 5] = q2;
    __syncthreads();
    float var = (s2[0] + s2[1] + s2[2] + s2[3]) * (1.0f / Dn);
    float rr = rsqrtf(var + 1e-5f);
    float4 gg = *(const float4*)(g + t * 4);
    float4 bb = *(const float4*)(be + t * 4);
    float o0 = d0 * rr * gg.x + bb.x;
    float o1 = d1 * rr * gg.y + bb.y;
    float o2 = d2 * rr * gg.z + bb.z;
    float o3 = d3 * rr * gg.w + bb.w;
    if (o) {
        float4 ov = {o0, o1, o2, o3};
        *(float4*)(o + base + t * 4) = ov;
    }
    if (o16) {
        *(__half2*)(o16 + base + t * 4)     = __floats2half2_rn(o0, o1);
        *(__half2*)(o16 + base + t * 4 + 2) = __floats2half2_rn(o2, o3);
    }
    if (res && t < 96) {
        float4 rv = {o0, o1, o2, o3};
        *(float4*)(res + (size_t)row * 384 + t * 4) = rv;
    }
}

// ================= launcher =================
extern "C" void kernel_launch(void* const* d_in, const int* in_sizes, int n_in,
                              void* d_out, int out_size)
{
    const float* x     = (const float*)d_in[0];
    const float* embk  = (const float*)d_in[1];
    const float* Wq    = (const float*)d_in[2];
    const float* bq    = (const float*)d_in[3];
    const float* Wk    = (const float*)d_in[4];
    const float* bk    = (const float*)d_in[5];
    const float* Wv    = (const float*)d_in[6];
    const float* bv    = (const float*)d_in[7];
    // d_in[8], d_in[9]: Wsig/bsig are dead code in the reference
    const float* Wo    = (const float*)d_in[10];
    const float* bo    = (const float*)d_in[11];
    const float* W1    = (const float*)d_in[12];
    const float* b1    = (const float*)d_in[13];
    const float* W2    = (const float*)d_in[14];
    const float* b2    = (const float*)d_in[15];
    const float* n1g   = (const float*)d_in[16];
    const float* n1b   = (const float*)d_in[17];
    const float* n2g   = (const float*)d_in[18];
    const float* n2b   = (const float*)d_in[19];
    const float* nfg   = (const float*)d_in[20];
    const float* nfb   = (const float*)d_in[21];
    const float* Wproj = (const float*)d_in[22];
    const float* bproj = (const float*)d_in[23];
    const float* Wfea  = (const float*)d_in[24];
    const float* bfea  = (const float*)d_in[25];
    float* out = (float*)d_out;

    float *h, *x1, *tmp, *bqkv;
    __half *h16,*x1h,*enc16,*qkv,*attnv,*ff1,*xcat,*wt;
    cudaGetSymbolAddress((void**)&h,     g_h);
    cudaGetSymbolAddress((void**)&x1,    g_x1);
    cudaGetSymbolAddress((void**)&tmp,   g_tmp);
    cudaGetSymbolAddress((void**)&bqkv,  g_bqkv);
    cudaGetSymbolAddress((void**)&h16,   g_h16);
    cudaGetSymbolAddress((void**)&x1h,   g_x1h);
    cudaGetSymbolAddress((void**)&enc16, g_enc16);
    cudaGetSymbolAddress((void**)&qkv,   g_qkv);
    cudaGetSymbolAddress((void**)&attnv, g_attnv);
    cudaGetSymbolAddress((void**)&ff1,   g_ff1);
    cudaGetSymbolAddress((void**)&xcat,  g_xcat);
    cudaGetSymbolAddress((void**)&wt,    g_wt);

    // outputs: fea_t | enc_res(384) | rec_temp(512) | emb(512)
    const size_t OFF_FEA = 0;
    const size_t OFF_RES = (size_t)Mn * Dn;
    const size_t OFF_REC = OFF_RES + (size_t)Mn * 384;
    const size_t OFF_EMB = OFF_REC + (size_t)Mn * Dn;
    float* emb = out + OFF_EMB;

    const int SM128 = 3 * (128 + 128) * 72 * 2;   // 110592 B (3 stages, K64 chunks)
    cudaFuncSetAttribute((const void*)gemm_mma<128>, cudaFuncAttributeMaxDynamicSharedMemorySize, SM128);
    cudaFuncSetAttribute((const void*)flash_attn, cudaFuncAttributeMaxDynamicSharedMemorySize, FL_SMEM);

    // ---- preprocessing ----
    transpose_all<<<9536, dim3(32, 8)>>>(Wq, Wk, Wv, Wo, W1, W2, Wproj, Wfea, wt);
    pack_misc<<<524 + Mn, 128>>>(embk, bq, bk, bv, x, wt + KTF, bqkv, xcat);

    gemm_mma<128><<<dim3(4, 64), 256, SM128>>>(xcat, 128, wt + KTF, 128, nullptr,
                                               emb, h16, Dn, 128, 0);

    for (int l = 0; l < NLn; l++) {
        const float* hin = (l == 0) ? emb : h;
        size_t o512 = (size_t)l * Dn * Dn, o1 = (size_t)l * Dn * DFFn;
        gemm_mma<128><<<dim3(12, 64), 256, SM128>>>(h16, Dn, wt + WQKV(l), Dn,
                                                    bqkv + l * 1536, nullptr, qkv, 1536, Dn, 0);
        flash_attn<<<dim3(BHn, 16), 256, FL_SMEM>>>(qkv, attnv);
        gemm_mma<128><<<dim3(4, 64), 256, SM128>>>(attnv, Dn, wt + WTO + o512, Dn,
                                                   bo + l * Dn, tmp, nullptr, Dn, Dn, 0);
        add_ln512<<<Mn, 128>>>(hin, tmp, n1g + l * Dn, n1b + l * Dn, x1, x1h, nullptr);
        gemm_mma<128><<<dim3(16, 64), 256, SM128>>>(x1h, Dn, wt + WT1 + o1, Dn,
                                                    b1 + l * DFFn, nullptr, ff1, DFFn, Dn, 1);
        gemm_mma<128><<<dim3(4, 64), 256, SM128>>>(ff1, DFFn, wt + WT2 + o1, DFFn,
                                                   b2 + l * Dn, tmp, nullptr, Dn, DFFn, 0);
        add_ln512<<<Mn, 128>>>(x1, tmp, n2g + l * Dn, n2b + l * Dn, h, h16, nullptr);
    }

    add_ln512<<<Mn, 128>>>(h, nullptr, nfg, nfb, nullptr, enc16, out + OFF_RES);

    gemm_mma<128><<<dim3(4, 64), 256, SM128>>>(enc16 + (Dn - DRESn), Dn, wt + WTF, DRESn,
                                               bfea, out + OFF_FEA, nullptr, Dn, DRESn, 0);
    gemm_mma<128><<<dim3(4, 64), 256, SM128>>>(enc16, Dn, wt + WTP, Dn,
                                               bproj, out + OFF_REC, nullptr, Dn, Dn, 0);
}

// round 12
// speedup vs baseline: 2.0606x; 1.0080x over previous
#include <cuda_runtime.h>
#include <cuda.h>
#include <cuda_fp16.h>
#include <math.h>

#define Bn   16
#define Ln   512
#define Cn   38
#define Dn   512
#define Hn   8
#define En   64
#define DFFn 2048
#define NLn  3
#define DRESn 128
#define Mn   (Bn*Ln)     /* 8192 */
#define BHn  (Bn*Hn)     /* 128  */

// ---------------- scratch (static device memory) ----------------
__device__ float  g_h   [Mn*Dn];
__device__ float  g_x1  [Mn*Dn];
__device__ float  g_tmp [Mn*Dn];
__device__ __align__(16) __half g_h16  [Mn*Dn];
__device__ __align__(16) __half g_x1h  [Mn*Dn];
__device__ __align__(16) __half g_enc16[Mn*Dn];
__device__ __align__(16) __half g_qkv  [Mn*1536];
__device__ __align__(16) __half g_attnv[Mn*Dn];
__device__ __align__(16) __half g_ff1  [Mn*DFFn];
__device__ __align__(16) __half g_xcat [Mn*128];
__device__ __align__(16) __half g_wt   [9830400];     // transposed weights (half)
__device__ float  g_bqkv[NLn*1536];

#define WQKV(l) ((size_t)(l) * 786432)                 /* fused [1536][512] per layer */
#define WTO 2359296
#define WT1 3145728
#define WT2 6291456
#define WTP 9437184
#define WTF 9699328
#define KTF 9764864

// ================= helpers =================
__device__ __forceinline__ unsigned smem_u32(const void* p) {
    unsigned a;
    asm("{ .reg .u64 t; cvta.to.shared.u64 t, %1; cvt.u32.u64 %0, t; }"
        : "=r"(a) : "l"(p));
    return a;
}
__device__ __forceinline__ void mma16(float* c, const unsigned* a, const unsigned* b) {
    asm volatile("mma.sync.aligned.m16n8k16.row.col.f32.f16.f16.f32 "
        "{%0,%1,%2,%3}, {%4,%5,%6,%7}, {%8,%9}, {%0,%1,%2,%3};"
        : "+f"(c[0]), "+f"(c[1]), "+f"(c[2]), "+f"(c[3])
        : "r"(a[0]), "r"(a[1]), "r"(a[2]), "r"(a[3]), "r"(b[0]), "r"(b[1]));
}
__device__ __forceinline__ void ldsm4(unsigned* r, unsigned addr) {
    asm volatile("ldmatrix.sync.aligned.m8n8.x4.shared.b16 {%0,%1,%2,%3}, [%4];"
        : "=r"(r[0]), "=r"(r[1]), "=r"(r[2]), "=r"(r[3]) : "r"(addr));
}
__device__ __forceinline__ void ldsm4t(unsigned* r, unsigned addr) {
    asm volatile("ldmatrix.sync.aligned.m8n8.x4.trans.shared.b16 {%0,%1,%2,%3}, [%4];"
        : "=r"(r[0]), "=r"(r[1]), "=r"(r[2]), "=r"(r[3]) : "r"(addr));
}
__device__ __forceinline__ unsigned h2u(__half2 v) { return *(unsigned*)&v; }
#define CP16(sa, gp) \
    asm volatile("cp.async.cg.shared.global [%0], [%1], 16;" :: "r"(sa), "l"(gp))
#define CPCOMMIT() asm volatile("cp.async.commit_group;" ::: "memory")
#define CPWAIT(n)  asm volatile("cp.async.wait_group %0;" :: "n"(n) : "memory")

// == fp16 tensor-core GEMM (3-stage pipeline, K-chunk 64, templated trips) ===
// NCT > 0: compile-time chunk count (fully unrolled). NCT == 0: runtime (K/64).
template<int NT, int NCT>
__global__ __launch_bounds__(256, 2)
void gemm_mma(const __half* __restrict__ A, int lda,
              const __half* __restrict__ BT, int ldb,
              const float* __restrict__ bias,
              float* __restrict__ C, __half* __restrict__ C16, int ldc,
              int K, int do_gelu)
{
    constexpr int WC  = 4;
    constexpr int WM  = 64;
    constexpr int MT  = WM / 16;
    constexpr int RS  = 72;                   // 64 data halves + 8 pad
    constexpr int STG = (128 + NT) * RS;      // halves per stage

    extern __shared__ __align__(16) char dsm[];
    __half* sm = (__half*)dsm;
    const int tid = threadIdx.x, w = tid >> 5, lane = tid & 31;
    const int m0 = blockIdx.y * 128, n0 = blockIdx.x * NT;
    const int g = lane >> 3, lr = lane & 7;

    auto load_stage = [&](int kc, int st) {
        __half* As = sm + st * STG;
        __half* Bs = As + 128 * RS;
        const __half* Ap = A + (size_t)m0 * lda + kc * 64;
#pragma unroll
        for (int i = 0; i < 4; i++) {
            int fi = tid + i * 256, row = fi >> 3, seg = fi & 7;
            CP16(smem_u32(As + row * RS + seg * 8), Ap + (size_t)row * lda + seg * 8);
        }
        const __half* Bp = BT + (size_t)n0 * ldb + kc * 64;
#pragma unroll
        for (int i = 0; i < NT / 32; i++) {
            int fi = tid + i * 256, row = fi >> 3, seg = fi & 7;
            CP16(smem_u32(Bs + row * RS + seg * 8), Bp + (size_t)row * ldb + seg * 8);
        }
    };

    float acc[MT][4][4];
#pragma unroll
    for (int mt = 0; mt < MT; mt++)
#pragma unroll
        for (int nt = 0; nt < 4; nt++)
#pragma unroll
            for (int j = 0; j < 4; j++) acc[mt][nt][j] = 0.f;

    const int wm0 = (w / WC) * WM, wn0 = (w % WC) * 32;
    const int r = lane >> 2, cl = lane & 3;
    const unsigned aLane = ((g & 1) * 8 + lr) * RS + (g >> 1) * 8;
    const unsigned bLane = ((g >> 1) * 8 + lr) * RS + (g & 1) * 8;

    auto compute = [&](int st) {
        __half* As = sm + st * STG;
        __half* Bs = As + 128 * RS;
        unsigned aBase = smem_u32(As) + 2u * (wm0 * RS + aLane);
        unsigned bBase = smem_u32(Bs) + 2u * (wn0 * RS + bLane);
#pragma unroll
        for (int ks = 0; ks < 4; ks++) {          // four k16 steps per 64-chunk
            const unsigned koff = ks * 32;
            unsigned a[MT][4], b[4][2];
#pragma unroll
            for (int mt = 0; mt < MT; mt++)
                ldsm4(a[mt], aBase + mt * (16 * RS * 2) + koff);
#pragma unroll
            for (int p = 0; p < 2; p++) {
                unsigned t[4];
                ldsm4(t, bBase + p * (16 * RS * 2) + koff);
                b[2 * p][0] = t[0]; b[2 * p][1] = t[1];
                b[2 * p + 1][0] = t[2]; b[2 * p + 1][1] = t[3];
            }
#pragma unroll
            for (int mt = 0; mt < MT; mt++)
#pragma unroll
                for (int nt = 0; nt < 4; nt++)
                    mma16(acc[mt][nt], a[mt], b[nt]);
        }
    };

    auto step = [&](int c, int NCloc) {
        if (c + 1 < NCloc) { CPWAIT(1); }      // chunk c landed; c+1 may fly
        else              { CPWAIT(0); }       // final chunk fully landed
        __syncthreads();
        compute(c % 3);
        if (c + 2 < NCloc) {
            load_stage(c + 2, (c + 2) % 3);
            CPCOMMIT();
        }
    };

    load_stage(0, 0); CPCOMMIT();
    if (NCT != 2) { load_stage(1, 1); CPCOMMIT(); }
    else {
        // NC==2: prologue loads both chunks
        load_stage(1, 1); CPCOMMIT();
    }

    if constexpr (NCT > 0) {
#pragma unroll
        for (int c = 0; c < NCT; c++) step(c, NCT);
    } else {
        const int NC = K >> 6;
        for (int c = 0; c < NC; c++) step(c, NC);
    }

#pragma unroll
    for (int mt = 0; mt < MT; mt++) {
#pragma unroll
        for (int nt = 0; nt < 4; nt++) {
            int row = m0 + wm0 + mt * 16 + r;
            int col = n0 + wn0 + nt * 8 + cl * 2;
            float bs0 = bias ? bias[col] : 0.f;
            float bs1 = bias ? bias[col + 1] : 0.f;
            float v0 = acc[mt][nt][0] + bs0;
            float v1 = acc[mt][nt][1] + bs1;
            float v2 = acc[mt][nt][2] + bs0;
            float v3 = acc[mt][nt][3] + bs1;
            if (do_gelu) {
                v0 = 0.5f * v0 * (1.0f + erff(v0 * 0.70710678118654752f));
                v1 = 0.5f * v1 * (1.0f + erff(v1 * 0.70710678118654752f));
                v2 = 0.5f * v2 * (1.0f + erff(v2 * 0.70710678118654752f));
                v3 = 0.5f * v3 * (1.0f + erff(v3 * 0.70710678118654752f));
            }
            if (C) {
                float* p0 = C + (size_t)row * ldc + col;
                float* p1 = p0 + (size_t)8 * ldc;
                p0[0] = v0; p0[1] = v1;
                p1[0] = v2; p1[1] = v3;
            }
            if (C16) {
                *(__half2*)(C16 + (size_t)row * ldc + col) = __floats2half2_rn(v0, v1);
                *(__half2*)(C16 + (size_t)(row + 8) * ldc + col) = __floats2half2_rn(v2, v3);
            }
        }
    }
}

// ================= flash attention: scores + softmax + P.V ==================
#define FL_RSQ 72
#define FL_RSK 72
#define FL_RSV 72
#define FL_KOFF (32*FL_RSQ)                    /* halves */
#define FL_VOFF (FL_KOFF + 512*FL_RSK)
#define FL_REDB ((FL_VOFF + 512*FL_RSV)*2)     /* bytes  */
#define FL_SMEM (FL_REDB + 2048 + 16)

__global__ __launch_bounds__(256, 1)
void flash_attn(const __half* __restrict__ qkv,
                __half* __restrict__ attnv)
{
    extern __shared__ __align__(16) char dsm[];
    __half* Qs = (__half*)dsm;
    __half* Ks = Qs + FL_KOFF;
    __half* Vs = Qs + FL_VOFF;
    float* red  = (float*)(dsm + FL_REDB);
    float* red2 = red + 256;

    const int tid = threadIdx.x, w = tid >> 5, lane = tid & 31;
    const int r = lane >> 2, cl = lane & 3;
    const int g = lane >> 3, lr = lane & 7;
    const int z = blockIdx.x;
    const int m0 = blockIdx.y * 32;
    const int b = z >> 3, hh = z & 7;
    const size_t qbase = ((size_t)b * Ln) * 1536 + (size_t)hh * 64;

    {
        int row = tid >> 3, seg = tid & 7;
        *(uint4*)(Qs + row * FL_RSQ + seg * 8) =
            *(const uint4*)(qkv + qbase + (size_t)(m0 + row) * 1536 + seg * 8);
    }
#pragma unroll 4
    for (int i = 0; i < 16; i++) {
        int idx = tid + i * 256, row = idx >> 3, seg = idx & 7;
        const __half* src = qkv + qbase + 512 + (size_t)row * 1536 + seg * 8;
        *(uint4*)(Ks + row * FL_RSK + seg * 8) = *(const uint4*)src;
        *(uint4*)(Vs + row * FL_RSV + seg * 8) = *(const uint4*)(src + 512);
    }
    __syncthreads();

    const int wn0 = w * 64;
    float acc[2][8][4];
#pragma unroll
    for (int mt = 0; mt < 2; mt++)
#pragma unroll
        for (int nt = 0; nt < 8; nt++)
#pragma unroll
            for (int j = 0; j < 4; j++) acc[mt][nt][j] = 0.f;

    const unsigned aBase = smem_u32(Qs) + 2u * (((g & 1) * 8 + lr) * FL_RSQ + (g >> 1) * 8);
    const unsigned bBase = smem_u32(Ks) + 2u * ((wn0 + (g >> 1) * 8 + lr) * FL_RSK + (g & 1) * 8);
#pragma unroll
    for (int ks = 0; ks < 4; ks++) {
        const unsigned koff = ks * 32;
        unsigned a[2][4], b[8][2];
#pragma unroll
        for (int mt = 0; mt < 2; mt++)
            ldsm4(a[mt], aBase + mt * (16 * FL_RSQ * 2) + koff);
#pragma unroll
        for (int p = 0; p < 4; p++) {
            unsigned t[4];
            ldsm4(t, bBase + p * (16 * FL_RSK * 2) + koff);
            b[2 * p][0] = t[0]; b[2 * p][1] = t[1];
            b[2 * p + 1][0] = t[2]; b[2 * p + 1][1] = t[3];
        }
#pragma unroll
        for (int mt = 0; mt < 2; mt++)
#pragma unroll
            for (int nt = 0; nt < 8; nt++)
                mma16(acc[mt][nt], a[mt], b[nt]);
    }

    float M[4], inv[4];
#pragma unroll
    for (int rs = 0; rs < 4; rs++) {
        int mt = rs >> 1, jb = (rs & 1) * 2;
        float mx = -1e30f;
#pragma unroll
        for (int nt = 0; nt < 8; nt++)
            mx = fmaxf(mx, fmaxf(acc[mt][nt][jb], acc[mt][nt][jb + 1]));
        mx = fmaxf(mx, __shfl_xor_sync(0xFFFFFFFFu, mx, 1));
        mx = fmaxf(mx, __shfl_xor_sync(0xFFFFFFFFu, mx, 2));
        if (cl == 0) red[w * 32 + mt * 16 + r + (rs & 1) * 8] = mx;
    }
    __syncthreads();
#pragma unroll
    for (int rs = 0; rs < 4; rs++) {
        int row = (rs >> 1) * 16 + r + (rs & 1) * 8;
        float mx = -1e30f;
#pragma unroll
        for (int w2 = 0; w2 < 8; w2++) mx = fmaxf(mx, red[w2 * 32 + row]);
        M[rs] = mx;
    }
#pragma unroll
    for (int rs = 0; rs < 4; rs++) {
        int mt = rs >> 1, jb = (rs & 1) * 2;
        float s = 0.f;
#pragma unroll
        for (int nt = 0; nt < 8; nt++) {
            float e0 = __expf((acc[mt][nt][jb]     - M[rs]) * 0.125f);
            float e1 = __expf((acc[mt][nt][jb + 1] - M[rs]) * 0.125f);
            acc[mt][nt][jb] = e0; acc[mt][nt][jb + 1] = e1;
            s += e0 + e1;
        }
        s += __shfl_xor_sync(0xFFFFFFFFu, s, 1);
        s += __shfl_xor_sync(0xFFFFFFFFu, s, 2);
        if (cl == 0) red2[w * 32 + mt * 16 + r + (rs & 1) * 8] = s;
    }
    __syncthreads();
#pragma unroll
    for (int rs = 0; rs < 4; rs++) {
        int row = (rs >> 1) * 16 + r + (rs & 1) * 8;
        float s = 0.f;
#pragma unroll
        for (int w2 = 0; w2 < 8; w2++) s += red2[w2 * 32 + row];
        inv[rs] = 1.0f / s;
    }

    float o[2][8][4];
#pragma unroll
    for (int mt = 0; mt < 2; mt++)
#pragma unroll
        for (int nt = 0; nt < 8; nt++)
#pragma unroll
            for (int j = 0; j < 4; j++) o[mt][nt][j] = 0.f;

    const unsigned vBase = smem_u32(Vs) + 2u * ((wn0 + (g & 1) * 8 + lr) * FL_RSV + (g >> 1) * 8);
#pragma unroll
    for (int t = 0; t < 4; t++) {
        unsigned a[2][4], b[8][2];
#pragma unroll
        for (int mt = 0; mt < 2; mt++) {
            a[mt][0] = h2u(__floats2half2_rn(acc[mt][2*t][0]   * inv[2*mt],     acc[mt][2*t][1]   * inv[2*mt]));
            a[mt][1] = h2u(__floats2half2_rn(acc[mt][2*t][2]   * inv[2*mt + 1], acc[mt][2*t][3]   * inv[2*mt + 1]));
            a[mt][2] = h2u(__floats2half2_rn(acc[mt][2*t+1][0] * inv[2*mt],     acc[mt][2*t+1][1] * inv[2*mt]));
            a[mt][3] = h2u(__floats2half2_rn(acc[mt][2*t+1][2] * inv[2*mt + 1], acc[mt][2*t+1][3] * inv[2*mt + 1]));
        }
#pragma unroll
        for (int p = 0; p < 4; p++) {
            unsigned tb[4];
            ldsm4t(tb, vBase + t * (16 * FL_RSV * 2) + p * 32);
            b[2 * p][0] = tb[0]; b[2 * p][1] = tb[1];
            b[2 * p + 1][0] = tb[2]; b[2 * p + 1][1] = tb[3];
        }
#pragma unroll
        for (int mt = 0; mt < 2; mt++)
#pragma unroll
            for (int nt = 0; nt < 8; nt++)
                mma16(o[mt][nt], a[mt], b[nt]);
    }

    float* part = (float*)(dsm + FL_KOFF * 2);
#pragma unroll
    for (int mt = 0; mt < 2; mt++)
#pragma unroll
        for (int nt = 0; nt < 8; nt++) {
            int row = mt * 16 + r, col = nt * 8 + cl * 2;
            float* p = part + w * 2112 + row * 66 + col;
            p[0] = o[mt][nt][0]; p[1] = o[mt][nt][1];
            p[8 * 66] = o[mt][nt][2]; p[8 * 66 + 1] = o[mt][nt][3];
        }
    __syncthreads();

    {
        int orow = tid >> 3, c0 = (tid & 7) * 8;
        float s[8];
#pragma unroll
        for (int c = 0; c < 8; c++) s[c] = 0.f;
#pragma unroll
        for (int w2 = 0; w2 < 8; w2++) {
            const float* p = part + w2 * 2112 + orow * 66 + c0;
#pragma unroll
            for (int c = 0; c < 8; c++) s[c] += p[c];
        }
        __align__(16) __half2 hb[4];
#pragma unroll
        for (int c = 0; c < 4; c++) hb[c] = __floats2half2_rn(s[2 * c], s[2 * c + 1]);
        *(uint4*)(attnv + ((size_t)b * Ln + m0 + orow) * Dn + hh * 64 + c0) = *(uint4*)hb;
    }
}

// ================= batched weight transpose (ALL weights, one launch) =======
__global__ void transpose_all(const float* __restrict__ Wq, const float* __restrict__ Wk,
                              const float* __restrict__ Wv, const float* __restrict__ Wo,
                              const float* __restrict__ W1, const float* __restrict__ W2,
                              const float* __restrict__ Wproj, const float* __restrict__ Wfea,
                              __half* __restrict__ wt)
{
    int bid = blockIdx.x;
    const float* in; __half* out; int K, N, bx, by;
    if (bid < 9216) {
        int l = bid / 3072, rr = bid - l * 3072;
        size_t o512 = (size_t)l * 262144, o1 = (size_t)l * 1048576;
        if (rr < 1024) {
            int m = rr >> 8, idx = rr & 255;
            K = 512; N = 512; bx = idx & 15; by = idx >> 4;
            if (m == 0)      { in = Wq + o512; out = wt + WQKV(l); }
            else if (m == 1) { in = Wk + o512; out = wt + WQKV(l) + 262144; }
            else if (m == 2) { in = Wv + o512; out = wt + WQKV(l) + 524288; }
            else             { in = Wo + o512; out = wt + WTO + o512; }
        } else if (rr < 2048) {
            int idx = rr - 1024;
            K = 512; N = 2048; bx = idx & 63; by = idx >> 6;
            in = W1 + o1; out = wt + WT1 + o1;
        } else {
            int idx = rr - 2048;
            K = 2048; N = 512; bx = idx & 15; by = idx >> 4;
            in = W2 + o1; out = wt + WT2 + o1;
        }
    } else if (bid < 9472) {
        int idx = bid - 9216;
        K = 512; N = 512; bx = idx & 15; by = idx >> 4;
        in = Wproj; out = wt + WTP;
    } else {
        int idx = bid - 9472;
        K = 128; N = 512; bx = idx & 15; by = idx >> 4;
        in = Wfea; out = wt + WTF;
    }
    __shared__ float t[32][33];
    int k0 = by * 32, n0 = bx * 32;
    int tx = threadIdx.x, ty = threadIdx.y;
#pragma unroll
    for (int rr2 = 0; rr2 < 4; rr2++)
        t[ty + rr2 * 8][tx] = in[(size_t)(k0 + ty + rr2 * 8) * N + n0 + tx];
    __syncthreads();
#pragma unroll
    for (int rr2 = 0; rr2 < 4; rr2++)
        out[(size_t)(n0 + ty + rr2 * 8) * K + k0 + tx] = __float2half(t[tx][ty + rr2 * 8]);
}

// ================= combined small packs: ktf | bqkv | xcat ==================
__global__ void pack_misc(const float* __restrict__ kern,
                          const float* __restrict__ bq, const float* __restrict__ bk,
                          const float* __restrict__ bv,
                          const float* __restrict__ x,
                          __half* __restrict__ kt, float* __restrict__ bdst,
                          __half* __restrict__ xc)
{
    int bid = blockIdx.x, tidx = threadIdx.x;
    if (bid < 512) {
        int d = bid;
        kt[(size_t)d * 128 + tidx] =
            __float2half((tidx < Cn * 3) ? kern[(size_t)d * (Cn * 3) + tidx] : 0.f);
    } else if (bid < 524) {
        int j = bid - 512;
        int l = j >> 2, i = (j & 3) * 128 + tidx;
        bdst[l * 1536 + i]        = bq[l * 512 + i];
        bdst[l * 1536 + 512 + i]  = bk[l * 512 + i];
        bdst[l * 1536 + 1024 + i] = bv[l * 512 + i];
    } else {
        int bl = bid - 524;
        int b = bl >> 9, l = bl & 511;
        float val = 0.f;
        if (tidx < Cn * 3) {
            int c = tidx / 3, t = tidx - c * 3;
            int ls = (l - 1 + t + Ln) & (Ln - 1);
            val = x[((size_t)b * Ln + ls) * Cn + c];
        }
        xc[(size_t)bl * 128 + tidx] = __float2half(val);
    }
}

// ===== layernorm (vectorized: 128 thr x float4) =====
__global__ void add_ln512(const float* __restrict__ a, const float* __restrict__ b,
                          const float* __restrict__ g, const float* __restrict__ be,
                          float* __restrict__ o, __half* __restrict__ o16,
                          float* __restrict__ res) {
    int row = blockIdx.x, t = threadIdx.x;        // 128 threads
    size_t base = (size_t)row * Dn;
    float4 v = *(const float4*)(a + base + t * 4);
    if (b) {
        float4 vb = *(const float4*)(b + base + t * 4);
        v.x += vb.x; v.y += vb.y; v.z += vb.z; v.w += vb.w;
    }
    float s = v.x + v.y + v.z + v.w;
#pragma unroll
    for (int oo = 16; oo > 0; oo >>= 1) s += __shfl_xor_sync(0xFFFFFFFFu, s, oo);
    __shared__ float s1[4], s2[4];
    if ((t & 31) == 0) s1[t >> 5] = s;
    __syncthreads();
    float mean = (s1[0] + s1[1] + s1[2] + s1[3]) * (1.0f / Dn);
    float d0 = v.x - mean, d1 = v.y - mean, d2 = v.z - mean, d3 = v.w - mean;
    float q2 = d0 * d0 + d1 * d1 + d2 * d2 + d3 * d3;
#pragma unroll
    for (int oo = 16; oo > 0; oo >>= 1) q2 += __shfl_xor_sync(0xFFFFFFFFu, q2, oo);
    if ((t & 31) == 0) s2[t >> 5] = q2;
    __syncthreads();
    float var = (s2[0] + s2[1] + s2[2] + s2[3]) * (1.0f / Dn);
    float rr = rsqrtf(var + 1e-5f);
    float4 gg = *(const float4*)(g + t * 4);
    float4 bb = *(const float4*)(be + t * 4);
    float o0 = d0 * rr * gg.x + bb.x;
    float o1 = d1 * rr * gg.y + bb.y;
    float o2 = d2 * rr * gg.z + bb.z;
    float o3 = d3 * rr * gg.w + bb.w;
    if (o) {
        float4 ov = {o0, o1, o2, o3};
        *(float4*)(o + base + t * 4) = ov;
    }
    if (o16) {
        *(__half2*)(o16 + base + t * 4)     = __floats2half2_rn(o0, o1);
        *(__half2*)(o16 + base + t * 4 + 2) = __floats2half2_rn(o2, o3);
    }
    if (res && t < 96) {
        float4 rv = {o0, o1, o2, o3};
        *(float4*)(res + (size_t)row * 384 + t * 4) = rv;
    }
}

// ================= launcher =================
extern "C" void kernel_launch(void* const* d_in, const int* in_sizes, int n_in,
                              void* d_out, int out_size)
{
    const float* x     = (const float*)d_in[0];
    const float* embk  = (const float*)d_in[1];
    const float* Wq    = (const float*)d_in[2];
    const float* bq    = (const float*)d_in[3];
    const float* Wk    = (const float*)d_in[4];
    const float* bk    = (const float*)d_in[5];
    const float* Wv    = (const float*)d_in[6];
    const float* bv    = (const float*)d_in[7];
    // d_in[8], d_in[9]: Wsig/bsig are dead code in the reference
    const float* Wo    = (const float*)d_in[10];
    const float* bo    = (const float*)d_in[11];
    const float* W1    = (const float*)d_in[12];
    const float* b1    = (const float*)d_in[13];
    const float* W2    = (const float*)d_in[14];
    const float* b2    = (const float*)d_in[15];
    const float* n1g   = (const float*)d_in[16];
    const float* n1b   = (const float*)d_in[17];
    const float* n2g   = (const float*)d_in[18];
    const float* n2b   = (const float*)d_in[19];
    const float* nfg   = (const float*)d_in[20];
    const float* nfb   = (const float*)d_in[21];
    const float* Wproj = (const float*)d_in[22];
    const float* bproj = (const float*)d_in[23];
    const float* Wfea  = (const float*)d_in[24];
    const float* bfea  = (const float*)d_in[25];
    float* out = (float*)d_out;

    float *h, *x1, *tmp, *bqkv;
    __half *h16,*x1h,*enc16,*qkv,*attnv,*ff1,*xcat,*wt;
    cudaGetSymbolAddress((void**)&h,     g_h);
    cudaGetSymbolAddress((void**)&x1,    g_x1);
    cudaGetSymbolAddress((void**)&tmp,   g_tmp);
    cudaGetSymbolAddress((void**)&bqkv,  g_bqkv);
    cudaGetSymbolAddress((void**)&h16,   g_h16);
    cudaGetSymbolAddress((void**)&x1h,   g_x1h);
    cudaGetSymbolAddress((void**)&enc16, g_enc16);
    cudaGetSymbolAddress((void**)&qkv,   g_qkv);
    cudaGetSymbolAddress((void**)&attnv, g_attnv);
    cudaGetSymbolAddress((void**)&ff1,   g_ff1);
    cudaGetSymbolAddress((void**)&xcat,  g_xcat);
    cudaGetSymbolAddress((void**)&wt,    g_wt);

    // outputs: fea_t | enc_res(384) | rec_temp(512) | emb(512)
    const size_t OFF_FEA = 0;
    const size_t OFF_RES = (size_t)Mn * Dn;
    const size_t OFF_REC = OFF_RES + (size_t)Mn * 384;
    const size_t OFF_EMB = OFF_REC + (size_t)Mn * Dn;
    float* emb = out + OFF_EMB;

    const int SM128 = 3 * (128 + 128) * 72 * 2;   // 110592 B (3 stages, K64 chunks)
    cudaFuncSetAttribute((const void*)gemm_mma<128,2>, cudaFuncAttributeMaxDynamicSharedMemorySize, SM128);
    cudaFuncSetAttribute((const void*)gemm_mma<128,8>, cudaFuncAttributeMaxDynamicSharedMemorySize, SM128);
    cudaFuncSetAttribute((const void*)gemm_mma<128,0>, cudaFuncAttributeMaxDynamicSharedMemorySize, SM128);
    cudaFuncSetAttribute((const void*)flash_attn, cudaFuncAttributeMaxDynamicSharedMemorySize, FL_SMEM);

    // ---- preprocessing ----
    transpose_all<<<9536, dim3(32, 8)>>>(Wq, Wk, Wv, Wo, W1, W2, Wproj, Wfea, wt);
    pack_misc<<<524 + Mn, 128>>>(embk, bq, bk, bv, x, wt + KTF, bqkv, xcat);

    // conv: K=128 -> NC=2 (unrolled)
    gemm_mma<128,2><<<dim3(4, 64), 256, SM128>>>(xcat, 128, wt + KTF, 128, nullptr,
                                                 emb, h16, Dn, 128, 0);

    for (int l = 0; l < NLn; l++) {
        const float* hin = (l == 0) ? emb : h;
        size_t o512 = (size_t)l * Dn * Dn, o1 = (size_t)l * Dn * DFFn;
        gemm_mma<128,8><<<dim3(12, 64), 256, SM128>>>(h16, Dn, wt + WQKV(l), Dn,
                                                      bqkv + l * 1536, nullptr, qkv, 1536, Dn, 0);
        flash_attn<<<dim3(BHn, 16), 256, FL_SMEM>>>(qkv, attnv);
        gemm_mma<128,8><<<dim3(4, 64), 256, SM128>>>(attnv, Dn, wt + WTO + o512, Dn,
                                                     bo + l * Dn, tmp, nullptr, Dn, Dn, 0);
        add_ln512<<<Mn, 128>>>(hin, tmp, n1g + l * Dn, n1b + l * Dn, x1, x1h, nullptr);
        gemm_mma<128,8><<<dim3(16, 64), 256, SM128>>>(x1h, Dn, wt + WT1 + o1, Dn,
                                                      b1 + l * DFFn, nullptr, ff1, DFFn, Dn, 1);
        gemm_mma<128,0><<<dim3(4, 64), 256, SM128>>>(ff1, DFFn, wt + WT2 + o1, DFFn,
                                                     b2 + l * Dn, tmp, nullptr, Dn, DFFn, 0);
        add_ln512<<<Mn, 128>>>(x1, tmp, n2g + l * Dn, n2b + l * Dn, h, h16, nullptr);
    }

    add_ln512<<<Mn, 128>>>(h, nullptr, nfg, nfb, nullptr, enc16, out + OFF_RES);

    // fea: K=128 -> NC=2 (unrolled); proj: K=512 -> NC=8 (unrolled)
    gemm_mma<128,2><<<dim3(4, 64), 256, SM128>>>(enc16 + (Dn - DRESn), Dn, wt + WTF, DRESn,
                                                 bfea, out + OFF_FEA, nullptr, Dn, DRESn, 0);
    gemm_mma<128,8><<<dim3(4, 64), 256, SM128>>>(enc16, Dn, wt + WTP, Dn,
                                                 bproj, out + OFF_REC, nullptr, Dn, Dn, 0);
}